// round 8
// baseline (speedup 1.0000x reference)
#include <cuda_runtime.h>
#include <cuda_bf16.h>
#include <math.h>

#define B_  64
#define S_  512
#define D_  768
#define H_  12
#define DH_ 64
#define NF_ 32
#define NL_ 12
#define OUT_ 512

static const int BS_  = B_ * S_;        // 32768
static const int BSD_ = B_ * S_ * D_;   // 25165824

// ---------------- scratch (allowed: __device__ globals) ----------------
__device__ float g_h [B_*S_*D_];
__device__ float g_q [B_*S_*D_];
__device__ float g_k [B_*S_*D_];
__device__ float g_v [B_*S_*D_];
__device__ float g_t1[B_*S_*D_];
__device__ float g_ff[B_*S_*D_];
__device__ float g_pq[B_*S_*H_*NF_];
__device__ float g_pk[B_*S_*H_*NF_];
__device__ float g_kv[B_*H_*NF_*DH_];
__device__ float g_ps[B_*H_*NF_];
__device__ float g_pool[B_*D_];

// ---------------- embedding ----------------
__global__ void embed_kernel(const int* __restrict__ x, const float* __restrict__ emb,
                             float* __restrict__ h)
{
    long i = (long)blockIdx.x * blockDim.x + threadIdx.x;
    if (i < (long)BSD_) {
        int bs = (int)(i / D_);
        int d  = (int)(i % D_);
        h[i] = emb[(long)x[bs] * D_ + d];
    }
}

// ---------------- SGEMM: C = A[MxK] @ B[KxN] + bias, opt. exact GELU ----------------
// M%128==0, N%128==0, K%8==0 assumed (32768 x 768 x 768 here).
template<int ACT>
__global__ void __launch_bounds__(256, 2)
sgemm_kernel(const float* __restrict__ A, const float* __restrict__ Bm,
             const float* __restrict__ bias, float* __restrict__ C,
             int M, int N, int K)
{
    __shared__ float As[2][8][128];
    __shared__ float Bs[2][8][128];

    const int tid = threadIdx.x;
    const int bx = blockIdx.x, by = blockIdx.y;
    const int tx = tid & 15, ty = tid >> 4;

    const int arow = tid >> 1;           // 0..127
    const int acol = (tid & 1) << 2;     // 0 or 4
    const int brow = tid >> 5;           // 0..7
    const int bcol = (tid & 31) << 2;    // 0..124

    const float* Aptr = A  + (size_t)(by * 128 + arow) * K + acol;
    const float* Bptr = Bm + (size_t)brow * N + bx * 128 + bcol;

    float acc[8][8];
    #pragma unroll
    for (int i = 0; i < 8; i++)
        #pragma unroll
        for (int j = 0; j < 8; j++) acc[i][j] = 0.f;

    // preload tile 0
    {
        float4 a4 = *(const float4*)(Aptr);
        float4 b4 = *(const float4*)(Bptr);
        As[0][acol + 0][arow] = a4.x;
        As[0][acol + 1][arow] = a4.y;
        As[0][acol + 2][arow] = a4.z;
        As[0][acol + 3][arow] = a4.w;
        *(float4*)&Bs[0][brow][bcol] = b4;
    }
    __syncthreads();

    const int nIter = K >> 3;
    int buf = 0;
    for (int t = 0; t < nIter; ++t) {
        float4 na, nb;
        bool more = (t + 1 < nIter);
        if (more) {
            na = *(const float4*)(Aptr + (size_t)(t + 1) * 8);
            nb = *(const float4*)(Bptr + (size_t)(t + 1) * 8 * N);
        }
        #pragma unroll
        for (int kk = 0; kk < 8; ++kk) {
            float a[8], b[8];
            *(float4*)&a[0] = *(const float4*)&As[buf][kk][ty * 8];
            *(float4*)&a[4] = *(const float4*)&As[buf][kk][ty * 8 + 4];
            *(float4*)&b[0] = *(const float4*)&Bs[buf][kk][tx * 8];
            *(float4*)&b[4] = *(const float4*)&Bs[buf][kk][tx * 8 + 4];
            #pragma unroll
            for (int i = 0; i < 8; i++)
                #pragma unroll
                for (int j = 0; j < 8; j++)
                    acc[i][j] = fmaf(a[i], b[j], acc[i][j]);
        }
        if (more) {
            int nbuf = buf ^ 1;
            As[nbuf][acol + 0][arow] = na.x;
            As[nbuf][acol + 1][arow] = na.y;
            As[nbuf][acol + 2][arow] = na.z;
            As[nbuf][acol + 3][arow] = na.w;
            *(float4*)&Bs[nbuf][brow][bcol] = nb;
        }
        __syncthreads();
        buf ^= 1;
    }

    const int crow0 = by * 128 + ty * 8;
    const int ccol0 = bx * 128 + tx * 8;
    #pragma unroll
    for (int i = 0; i < 8; i++) {
        #pragma unroll
        for (int j0 = 0; j0 < 8; j0 += 4) {
            float o[4];
            #pragma unroll
            for (int j = 0; j < 4; j++) {
                float v = acc[i][j0 + j] + bias[ccol0 + j0 + j];
                if (ACT == 1) v = 0.5f * v * (1.0f + erff(v * 0.70710678118654752f));
                o[j] = v;
            }
            *(float4*)(C + (size_t)(crow0 + i) * N + ccol0 + j0) = *(float4*)o;
        }
    }
}

// ---------------- rotary (in smem) + feature maps: pq=relu(q@om), pk=relu(k@om)*mask ----------------
__global__ void feat_kernel(const float* __restrict__ q, const float* __restrict__ k,
                            const float* __restrict__ om, const float* __restrict__ mask,
                            float* __restrict__ pq, float* __restrict__ pk)
{
    const int bs  = blockIdx.x;        // 0..BS-1
    const int t   = bs % S_;           // position
    const int tid = threadIdx.x;       // 384 threads

    __shared__ float sq[D_];
    __shared__ float sk[D_];
    __shared__ float som[DH_ * NF_];

    for (int i = tid; i < D_; i += 384) {
        sq[i] = q[(size_t)bs * D_ + i];
        sk[i] = k[(size_t)bs * D_ + i];
    }
    for (int i = tid; i < DH_ * NF_; i += 384) som[i] = om[i];
    __syncthreads();

    // rotary: each thread owns exactly one (head, j) pair -> no cross-thread hazard
    {
        const int hh = tid >> 5, j = tid & 31;
        const int base = hh * DH_ + j;
        float invf = expf(-(float)j * 0.28782313662425572f); // ln(1e4)/32
        float ang = (float)t * invf;
        float c = cosf(ang), s = sinf(ang);
        float qa = sq[base], qb = sq[base + 32];
        float ka = sk[base], kb = sk[base + 32];
        sq[base]      = qa * c - qb * s;
        sq[base + 32] = qb * c + qa * s;
        sk[base]      = ka * c - kb * s;
        sk[base + 32] = kb * c + ka * s;
    }
    __syncthreads();

    const int hh = tid >> 5, f = tid & 31;
    float aq = 0.f, ak = 0.f;
    #pragma unroll 16
    for (int d = 0; d < DH_; ++d) {
        float w = som[d * NF_ + f];
        aq = fmaf(sq[hh * DH_ + d], w, aq);
        ak = fmaf(sk[hh * DH_ + d], w, ak);
    }
    float m = mask[bs];
    pq[((size_t)bs * H_ + hh) * NF_ + f] = fmaxf(aq, 0.f);
    pk[((size_t)bs * H_ + hh) * NF_ + f] = fmaxf(ak, 0.f) * m;
}

// ---------------- kv[b,h,f,d] = sum_s pk*v ; ps[b,h,f] = sum_s pk ----------------
__global__ void kv_kernel(const float* __restrict__ pk, const float* __restrict__ v,
                          float* __restrict__ kv, float* __restrict__ ps)
{
    const int b = blockIdx.x / H_;
    const int h = blockIdx.x % H_;
    const int tid = threadIdx.x;      // 256

    __shared__ float spk[32][NF_];
    __shared__ float sv [32][DH_];

    const int f  = tid >> 3;          // 0..31
    const int d0 = (tid & 7) * 8;     // 0..56

    float acc[8];
    #pragma unroll
    for (int i = 0; i < 8; i++) acc[i] = 0.f;
    float psum = 0.f;

    for (int s0 = 0; s0 < S_; s0 += 32) {
        for (int i = tid; i < 32 * NF_; i += 256) {
            int sl = i >> 5, ff = i & 31;
            spk[sl][ff] = pk[(((size_t)(b * S_ + s0 + sl)) * H_ + h) * NF_ + ff];
        }
        for (int i = tid; i < 32 * DH_; i += 256) {
            int sl = i >> 6, dd = i & 63;
            sv[sl][dd] = v[((size_t)(b * S_ + s0 + sl)) * D_ + h * DH_ + dd];
        }
        __syncthreads();
        #pragma unroll 8
        for (int sl = 0; sl < 32; ++sl) {
            float pv = spk[sl][f];
            psum += pv;
            #pragma unroll
            for (int i = 0; i < 8; i++)
                acc[i] = fmaf(pv, sv[sl][d0 + i], acc[i]);
        }
        __syncthreads();
    }
    #pragma unroll
    for (int i = 0; i < 8; i++)
        kv[(((size_t)(b * H_ + h)) * NF_ + f) * DH_ + d0 + i] = acc[i];
    if ((tid & 7) == 0) ps[((size_t)(b * H_ + h)) * NF_ + f] = psum;
}

// ---------------- att[b,s,h*64+d] = (1/(pq.ps + eps)) * sum_f pq*kv ----------------
__global__ void att_kernel(const float* __restrict__ pq, const float* __restrict__ kv,
                           const float* __restrict__ ps, float* __restrict__ att)
{
    const int b = blockIdx.x / H_;
    const int h = blockIdx.x % H_;
    const int tid = threadIdx.x;   // 256

    __shared__ float skv[NF_ * DH_];
    __shared__ float sps[NF_];
    __shared__ float spq[4][NF_];

    for (int i = tid; i < NF_ * DH_; i += 256)
        skv[i] = kv[((size_t)(b * H_ + h)) * NF_ * DH_ + i];
    if (tid < NF_) sps[tid] = ps[((size_t)(b * H_ + h)) * NF_ + tid];
    __syncthreads();

    const int sl = tid >> 6;   // 0..3
    const int d  = tid & 63;

    for (int s0 = 0; s0 < S_; s0 += 4) {
        if (tid < 128) {
            int l = tid >> 5, ff = tid & 31;
            spq[l][ff] = pq[(((size_t)(b * S_ + s0 + l)) * H_ + h) * NF_ + ff];
        }
        __syncthreads();
        float za = 0.f, aa = 0.f;
        #pragma unroll 8
        for (int ff = 0; ff < NF_; ++ff) {
            float pv = spq[sl][ff];
            za = fmaf(pv, sps[ff], za);
            aa = fmaf(pv, skv[ff * DH_ + d], aa);
        }
        float z = 1.0f / (za + 1e-6f);
        att[((size_t)(b * S_ + s0 + sl)) * D_ + h * DH_ + d] = aa * z;
        __syncthreads();
    }
}

// ---------------- h = LN(h + r) * gamma + beta  (in place on h) ----------------
__global__ void addln_kernel(float* __restrict__ h, const float* __restrict__ r,
                             const float* __restrict__ gam, const float* __restrict__ bet)
{
    const int row = blockIdx.x;
    const int tid = threadIdx.x;   // 256
    const size_t base = (size_t)row * D_;

    float x0 = h[base + tid]       + r[base + tid];
    float x1 = h[base + tid + 256] + r[base + tid + 256];
    float x2 = h[base + tid + 512] + r[base + tid + 512];

    __shared__ float red[8];
    float s = x0 + x1 + x2;
    #pragma unroll
    for (int o = 16; o; o >>= 1) s += __shfl_xor_sync(0xffffffffu, s, o);
    if ((tid & 31) == 0) red[tid >> 5] = s;
    __syncthreads();
    float tot = red[0] + red[1] + red[2] + red[3] + red[4] + red[5] + red[6] + red[7];
    float mean = tot * (1.0f / 768.0f);

    float d0 = x0 - mean, d1 = x1 - mean, d2 = x2 - mean;
    float s2 = d0 * d0 + d1 * d1 + d2 * d2;
    #pragma unroll
    for (int o = 16; o; o >>= 1) s2 += __shfl_xor_sync(0xffffffffu, s2, o);
    __syncthreads();   // all reads of red[] done before overwrite
    if ((tid & 31) == 0) red[tid >> 5] = s2;
    __syncthreads();
    float var = (red[0] + red[1] + red[2] + red[3] + red[4] + red[5] + red[6] + red[7]) * (1.0f / 768.0f);
    float inv = rsqrtf(var + 1e-5f);

    h[base + tid]       = d0 * inv * gam[tid]       + bet[tid];
    h[base + tid + 256] = d1 * inv * gam[tid + 256] + bet[tid + 256];
    h[base + tid + 512] = d2 * inv * gam[tid + 512] + bet[tid + 512];
}

// ---------------- masked mean pool ----------------
__global__ void pool_kernel(const float* __restrict__ h, const float* __restrict__ mask,
                            float* __restrict__ pool)
{
    const int b = blockIdx.x;
    const int tid = threadIdx.x;   // 256
    float acc0 = 0.f, acc1 = 0.f, acc2 = 0.f, dn = 0.f;
    for (int s = 0; s < S_; ++s) {
        float m = mask[b * S_ + s];
        dn += m;
        const float* hp = h + ((size_t)(b * S_ + s)) * D_;
        acc0 += hp[tid]       * m;
        acc1 += hp[tid + 256] * m;
        acc2 += hp[tid + 512] * m;
    }
    dn = fmaxf(dn, 1e-9f);
    float idn = 1.0f / dn;
    pool[(size_t)b * D_ + tid]       = acc0 * idn;
    pool[(size_t)b * D_ + tid + 256] = acc1 * idn;
    pool[(size_t)b * D_ + tid + 512] = acc2 * idn;
}

// ---------------- final: out = relu(pool @ Wl + bl) ----------------
__global__ void final_kernel(const float* __restrict__ pool, const float* __restrict__ Wl,
                             const float* __restrict__ bl, float* __restrict__ out)
{
    const int b = blockIdx.x;
    const int o = threadIdx.x;   // 512
    __shared__ float sp[D_];
    for (int i = o; i < D_; i += 512) sp[i] = pool[(size_t)b * D_ + i];
    __syncthreads();
    float acc = bl[o];
    #pragma unroll 8
    for (int k = 0; k < D_; ++k)
        acc = fmaf(sp[k], Wl[(size_t)k * OUT_ + o], acc);
    out[(size_t)b * OUT_ + o] = fmaxf(acc, 0.f);
}

// ---------------- host ----------------
extern "C" void kernel_launch(void* const* d_in, const int* in_sizes, int n_in,
                              void* d_out, int out_size)
{
    const int*   x     = (const int*)  d_in[0];
    const float* mask  = (const float*)d_in[1];
    const float* tok   = (const float*)d_in[2];
    const float* Wq    = (const float*)d_in[3];
    const float* bq    = (const float*)d_in[4];
    const float* Wk    = (const float*)d_in[5];
    const float* bk    = (const float*)d_in[6];
    const float* Wv    = (const float*)d_in[7];
    const float* bv    = (const float*)d_in[8];
    const float* Wo    = (const float*)d_in[9];
    const float* bo    = (const float*)d_in[10];
    const float* omega = (const float*)d_in[11];
    const float* ln1s  = (const float*)d_in[12];
    const float* ln1b  = (const float*)d_in[13];
    const float* W1    = (const float*)d_in[14];
    const float* b1    = (const float*)d_in[15];
    const float* W2    = (const float*)d_in[16];
    const float* b2    = (const float*)d_in[17];
    const float* ln2s  = (const float*)d_in[18];
    const float* ln2b  = (const float*)d_in[19];
    const float* Wl    = (const float*)d_in[20];
    const float* bl    = (const float*)d_in[21];

    float *h, *q, *k, *v, *t1, *ff, *pq, *pk, *kv, *ps, *pool;
    cudaGetSymbolAddress((void**)&h,  g_h);
    cudaGetSymbolAddress((void**)&q,  g_q);
    cudaGetSymbolAddress((void**)&k,  g_k);
    cudaGetSymbolAddress((void**)&v,  g_v);
    cudaGetSymbolAddress((void**)&t1, g_t1);
    cudaGetSymbolAddress((void**)&ff, g_ff);
    cudaGetSymbolAddress((void**)&pq, g_pq);
    cudaGetSymbolAddress((void**)&pk, g_pk);
    cudaGetSymbolAddress((void**)&kv, g_kv);
    cudaGetSymbolAddress((void**)&ps, g_ps);
    cudaGetSymbolAddress((void**)&pool, g_pool);

    const int M = BS_, N = D_, K = D_;
    dim3 gGemm(N / 128, M / 128);   // (6, 256)

    embed_kernel<<<(BSD_ + 255) / 256, 256>>>(x, tok, h);

    for (int l = 0; l < NL_; ++l) {
        const float* lWq = Wq + (size_t)l * D_ * D_;
        const float* lWk = Wk + (size_t)l * D_ * D_;
        const float* lWv = Wv + (size_t)l * D_ * D_;
        const float* lWo = Wo + (size_t)l * D_ * D_;
        const float* lW1 = W1 + (size_t)l * D_ * D_;
        const float* lW2 = W2 + (size_t)l * D_ * D_;
        const float* lbq = bq + (size_t)l * D_;
        const float* lbk = bk + (size_t)l * D_;
        const float* lbv = bv + (size_t)l * D_;
        const float* lbo = bo + (size_t)l * D_;
        const float* lb1 = b1 + (size_t)l * D_;
        const float* lb2 = b2 + (size_t)l * D_;
        const float* lom = omega + (size_t)l * DH_ * NF_;
        const float* l1s = ln1s + (size_t)l * D_;
        const float* l1b = ln1b + (size_t)l * D_;
        const float* l2s = ln2s + (size_t)l * D_;
        const float* l2b = ln2b + (size_t)l * D_;

        sgemm_kernel<0><<<gGemm, 256>>>(h, lWq, lbq, q, M, N, K);
        sgemm_kernel<0><<<gGemm, 256>>>(h, lWk, lbk, k, M, N, K);
        sgemm_kernel<0><<<gGemm, 256>>>(h, lWv, lbv, v, M, N, K);

        feat_kernel<<<BS_, 384>>>(q, k, lom, mask, pq, pk);
        kv_kernel<<<B_ * H_, 256>>>(pk, v, kv, ps);
        att_kernel<<<B_ * H_, 256>>>(pq, kv, ps, t1);

        sgemm_kernel<0><<<gGemm, 256>>>(t1, lWo, lbo, q, M, N, K);  // reuse q as proj out
        addln_kernel<<<BS_, 256>>>(h, q, l1s, l1b);

        sgemm_kernel<1><<<gGemm, 256>>>(h, lW1, lb1, ff, M, N, K);  // GELU epilogue
        sgemm_kernel<0><<<gGemm, 256>>>(ff, lW2, lb2, t1, M, N, K);
        addln_kernel<<<BS_, 256>>>(h, t1, l2s, l2b);
    }

    pool_kernel<<<B_, 256>>>(h, mask, pool);
    final_kernel<<<B_, 512>>>(pool, Wl, bl, (float*)d_out);
}

// round 9
// speedup vs baseline: 1.0002x; 1.0002x over previous
#include <cuda_runtime.h>
#include <cuda_bf16.h>
#include <math.h>

#define B_  64
#define S_  512
#define D_  768
#define H_  12
#define DH_ 64
#define NF_ 32
#define NL_ 12
#define OUT_ 512

static const int BS_  = B_ * S_;        // 32768
static const int BSD_ = B_ * S_ * D_;   // 25165824

// ---------------- scratch (allowed: __device__ globals) ----------------
__device__ float g_h [B_*S_*D_];
__device__ float g_q [B_*S_*D_];
__device__ float g_k [B_*S_*D_];
__device__ float g_v [B_*S_*D_];
__device__ float g_t1[B_*S_*D_];
__device__ float g_ff[B_*S_*D_];
__device__ float g_pq[B_*S_*H_*NF_];
__device__ float g_pk[B_*S_*H_*NF_];
__device__ float g_kv[B_*H_*NF_*DH_];
__device__ float g_ps[B_*H_*NF_];
__device__ float g_pool[B_*D_];

// ---------------- embedding ----------------
__global__ void embed_kernel(const int* __restrict__ x, const float* __restrict__ emb,
                             float* __restrict__ h)
{
    long i = (long)blockIdx.x * blockDim.x + threadIdx.x;
    if (i < (long)BSD_) {
        int bs = (int)(i / D_);
        int d  = (int)(i % D_);
        h[i] = emb[(long)x[bs] * D_ + d];
    }
}

// ---------------- SGEMM: C = A[MxK] @ B[KxN] + bias, opt. exact GELU ----------------
// M%128==0, N%128==0, K%8==0 assumed (32768 x 768 x 768 here).
template<int ACT>
__global__ void __launch_bounds__(256, 2)
sgemm_kernel(const float* __restrict__ A, const float* __restrict__ Bm,
             const float* __restrict__ bias, float* __restrict__ C,
             int M, int N, int K)
{
    __shared__ float As[2][8][128];
    __shared__ float Bs[2][8][128];

    const int tid = threadIdx.x;
    const int bx = blockIdx.x, by = blockIdx.y;
    const int tx = tid & 15, ty = tid >> 4;

    const int arow = tid >> 1;           // 0..127
    const int acol = (tid & 1) << 2;     // 0 or 4
    const int brow = tid >> 5;           // 0..7
    const int bcol = (tid & 31) << 2;    // 0..124

    const float* Aptr = A  + (size_t)(by * 128 + arow) * K + acol;
    const float* Bptr = Bm + (size_t)brow * N + bx * 128 + bcol;

    float acc[8][8];
    #pragma unroll
    for (int i = 0; i < 8; i++)
        #pragma unroll
        for (int j = 0; j < 8; j++) acc[i][j] = 0.f;

    // preload tile 0
    {
        float4 a4 = *(const float4*)(Aptr);
        float4 b4 = *(const float4*)(Bptr);
        As[0][acol + 0][arow] = a4.x;
        As[0][acol + 1][arow] = a4.y;
        As[0][acol + 2][arow] = a4.z;
        As[0][acol + 3][arow] = a4.w;
        *(float4*)&Bs[0][brow][bcol] = b4;
    }
    __syncthreads();

    const int nIter = K >> 3;
    int buf = 0;
    for (int t = 0; t < nIter; ++t) {
        float4 na, nb;
        bool more = (t + 1 < nIter);
        if (more) {
            na = *(const float4*)(Aptr + (size_t)(t + 1) * 8);
            nb = *(const float4*)(Bptr + (size_t)(t + 1) * 8 * N);
        }
        #pragma unroll
        for (int kk = 0; kk < 8; ++kk) {
            float a[8], b[8];
            *(float4*)&a[0] = *(const float4*)&As[buf][kk][ty * 8];
            *(float4*)&a[4] = *(const float4*)&As[buf][kk][ty * 8 + 4];
            *(float4*)&b[0] = *(const float4*)&Bs[buf][kk][tx * 8];
            *(float4*)&b[4] = *(const float4*)&Bs[buf][kk][tx * 8 + 4];
            #pragma unroll
            for (int i = 0; i < 8; i++)
                #pragma unroll
                for (int j = 0; j < 8; j++)
                    acc[i][j] = fmaf(a[i], b[j], acc[i][j]);
        }
        if (more) {
            int nbuf = buf ^ 1;
            As[nbuf][acol + 0][arow] = na.x;
            As[nbuf][acol + 1][arow] = na.y;
            As[nbuf][acol + 2][arow] = na.z;
            As[nbuf][acol + 3][arow] = na.w;
            *(float4*)&Bs[nbuf][brow][bcol] = nb;
        }
        __syncthreads();
        buf ^= 1;
    }

    const int crow0 = by * 128 + ty * 8;
    const int ccol0 = bx * 128 + tx * 8;
    #pragma unroll
    for (int i = 0; i < 8; i++) {
        #pragma unroll
        for (int j0 = 0; j0 < 8; j0 += 4) {
            float o[4];
            #pragma unroll
            for (int j = 0; j < 4; j++) {
                float v = acc[i][j0 + j] + bias[ccol0 + j0 + j];
                if (ACT == 1) v = 0.5f * v * (1.0f + erff(v * 0.70710678118654752f));
                o[j] = v;
            }
            *(float4*)(C + (size_t)(crow0 + i) * N + ccol0 + j0) = *(float4*)o;
        }
    }
}

// ---------------- rotary (in smem) + feature maps: pq=relu(q@om), pk=relu(k@om)*mask ----------------
__global__ void feat_kernel(const float* __restrict__ q, const float* __restrict__ k,
                            const float* __restrict__ om, const float* __restrict__ mask,
                            float* __restrict__ pq, float* __restrict__ pk)
{
    const int bs  = blockIdx.x;        // 0..BS-1
    const int t   = bs % S_;           // position
    const int tid = threadIdx.x;       // 384 threads

    __shared__ float sq[D_];
    __shared__ float sk[D_];
    __shared__ float som[DH_ * NF_];

    for (int i = tid; i < D_; i += 384) {
        sq[i] = q[(size_t)bs * D_ + i];
        sk[i] = k[(size_t)bs * D_ + i];
    }
    for (int i = tid; i < DH_ * NF_; i += 384) som[i] = om[i];
    __syncthreads();

    // rotary: each thread owns exactly one (head, j) pair -> no cross-thread hazard
    {
        const int hh = tid >> 5, j = tid & 31;
        const int base = hh * DH_ + j;
        float invf = expf(-(float)j * 0.28782313662425572f); // ln(1e4)/32
        float ang = (float)t * invf;
        float c = cosf(ang), s = sinf(ang);
        float qa = sq[base], qb = sq[base + 32];
        float ka = sk[base], kb = sk[base + 32];
        sq[base]      = qa * c - qb * s;
        sq[base + 32] = qb * c + qa * s;
        sk[base]      = ka * c - kb * s;
        sk[base + 32] = kb * c + ka * s;
    }
    __syncthreads();

    const int hh = tid >> 5, f = tid & 31;
    float aq = 0.f, ak = 0.f;
    #pragma unroll 16
    for (int d = 0; d < DH_; ++d) {
        float w = som[d * NF_ + f];
        aq = fmaf(sq[hh * DH_ + d], w, aq);
        ak = fmaf(sk[hh * DH_ + d], w, ak);
    }
    float m = mask[bs];
    pq[((size_t)bs * H_ + hh) * NF_ + f] = fmaxf(aq, 0.f);
    pk[((size_t)bs * H_ + hh) * NF_ + f] = fmaxf(ak, 0.f) * m;
}

// ---------------- kv[b,h,f,d] = sum_s pk*v ; ps[b,h,f] = sum_s pk ----------------
__global__ void kv_kernel(const float* __restrict__ pk, const float* __restrict__ v,
                          float* __restrict__ kv, float* __restrict__ ps)
{
    const int b = blockIdx.x / H_;
    const int h = blockIdx.x % H_;
    const int tid = threadIdx.x;      // 256

    __shared__ float spk[32][NF_];
    __shared__ float sv [32][DH_];

    const int f  = tid >> 3;          // 0..31
    const int d0 = (tid & 7) * 8;     // 0..56

    float acc[8];
    #pragma unroll
    for (int i = 0; i < 8; i++) acc[i] = 0.f;
    float psum = 0.f;

    for (int s0 = 0; s0 < S_; s0 += 32) {
        for (int i = tid; i < 32 * NF_; i += 256) {
            int sl = i >> 5, ff = i & 31;
            spk[sl][ff] = pk[(((size_t)(b * S_ + s0 + sl)) * H_ + h) * NF_ + ff];
        }
        for (int i = tid; i < 32 * DH_; i += 256) {
            int sl = i >> 6, dd = i & 63;
            sv[sl][dd] = v[((size_t)(b * S_ + s0 + sl)) * D_ + h * DH_ + dd];
        }
        __syncthreads();
        #pragma unroll 8
        for (int sl = 0; sl < 32; ++sl) {
            float pv = spk[sl][f];
            psum += pv;
            #pragma unroll
            for (int i = 0; i < 8; i++)
                acc[i] = fmaf(pv, sv[sl][d0 + i], acc[i]);
        }
        __syncthreads();
    }
    #pragma unroll
    for (int i = 0; i < 8; i++)
        kv[(((size_t)(b * H_ + h)) * NF_ + f) * DH_ + d0 + i] = acc[i];
    if ((tid & 7) == 0) ps[((size_t)(b * H_ + h)) * NF_ + f] = psum;
}

// ---------------- att[b,s,h*64+d] = (1/(pq.ps + eps)) * sum_f pq*kv ----------------
__global__ void att_kernel(const float* __restrict__ pq, const float* __restrict__ kv,
                           const float* __restrict__ ps, float* __restrict__ att)
{
    const int b = blockIdx.x / H_;
    const int h = blockIdx.x % H_;
    const int tid = threadIdx.x;   // 256

    __shared__ float skv[NF_ * DH_];
    __shared__ float sps[NF_];
    __shared__ float spq[4][NF_];

    for (int i = tid; i < NF_ * DH_; i += 256)
        skv[i] = kv[((size_t)(b * H_ + h)) * NF_ * DH_ + i];
    if (tid < NF_) sps[tid] = ps[((size_t)(b * H_ + h)) * NF_ + tid];
    __syncthreads();

    const int sl = tid >> 6;   // 0..3
    const int d  = tid & 63;

    for (int s0 = 0; s0 < S_; s0 += 4) {
        if (tid < 128) {
            int l = tid >> 5, ff = tid & 31;
            spq[l][ff] = pq[(((size_t)(b * S_ + s0 + l)) * H_ + h) * NF_ + ff];
        }
        __syncthreads();
        float za = 0.f, aa = 0.f;
        #pragma unroll 8
        for (int ff = 0; ff < NF_; ++ff) {
            float pv = spq[sl][ff];
            za = fmaf(pv, sps[ff], za);
            aa = fmaf(pv, skv[ff * DH_ + d], aa);
        }
        float z = 1.0f / (za + 1e-6f);
        att[((size_t)(b * S_ + s0 + sl)) * D_ + h * DH_ + d] = aa * z;
        __syncthreads();
    }
}

// ---------------- h = LN(h + r) * gamma + beta  (in place on h) ----------------
__global__ void addln_kernel(float* __restrict__ h, const float* __restrict__ r,
                             const float* __restrict__ gam, const float* __restrict__ bet)
{
    const int row = blockIdx.x;
    const int tid = threadIdx.x;   // 256
    const size_t base = (size_t)row * D_;

    float x0 = h[base + tid]       + r[base + tid];
    float x1 = h[base + tid + 256] + r[base + tid + 256];
    float x2 = h[base + tid + 512] + r[base + tid + 512];

    __shared__ float red[8];
    float s = x0 + x1 + x2;
    #pragma unroll
    for (int o = 16; o; o >>= 1) s += __shfl_xor_sync(0xffffffffu, s, o);
    if ((tid & 31) == 0) red[tid >> 5] = s;
    __syncthreads();
    float tot = red[0] + red[1] + red[2] + red[3] + red[4] + red[5] + red[6] + red[7];
    float mean = tot * (1.0f / 768.0f);

    float d0 = x0 - mean, d1 = x1 - mean, d2 = x2 - mean;
    float s2 = d0 * d0 + d1 * d1 + d2 * d2;
    #pragma unroll
    for (int o = 16; o; o >>= 1) s2 += __shfl_xor_sync(0xffffffffu, s2, o);
    __syncthreads();   // all reads of red[] done before overwrite
    if ((tid & 31) == 0) red[tid >> 5] = s2;
    __syncthreads();
    float var = (red[0] + red[1] + red[2] + red[3] + red[4] + red[5] + red[6] + red[7]) * (1.0f / 768.0f);
    float inv = rsqrtf(var + 1e-5f);

    h[base + tid]       = d0 * inv * gam[tid]       + bet[tid];
    h[base + tid + 256] = d1 * inv * gam[tid + 256] + bet[tid + 256];
    h[base + tid + 512] = d2 * inv * gam[tid + 512] + bet[tid + 512];
}

// ---------------- masked mean pool ----------------
__global__ void pool_kernel(const float* __restrict__ h, const float* __restrict__ mask,
                            float* __restrict__ pool)
{
    const int b = blockIdx.x;
    const int tid = threadIdx.x;   // 256
    float acc0 = 0.f, acc1 = 0.f, acc2 = 0.f, dn = 0.f;
    for (int s = 0; s < S_; ++s) {
        float m = mask[b * S_ + s];
        dn += m;
        const float* hp = h + ((size_t)(b * S_ + s)) * D_;
        acc0 += hp[tid]       * m;
        acc1 += hp[tid + 256] * m;
        acc2 += hp[tid + 512] * m;
    }
    dn = fmaxf(dn, 1e-9f);
    float idn = 1.0f / dn;
    pool[(size_t)b * D_ + tid]       = acc0 * idn;
    pool[(size_t)b * D_ + tid + 256] = acc1 * idn;
    pool[(size_t)b * D_ + tid + 512] = acc2 * idn;
}

// ---------------- final: out = relu(pool @ Wl + bl) ----------------
__global__ void final_kernel(const float* __restrict__ pool, const float* __restrict__ Wl,
                             const float* __restrict__ bl, float* __restrict__ out)
{
    const int b = blockIdx.x;
    const int o = threadIdx.x;   // 512
    __shared__ float sp[D_];
    for (int i = o; i < D_; i += 512) sp[i] = pool[(size_t)b * D_ + i];
    __syncthreads();
    float acc = bl[o];
    #pragma unroll 8
    for (int k = 0; k < D_; ++k)
        acc = fmaf(sp[k], Wl[(size_t)k * OUT_ + o], acc);
    out[(size_t)b * OUT_ + o] = fmaxf(acc, 0.f);
}

// ---------------- host ----------------
extern "C" void kernel_launch(void* const* d_in, const int* in_sizes, int n_in,
                              void* d_out, int out_size)
{
    const int*   x     = (const int*)  d_in[0];
    const float* mask  = (const float*)d_in[1];
    const float* tok   = (const float*)d_in[2];
    const float* Wq    = (const float*)d_in[3];
    const float* bq    = (const float*)d_in[4];
    const float* Wk    = (const float*)d_in[5];
    const float* bk    = (const float*)d_in[6];
    const float* Wv    = (const float*)d_in[7];
    const float* bv    = (const float*)d_in[8];
    const float* Wo    = (const float*)d_in[9];
    const float* bo    = (const float*)d_in[10];
    const float* omega = (const float*)d_in[11];
    const float* ln1s  = (const float*)d_in[12];
    const float* ln1b  = (const float*)d_in[13];
    const float* W1    = (const float*)d_in[14];
    const float* b1    = (const float*)d_in[15];
    const float* W2    = (const float*)d_in[16];
    const float* b2    = (const float*)d_in[17];
    const float* ln2s  = (const float*)d_in[18];
    const float* ln2b  = (const float*)d_in[19];
    const float* Wl    = (const float*)d_in[20];
    const float* bl    = (const float*)d_in[21];

    float *h, *q, *k, *v, *t1, *ff, *pq, *pk, *kv, *ps, *pool;
    cudaGetSymbolAddress((void**)&h,  g_h);
    cudaGetSymbolAddress((void**)&q,  g_q);
    cudaGetSymbolAddress((void**)&k,  g_k);
    cudaGetSymbolAddress((void**)&v,  g_v);
    cudaGetSymbolAddress((void**)&t1, g_t1);
    cudaGetSymbolAddress((void**)&ff, g_ff);
    cudaGetSymbolAddress((void**)&pq, g_pq);
    cudaGetSymbolAddress((void**)&pk, g_pk);
    cudaGetSymbolAddress((void**)&kv, g_kv);
    cudaGetSymbolAddress((void**)&ps, g_ps);
    cudaGetSymbolAddress((void**)&pool, g_pool);

    const int M = BS_, N = D_, K = D_;
    dim3 gGemm(N / 128, M / 128);   // (6, 256)

    embed_kernel<<<(BSD_ + 255) / 256, 256>>>(x, tok, h);

    for (int l = 0; l < NL_; ++l) {
        const float* lWq = Wq + (size_t)l * D_ * D_;
        const float* lWk = Wk + (size_t)l * D_ * D_;
        const float* lWv = Wv + (size_t)l * D_ * D_;
        const float* lWo = Wo + (size_t)l * D_ * D_;
        const float* lW1 = W1 + (size_t)l * D_ * D_;
        const float* lW2 = W2 + (size_t)l * D_ * D_;
        const float* lbq = bq + (size_t)l * D_;
        const float* lbk = bk + (size_t)l * D_;
        const float* lbv = bv + (size_t)l * D_;
        const float* lbo = bo + (size_t)l * D_;
        const float* lb1 = b1 + (size_t)l * D_;
        const float* lb2 = b2 + (size_t)l * D_;
        const float* lom = omega + (size_t)l * DH_ * NF_;
        const float* l1s = ln1s + (size_t)l * D_;
        const float* l1b = ln1b + (size_t)l * D_;
        const float* l2s = ln2s + (size_t)l * D_;
        const float* l2b = ln2b + (size_t)l * D_;

        sgemm_kernel<0><<<gGemm, 256>>>(h, lWq, lbq, q, M, N, K);
        sgemm_kernel<0><<<gGemm, 256>>>(h, lWk, lbk, k, M, N, K);
        sgemm_kernel<0><<<gGemm, 256>>>(h, lWv, lbv, v, M, N, K);

        feat_kernel<<<BS_, 384>>>(q, k, lom, mask, pq, pk);
        kv_kernel<<<B_ * H_, 256>>>(pk, v, kv, ps);
        att_kernel<<<B_ * H_, 256>>>(pq, kv, ps, t1);

        sgemm_kernel<0><<<gGemm, 256>>>(t1, lWo, lbo, q, M, N, K);  // reuse q as proj out
        addln_kernel<<<BS_, 256>>>(h, q, l1s, l1b);

        sgemm_kernel<1><<<gGemm, 256>>>(h, lW1, lb1, ff, M, N, K);  // GELU epilogue
        sgemm_kernel<0><<<gGemm, 256>>>(ff, lW2, lb2, t1, M, N, K);
        addln_kernel<<<BS_, 256>>>(h, t1, l2s, l2b);
    }

    pool_kernel<<<B_, 256>>>(h, mask, pool);
    final_kernel<<<B_, 512>>>(pool, Wl, bl, (float*)d_out);
}

// round 11
// speedup vs baseline: 1.7902x; 1.7898x over previous
#include <cuda_runtime.h>
#include <cuda_bf16.h>
#include <math.h>
#include <stdint.h>

#define B_  64
#define S_  512
#define D_  768
#define H_  12
#define DH_ 64
#define NF_ 32
#define NL_ 12
#define OUT_ 512

static const int BS_  = B_ * S_;        // 32768
static const int BSD_ = B_ * S_ * D_;   // 25165824

// ---------------- scratch (allowed: __device__ globals) ----------------
__device__ float g_h [B_*S_*D_];
__device__ float g_q [B_*S_*D_];
__device__ float g_k [B_*S_*D_];
__device__ float g_v [B_*S_*D_];
__device__ float g_t1[B_*S_*D_];
__device__ float g_ff[B_*S_*D_];
__device__ float g_pq[B_*S_*H_*NF_];
__device__ float g_pk[B_*S_*H_*NF_];
__device__ float g_kv[B_*H_*NF_*DH_];
__device__ float g_ps[B_*H_*NF_];
__device__ float g_pool[B_*D_];
// pre-split transposed weights: [mat 0..5][layer][n][k], bf16 hi/lo
__device__ __nv_bfloat16 g_whi[6 * NL_ * D_ * D_];
__device__ __nv_bfloat16 g_wlo[6 * NL_ * D_ * D_];

// ==================== PTX helpers (arch-agnostic: ldmatrix/mma/cp.async) ====================
__device__ __forceinline__ uint32_t smem_u32(const void* p){
    uint32_t a;
    asm("{ .reg .u64 t; cvta.to.shared.u64 t, %1; cvt.u32.u64 %0, t; }" : "=r"(a) : "l"(p));
    return a;
}

#define LDSMX4(r, addr) \
    asm volatile("ldmatrix.sync.aligned.m8n8.x4.shared.b16 {%0,%1,%2,%3}, [%4];" \
        : "=r"((r)[0]), "=r"((r)[1]), "=r"((r)[2]), "=r"((r)[3]) : "r"(addr))

#define MMA16816(d, a, b) \
    asm volatile("mma.sync.aligned.m16n8k16.row.col.f32.bf16.bf16.f32 " \
        "{%0,%1,%2,%3}, {%4,%5,%6,%7}, {%8,%9}, {%0,%1,%2,%3};" \
        : "+f"((d)[0]), "+f"((d)[1]), "+f"((d)[2]), "+f"((d)[3]) \
        : "r"((a)[0]), "r"((a)[1]), "r"((a)[2]), "r"((a)[3]), \
          "r"((b)[0]), "r"((b)[1]))

#define CP_ASYNC16(dst, src) \
    asm volatile("cp.async.cg.shared.global [%0], [%1], 16;" :: "r"(dst), "l"(src))
#define CP_COMMIT() asm volatile("cp.async.commit_group;" ::: "memory")
#define CP_WAIT0()  asm volatile("cp.async.wait_group 0;" ::: "memory")

// ---------------- embedding ----------------
__global__ void embed_kernel(const int* __restrict__ x, const float* __restrict__ emb,
                             float* __restrict__ h)
{
    long i = (long)blockIdx.x * blockDim.x + threadIdx.x;
    if (i < (long)BSD_) {
        int bs = (int)(i / D_);
        int d  = (int)(i % D_);
        h[i] = emb[(long)x[bs] * D_ + d];
    }
}

// ---------------- weight transpose + bf16 hi/lo split ----------------
// in:  W[l][k][n] (12 x 768 x 768 fp32); out: whi/wlo[(l*768+n)*768+k] ([N,K] K-major)
__global__ void wsplit_kernel(const float* __restrict__ W,
                              __nv_bfloat16* __restrict__ whi,
                              __nv_bfloat16* __restrict__ wlo)
{
    __shared__ float s[32][33];
    const int l  = blockIdx.z;
    const int k0 = blockIdx.x * 32;
    const int n0 = blockIdx.y * 32;
    const int tx = threadIdx.x;       // 0..31
    const int ty = threadIdx.y;       // 0..7
    const float* Wl = W + (size_t)l * D_ * D_;
    #pragma unroll
    for (int i = 0; i < 4; i++)
        s[ty + 8 * i][tx] = Wl[(size_t)(k0 + ty + 8 * i) * D_ + n0 + tx];
    __syncthreads();
    #pragma unroll
    for (int i = 0; i < 4; i++) {
        int n = n0 + ty + 8 * i;
        int k = k0 + tx;
        float v = s[tx][ty + 8 * i];
        __nv_bfloat16 hi = __float2bfloat16(v);
        __nv_bfloat16 lo = __float2bfloat16(v - __bfloat162float(hi));
        size_t o = ((size_t)l * D_ + n) * D_ + k;
        whi[o] = hi;
        wlo[o] = lo;
    }
}

// ==================== mma.sync bf16x2 GEMM ====================
// C[32768,768] = A[32768,768](fp32) @ W[768,768] + bias (+ exact GELU if ACT)
// W pre-split bf16 hi/lo, [N,K] K-major.  Tile 128x128x32, 8 warps (4m x 2n).
// SMEM rows padded to 80B (40 bf16) -> conflict-free ldmatrix.
#define GB_BUF    40960          // one buffer: Ahi,Alo,Bhi,Blo @ 10240 each
#define GB_AHI    0
#define GB_ALO    10240
#define GB_BHI    20480
#define GB_BLO    30720
#define GB_SMEM   (2 * GB_BUF)   // 81920

template<int ACT>
__global__ void __launch_bounds__(256, 1)
mmagemm_kernel(const float* __restrict__ A,
               const __nv_bfloat16* __restrict__ Whi,
               const __nv_bfloat16* __restrict__ Wlo,
               const float* __restrict__ bias, float* __restrict__ C)
{
    extern __shared__ char dsm[];
    const uint32_t sb32 = smem_u32(dsm);

    const int tid  = threadIdx.x;
    const int wid  = tid >> 5, lane = tid & 31;
    const int bx   = blockIdx.x;   // N tile (0..5)
    const int by   = blockIdx.y;   // M tile (0..255)
    const int wm   = wid >> 1;     // 0..3  (32 rows each)
    const int wn   = wid & 1;      // 0..1  (64 cols each)

    // ---- staging thread mapping: row r (0..127), half hf (16 elems) ----
    const int r  = tid >> 1;
    const int hf = tid & 1;
    const float*         Ap  = A   + ((size_t)(by * 128) + r) * 768 + hf * 16;
    const __nv_bfloat16* Bhp = Whi + ((size_t)(bx * 128) + r) * 768 + hf * 16;
    const __nv_bfloat16* Blp = Wlo + ((size_t)(bx * 128) + r) * 768 + hf * 16;
    const uint32_t stOff = (uint32_t)r * 80u + (uint32_t)hf * 32u;

    // ---- ldmatrix per-lane offsets ----
    const uint32_t offA = (uint32_t)(wm * 32 + (lane & 15)) * 80u + ((lane >> 4) & 1) * 16u;
    const uint32_t offB = (uint32_t)(wn * 64 + (lane & 7) + ((lane >> 4) & 1) * 8) * 80u
                        + ((lane >> 3) & 1) * 16u;

    float acc[2][8][4];
    #pragma unroll
    for (int mt = 0; mt < 2; mt++)
        #pragma unroll
        for (int nt = 0; nt < 8; nt++)
            #pragma unroll
            for (int j = 0; j < 4; j++) acc[mt][nt][j] = 0.f;

    // ---- helpers ----
    auto cpasyncB = [&](int kt, int buf) {
        uint32_t d = sb32 + (uint32_t)buf * GB_BUF;
        const char* sh = (const char*)(Bhp + kt * 32);
        const char* sl = (const char*)(Blp + kt * 32);
        CP_ASYNC16(d + GB_BHI + stOff,      sh);
        CP_ASYNC16(d + GB_BHI + stOff + 16, sh + 16);
        CP_ASYNC16(d + GB_BLO + stOff,      sl);
        CP_ASYNC16(d + GB_BLO + stOff + 16, sl + 16);
    };
    auto ldgA = [&](int kt, float* a_st) {
        const float4* s = (const float4*)(Ap + kt * 32);
        *(float4*)&a_st[0]  = s[0];
        *(float4*)&a_st[4]  = s[1];
        *(float4*)&a_st[8]  = s[2];
        *(float4*)&a_st[12] = s[3];
    };
    auto stsA = [&](const float* a_st, int buf) {
        uint32_t hi[8], lo[8];
        #pragma unroll
        for (int i = 0; i < 8; i++) {
            float f0 = a_st[2 * i], f1 = a_st[2 * i + 1];
            uint32_t u0 = __float_as_uint(f0), u1 = __float_as_uint(f1);
            asm("prmt.b32 %0, %1, %2, 0x7632;" : "=r"(hi[i]) : "r"(u0), "r"(u1));
            float f0l = f0 - __uint_as_float(u0 & 0xFFFF0000u);
            float f1l = f1 - __uint_as_float(u1 & 0xFFFF0000u);
            __nv_bfloat162 lp = __floats2bfloat162_rn(f0l, f1l);
            lo[i] = *(uint32_t*)&lp;
        }
        char* d = dsm + (size_t)buf * GB_BUF + stOff;
        *(uint4*)(d + GB_AHI)      = make_uint4(hi[0], hi[1], hi[2], hi[3]);
        *(uint4*)(d + GB_AHI + 16) = make_uint4(hi[4], hi[5], hi[6], hi[7]);
        *(uint4*)(d + GB_ALO)      = make_uint4(lo[0], lo[1], lo[2], lo[3]);
        *(uint4*)(d + GB_ALO + 16) = make_uint4(lo[4], lo[5], lo[6], lo[7]);
    };

    // ---- prologue: chunk 0 -> buf 0 ----
    {
        float a_st[16];
        cpasyncB(0, 0); CP_COMMIT();
        ldgA(0, a_st);
        stsA(a_st, 0);
        CP_WAIT0();
        __syncthreads();
    }

    #pragma unroll 1
    for (int t = 0; t < 24; ++t) {
        const int cur = t & 1, nxt = cur ^ 1;
        const bool more = (t + 1 < 24);
        float a_st[16];
        if (more) {
            cpasyncB(t + 1, nxt); CP_COMMIT();
            ldgA(t + 1, a_st);
        }

        // ---- MMA on buf cur ----
        const uint32_t bufb = sb32 + (uint32_t)cur * GB_BUF;
        #pragma unroll
        for (int ks = 0; ks < 2; ks++) {
            uint32_t ah[2][4], al[2][4];
            #pragma unroll
            for (int mt = 0; mt < 2; mt++) {
                uint32_t ad = bufb + offA + (uint32_t)mt * (16u * 80u) + (uint32_t)ks * 32u;
                LDSMX4(ah[mt], ad + GB_AHI);
                LDSMX4(al[mt], ad + GB_ALO);
            }
            #pragma unroll
            for (int half = 0; half < 2; half++) {
                uint32_t bh[4][2], bl[4][2];
                #pragma unroll
                for (int np = 0; np < 2; np++) {
                    uint32_t bd = bufb + offB + (uint32_t)(half * 2 + np) * (16u * 80u)
                                + (uint32_t)ks * 32u;
                    uint32_t th[4], tl[4];
                    LDSMX4(th, bd + GB_BHI);
                    LDSMX4(tl, bd + GB_BLO);
                    bh[2*np][0] = th[0]; bh[2*np][1] = th[1];
                    bh[2*np+1][0] = th[2]; bh[2*np+1][1] = th[3];
                    bl[2*np][0] = tl[0]; bl[2*np][1] = tl[1];
                    bl[2*np+1][0] = tl[2]; bl[2*np+1][1] = tl[3];
                }
                #pragma unroll
                for (int mt = 0; mt < 2; mt++)
                    #pragma unroll
                    for (int j = 0; j < 4; j++) {
                        int nt = half * 4 + j;
                        MMA16816(acc[mt][nt], ah[mt], bh[j]);
                        MMA16816(acc[mt][nt], ah[mt], bl[j]);
                        MMA16816(acc[mt][nt], al[mt], bh[j]);
                    }
            }
        }

        if (more) {
            stsA(a_st, nxt);
            CP_WAIT0();
        }
        __syncthreads();
    }

    // ---- epilogue ----
    const int erow = lane >> 2;
    const int ecol = (lane & 3) * 2;
    #pragma unroll
    for (int mt = 0; mt < 2; mt++) {
        #pragma unroll
        for (int nt = 0; nt < 8; nt++) {
            int grow = by * 128 + wm * 32 + mt * 16 + erow;
            int gcol = bx * 128 + wn * 64 + nt * 8 + ecol;
            float b0 = __ldg(bias + gcol), b1 = __ldg(bias + gcol + 1);
            float v0 = acc[mt][nt][0] + b0;
            float v1 = acc[mt][nt][1] + b1;
            float v2 = acc[mt][nt][2] + b0;
            float v3 = acc[mt][nt][3] + b1;
            if (ACT == 1) {
                v0 = 0.5f * v0 * (1.0f + erff(v0 * 0.70710678118654752f));
                v1 = 0.5f * v1 * (1.0f + erff(v1 * 0.70710678118654752f));
                v2 = 0.5f * v2 * (1.0f + erff(v2 * 0.70710678118654752f));
                v3 = 0.5f * v3 * (1.0f + erff(v3 * 0.70710678118654752f));
            }
            *(float2*)(C + (size_t)grow * 768 + gcol)       = make_float2(v0, v1);
            *(float2*)(C + (size_t)(grow + 8) * 768 + gcol) = make_float2(v2, v3);
        }
    }
}

// ---------------- rotary (in smem) + feature maps ----------------
__global__ void feat_kernel(const float* __restrict__ q, const float* __restrict__ k,
                            const float* __restrict__ om, const float* __restrict__ mask,
                            float* __restrict__ pq, float* __restrict__ pk)
{
    const int bs  = blockIdx.x;
    const int t   = bs % S_;
    const int tid = threadIdx.x;       // 384 threads

    __shared__ float sq[D_];
    __shared__ float sk[D_];
    __shared__ float som[DH_ * NF_];

    for (int i = tid; i < D_; i += 384) {
        sq[i] = q[(size_t)bs * D_ + i];
        sk[i] = k[(size_t)bs * D_ + i];
    }
    for (int i = tid; i < DH_ * NF_; i += 384) som[i] = om[i];
    __syncthreads();

    {
        const int hh = tid >> 5, j = tid & 31;
        const int base = hh * DH_ + j;
        float invf = expf(-(float)j * 0.28782313662425572f);
        float ang = (float)t * invf;
        float c = cosf(ang), s = sinf(ang);
        float qa = sq[base], qb = sq[base + 32];
        float ka = sk[base], kb = sk[base + 32];
        sq[base]      = qa * c - qb * s;
        sq[base + 32] = qb * c + qa * s;
        sk[base]      = ka * c - kb * s;
        sk[base + 32] = kb * c + ka * s;
    }
    __syncthreads();

    const int hh = tid >> 5, f = tid & 31;
    float aq = 0.f, ak = 0.f;
    #pragma unroll 16
    for (int d = 0; d < DH_; ++d) {
        float w = som[d * NF_ + f];
        aq = fmaf(sq[hh * DH_ + d], w, aq);
        ak = fmaf(sk[hh * DH_ + d], w, ak);
    }
    float m = mask[bs];
    pq[((size_t)bs * H_ + hh) * NF_ + f] = fmaxf(aq, 0.f);
    pk[((size_t)bs * H_ + hh) * NF_ + f] = fmaxf(ak, 0.f) * m;
}

// ---------------- kv + pk row-sum ----------------
__global__ void kv_kernel(const float* __restrict__ pk, const float* __restrict__ v,
                          float* __restrict__ kv, float* __restrict__ ps)
{
    const int b = blockIdx.x / H_;
    const int h = blockIdx.x % H_;
    const int tid = threadIdx.x;      // 256

    __shared__ float spk[32][NF_];
    __shared__ float sv [32][DH_];

    const int f  = tid >> 3;
    const int d0 = (tid & 7) * 8;

    float acc[8];
    #pragma unroll
    for (int i = 0; i < 8; i++) acc[i] = 0.f;
    float psum = 0.f;

    for (int s0 = 0; s0 < S_; s0 += 32) {
        for (int i = tid; i < 32 * NF_; i += 256) {
            int sl = i >> 5, ff = i & 31;
            spk[sl][ff] = pk[(((size_t)(b * S_ + s0 + sl)) * H_ + h) * NF_ + ff];
        }
        for (int i = tid; i < 32 * DH_; i += 256) {
            int sl = i >> 6, dd = i & 63;
            sv[sl][dd] = v[((size_t)(b * S_ + s0 + sl)) * D_ + h * DH_ + dd];
        }
        __syncthreads();
        #pragma unroll 8
        for (int sl = 0; sl < 32; ++sl) {
            float pv = spk[sl][f];
            psum += pv;
            #pragma unroll
            for (int i = 0; i < 8; i++)
                acc[i] = fmaf(pv, sv[sl][d0 + i], acc[i]);
        }
        __syncthreads();
    }
    #pragma unroll
    for (int i = 0; i < 8; i++)
        kv[(((size_t)(b * H_ + h)) * NF_ + f) * DH_ + d0 + i] = acc[i];
    if ((tid & 7) == 0) ps[((size_t)(b * H_ + h)) * NF_ + f] = psum;
}

// ---------------- att: z normalize + pq@kv (512 threads) ----------------
__global__ void att_kernel(const float* __restrict__ pq, const float* __restrict__ kv,
                           const float* __restrict__ ps, float* __restrict__ att)
{
    const int b = blockIdx.x / H_;
    const int h = blockIdx.x % H_;
    const int tid = threadIdx.x;   // 512

    __shared__ float skv[NF_ * DH_];
    __shared__ float sps[NF_];
    __shared__ float spq[8][NF_];

    for (int i = tid; i < NF_ * DH_; i += 512)
        skv[i] = kv[((size_t)(b * H_ + h)) * NF_ * DH_ + i];
    if (tid < NF_) sps[tid] = ps[((size_t)(b * H_ + h)) * NF_ + tid];
    __syncthreads();

    const int sl = tid >> 6;   // 0..7
    const int d  = tid & 63;

    for (int s0 = 0; s0 < S_; s0 += 8) {
        if (tid < 256) {
            int l = tid >> 5, ff = tid & 31;
            spq[l][ff] = pq[(((size_t)(b * S_ + s0 + l)) * H_ + h) * NF_ + ff];
        }
        __syncthreads();
        float za = 0.f, aa = 0.f;
        #pragma unroll 8
        for (int ff = 0; ff < NF_; ++ff) {
            float pv = spq[sl][ff];
            za = fmaf(pv, sps[ff], za);
            aa = fmaf(pv, skv[ff * DH_ + d], aa);
        }
        float z = 1.0f / (za + 1e-6f);
        att[((size_t)(b * S_ + s0 + sl)) * D_ + h * DH_ + d] = aa * z;
        __syncthreads();
    }
}

// ---------------- residual + LayerNorm ----------------
__global__ void addln_kernel(float* __restrict__ h, const float* __restrict__ r,
                             const float* __restrict__ gam, const float* __restrict__ bet)
{
    const int row = blockIdx.x;
    const int tid = threadIdx.x;   // 256
    const size_t base = (size_t)row * D_;

    float x0 = h[base + tid]       + r[base + tid];
    float x1 = h[base + tid + 256] + r[base + tid + 256];
    float x2 = h[base + tid + 512] + r[base + tid + 512];

    __shared__ float red[8];
    float s = x0 + x1 + x2;
    #pragma unroll
    for (int o = 16; o; o >>= 1) s += __shfl_xor_sync(0xffffffffu, s, o);
    if ((tid & 31) == 0) red[tid >> 5] = s;
    __syncthreads();
    float tot = red[0] + red[1] + red[2] + red[3] + red[4] + red[5] + red[6] + red[7];
    float mean = tot * (1.0f / 768.0f);

    float d0 = x0 - mean, d1 = x1 - mean, d2 = x2 - mean;
    float s2 = d0 * d0 + d1 * d1 + d2 * d2;
    #pragma unroll
    for (int o = 16; o; o >>= 1) s2 += __shfl_xor_sync(0xffffffffu, s2, o);
    __syncthreads();
    if ((tid & 31) == 0) red[tid >> 5] = s2;
    __syncthreads();
    float var = (red[0] + red[1] + red[2] + red[3] + red[4] + red[5] + red[6] + red[7]) * (1.0f / 768.0f);
    float inv = rsqrtf(var + 1e-5f);

    h[base + tid]       = d0 * inv * gam[tid]       + bet[tid];
    h[base + tid + 256] = d1 * inv * gam[tid + 256] + bet[tid + 256];
    h[base + tid + 512] = d2 * inv * gam[tid + 512] + bet[tid + 512];
}

// ---------------- masked mean pool (parallel over column chunks) ----------------
__global__ void pool_kernel(const float* __restrict__ h, const float* __restrict__ mask,
                            float* __restrict__ pool)
{
    const int b = blockIdx.x;
    const int c = blockIdx.y * 128 + threadIdx.x;   // grid.y = 6, 128 threads
    float acc = 0.f, dn = 0.f;
    for (int s = 0; s < S_; ++s) {
        float m = mask[b * S_ + s];
        dn += m;
        acc += h[((size_t)(b * S_ + s)) * D_ + c] * m;
    }
    dn = fmaxf(dn, 1e-9f);
    pool[(size_t)b * D_ + c] = acc / dn;
}

// ---------------- final: out = relu(pool @ Wl + bl) ----------------
__global__ void final_kernel(const float* __restrict__ pool, const float* __restrict__ Wl,
                             const float* __restrict__ bl, float* __restrict__ out)
{
    const int b = blockIdx.x;
    const int o = threadIdx.x;   // 512
    __shared__ float sp[D_];
    for (int i = o; i < D_; i += 512) sp[i] = pool[(size_t)b * D_ + i];
    __syncthreads();
    float acc = bl[o];
    #pragma unroll 8
    for (int k = 0; k < D_; ++k)
        acc = fmaf(sp[k], Wl[(size_t)k * OUT_ + o], acc);
    out[(size_t)b * OUT_ + o] = fmaxf(acc, 0.f);
}

// ---------------- host ----------------
extern "C" void kernel_launch(void* const* d_in, const int* in_sizes, int n_in,
                              void* d_out, int out_size)
{
    const int*   x     = (const int*)  d_in[0];
    const float* mask  = (const float*)d_in[1];
    const float* tok   = (const float*)d_in[2];
    const float* Wq    = (const float*)d_in[3];
    const float* bq    = (const float*)d_in[4];
    const float* Wk    = (const float*)d_in[5];
    const float* bk    = (const float*)d_in[6];
    const float* Wv    = (const float*)d_in[7];
    const float* bv    = (const float*)d_in[8];
    const float* Wo    = (const float*)d_in[9];
    const float* bo    = (const float*)d_in[10];
    const float* omega = (const float*)d_in[11];
    const float* ln1s  = (const float*)d_in[12];
    const float* ln1b  = (const float*)d_in[13];
    const float* W1    = (const float*)d_in[14];
    const float* b1    = (const float*)d_in[15];
    const float* W2    = (const float*)d_in[16];
    const float* b2    = (const float*)d_in[17];
    const float* ln2s  = (const float*)d_in[18];
    const float* ln2b  = (const float*)d_in[19];
    const float* Wl    = (const float*)d_in[20];
    const float* bl    = (const float*)d_in[21];

    float *h, *q, *k, *v, *t1, *ff, *pq, *pk, *kv, *ps, *pool;
    __nv_bfloat16 *whi, *wlo;
    cudaGetSymbolAddress((void**)&h,  g_h);
    cudaGetSymbolAddress((void**)&q,  g_q);
    cudaGetSymbolAddress((void**)&k,  g_k);
    cudaGetSymbolAddress((void**)&v,  g_v);
    cudaGetSymbolAddress((void**)&t1, g_t1);
    cudaGetSymbolAddress((void**)&ff, g_ff);
    cudaGetSymbolAddress((void**)&pq, g_pq);
    cudaGetSymbolAddress((void**)&pk, g_pk);
    cudaGetSymbolAddress((void**)&kv, g_kv);
    cudaGetSymbolAddress((void**)&ps, g_ps);
    cudaGetSymbolAddress((void**)&pool, g_pool);
    cudaGetSymbolAddress((void**)&whi, g_whi);
    cudaGetSymbolAddress((void**)&wlo, g_wlo);

    cudaFuncSetAttribute(mmagemm_kernel<0>, cudaFuncAttributeMaxDynamicSharedMemorySize, GB_SMEM);
    cudaFuncSetAttribute(mmagemm_kernel<1>, cudaFuncAttributeMaxDynamicSharedMemorySize, GB_SMEM);

    const size_t MATSZ = (size_t)NL_ * D_ * D_;

    // pre-split all weights: 0=Wq 1=Wk 2=Wv 3=Wo 4=W1 5=W2
    {
        dim3 gT(D_ / 32, D_ / 32, NL_);
        dim3 bT(32, 8);
        wsplit_kernel<<<gT, bT>>>(Wq, whi + 0 * MATSZ, wlo + 0 * MATSZ);
        wsplit_kernel<<<gT, bT>>>(Wk, whi + 1 * MATSZ, wlo + 1 * MATSZ);
        wsplit_kernel<<<gT, bT>>>(Wv, whi + 2 * MATSZ, wlo + 2 * MATSZ);
        wsplit_kernel<<<gT, bT>>>(Wo, whi + 3 * MATSZ, wlo + 3 * MATSZ);
        wsplit_kernel<<<gT, bT>>>(W1, whi + 4 * MATSZ, wlo + 4 * MATSZ);
        wsplit_kernel<<<gT, bT>>>(W2, whi + 5 * MATSZ, wlo + 5 * MATSZ);
    }

    embed_kernel<<<(BSD_ + 255) / 256, 256>>>(x, tok, h);

    dim3 gGemm(D_ / 128, BS_ / 128);   // (6, 256)
    const size_t LSZ = (size_t)D_ * D_;

    for (int l = 0; l < NL_; ++l) {
        const __nv_bfloat16* qh  = whi + 0 * MATSZ + l * LSZ;
        const __nv_bfloat16* ql  = wlo + 0 * MATSZ + l * LSZ;
        const __nv_bfloat16* kh  = whi + 1 * MATSZ + l * LSZ;
        const __nv_bfloat16* kl  = wlo + 1 * MATSZ + l * LSZ;
        const __nv_bfloat16* vh  = whi + 2 * MATSZ + l * LSZ;
        const __nv_bfloat16* vl  = wlo + 2 * MATSZ + l * LSZ;
        const __nv_bfloat16* oh  = whi + 3 * MATSZ + l * LSZ;
        const __nv_bfloat16* ol  = wlo + 3 * MATSZ + l * LSZ;
        const __nv_bfloat16* f1h = whi + 4 * MATSZ + l * LSZ;
        const __nv_bfloat16* f1l = wlo + 4 * MATSZ + l * LSZ;
        const __nv_bfloat16* f2h = whi + 5 * MATSZ + l * LSZ;
        const __nv_bfloat16* f2l = wlo + 5 * MATSZ + l * LSZ;
        const float* lbq = bq + (size_t)l * D_;
        const float* lbk = bk + (size_t)l * D_;
        const float* lbv = bv + (size_t)l * D_;
        const float* lbo = bo + (size_t)l * D_;
        const float* lb1 = b1 + (size_t)l * D_;
        const float* lb2 = b2 + (size_t)l * D_;
        const float* lom = omega + (size_t)l * DH_ * NF_;
        const float* l1s = ln1s + (size_t)l * D_;
        const float* l1b = ln1b + (size_t)l * D_;
        const float* l2s = ln2s + (size_t)l * D_;
        const float* l2b = ln2b + (size_t)l * D_;

        mmagemm_kernel<0><<<gGemm, 256, GB_SMEM>>>(h, qh, ql, lbq, q);
        mmagemm_kernel<0><<<gGemm, 256, GB_SMEM>>>(h, kh, kl, lbk, k);
        mmagemm_kernel<0><<<gGemm, 256, GB_SMEM>>>(h, vh, vl, lbv, v);

        feat_kernel<<<BS_, 384>>>(q, k, lom, mask, pq, pk);
        kv_kernel<<<B_ * H_, 256>>>(pk, v, kv, ps);
        att_kernel<<<B_ * H_, 512>>>(pq, kv, ps, t1);

        mmagemm_kernel<0><<<gGemm, 256, GB_SMEM>>>(t1, oh, ol, lbo, q);   // reuse q
        addln_kernel<<<BS_, 256>>>(h, q, l1s, l1b);

        mmagemm_kernel<1><<<gGemm, 256, GB_SMEM>>>(h, f1h, f1l, lb1, ff); // GELU
        mmagemm_kernel<0><<<gGemm, 256, GB_SMEM>>>(ff, f2h, f2l, lb2, t1);
        addln_kernel<<<BS_, 256>>>(h, t1, l2s, l2b);
    }

    dim3 gPool(B_, D_ / 128);
    pool_kernel<<<gPool, 128>>>(h, mask, pool);
    final_kernel<<<B_, 512>>>(pool, Wl, bl, (float*)d_out);
}

// round 12
// speedup vs baseline: 1.9031x; 1.0630x over previous
#include <cuda_runtime.h>
#include <cuda_bf16.h>
#include <math.h>
#include <stdint.h>

#define B_  64
#define S_  512
#define D_  768
#define H_  12
#define DH_ 64
#define NF_ 32
#define NL_ 12
#define OUT_ 512

static const int BS_  = B_ * S_;        // 32768
static const int BSD_ = B_ * S_ * D_;   // 25165824

// ---------------- scratch (allowed: __device__ globals) ----------------
__device__ float g_h [B_*S_*D_];
__device__ float g_q [B_*S_*D_];
__device__ float g_k [B_*S_*D_];
__device__ float g_v [B_*S_*D_];
__device__ float g_t1[B_*S_*D_];
__device__ float g_pq[B_*S_*H_*NF_];
__device__ float g_pk[B_*S_*H_*NF_];
__device__ float g_kv[B_*H_*NF_*DH_];
__device__ float g_ps[B_*H_*NF_];
__device__ float g_pool[B_*D_];
// bf16 hi/lo activations (GEMM A operands)
__device__ __nv_bfloat16 g_hhi [B_*S_*D_];
__device__ __nv_bfloat16 g_hlo [B_*S_*D_];
__device__ __nv_bfloat16 g_t1hi[B_*S_*D_];
__device__ __nv_bfloat16 g_t1lo[B_*S_*D_];
__device__ __nv_bfloat16 g_ffhi[B_*S_*D_];
__device__ __nv_bfloat16 g_fflo[B_*S_*D_];
// pre-split transposed weights: [mat 0..5][layer][n][k], bf16 hi/lo
__device__ __nv_bfloat16 g_whi[6 * NL_ * D_ * D_];
__device__ __nv_bfloat16 g_wlo[6 * NL_ * D_ * D_];

// ==================== PTX helpers ====================
__device__ __forceinline__ uint32_t smem_u32(const void* p){
    uint32_t a;
    asm("{ .reg .u64 t; cvta.to.shared.u64 t, %1; cvt.u32.u64 %0, t; }" : "=r"(a) : "l"(p));
    return a;
}

#define LDSMX4(r, addr) \
    asm volatile("ldmatrix.sync.aligned.m8n8.x4.shared.b16 {%0,%1,%2,%3}, [%4];" \
        : "=r"((r)[0]), "=r"((r)[1]), "=r"((r)[2]), "=r"((r)[3]) : "r"(addr))

#define MMA16816(d, a, b) \
    asm volatile("mma.sync.aligned.m16n8k16.row.col.f32.bf16.bf16.f32 " \
        "{%0,%1,%2,%3}, {%4,%5,%6,%7}, {%8,%9}, {%0,%1,%2,%3};" \
        : "+f"((d)[0]), "+f"((d)[1]), "+f"((d)[2]), "+f"((d)[3]) \
        : "r"((a)[0]), "r"((a)[1]), "r"((a)[2]), "r"((a)[3]), \
          "r"((b)[0]), "r"((b)[1]))

#define CP_ASYNC16(dst, src) \
    asm volatile("cp.async.cg.shared.global [%0], [%1], 16;" :: "r"(dst), "l"(src))
#define CP_COMMIT() asm volatile("cp.async.commit_group;" ::: "memory")
#define CP_WAIT0()  asm volatile("cp.async.wait_group 0;" ::: "memory")
#define CP_WAIT1()  asm volatile("cp.async.wait_group 1;" ::: "memory")

__device__ __forceinline__ void split_bf16(float v, __nv_bfloat16& hi, __nv_bfloat16& lo){
    hi = __float2bfloat16(v);
    lo = __float2bfloat16(v - __bfloat162float(hi));
}

// ---------------- embedding: h fp32 + hi/lo split ----------------
__global__ void embed_kernel(const int* __restrict__ x, const float* __restrict__ emb,
                             float* __restrict__ h,
                             __nv_bfloat16* __restrict__ hhi, __nv_bfloat16* __restrict__ hlo)
{
    long i = (long)blockIdx.x * blockDim.x + threadIdx.x;
    if (i < (long)BSD_) {
        int bs = (int)(i / D_);
        int d  = (int)(i % D_);
        float v = emb[(long)x[bs] * D_ + d];
        h[i] = v;
        __nv_bfloat16 hi, lo;
        split_bf16(v, hi, lo);
        hhi[i] = hi; hlo[i] = lo;
    }
}

// ---------------- weight transpose + bf16 hi/lo split ----------------
__global__ void wsplit_kernel(const float* __restrict__ W,
                              __nv_bfloat16* __restrict__ whi,
                              __nv_bfloat16* __restrict__ wlo)
{
    __shared__ float s[32][33];
    const int l  = blockIdx.z;
    const int k0 = blockIdx.x * 32;
    const int n0 = blockIdx.y * 32;
    const int tx = threadIdx.x;       // 0..31
    const int ty = threadIdx.y;       // 0..7
    const float* Wl = W + (size_t)l * D_ * D_;
    #pragma unroll
    for (int i = 0; i < 4; i++)
        s[ty + 8 * i][tx] = Wl[(size_t)(k0 + ty + 8 * i) * D_ + n0 + tx];
    __syncthreads();
    #pragma unroll
    for (int i = 0; i < 4; i++) {
        int n = n0 + ty + 8 * i;
        int k = k0 + tx;
        float v = s[tx][ty + 8 * i];
        __nv_bfloat16 hi, lo;
        split_bf16(v, hi, lo);
        size_t o = ((size_t)l * D_ + n) * D_ + k;
        whi[o] = hi;
        wlo[o] = lo;
    }
}

// ==================== mma.sync bf16x2 GEMM (pure cp.async pipeline) ====================
// C[32768,768] = (Ahi+Alo) @ (Whi+Wlo)^T + bias, 3-term split, fp32 accum.
// Tile 128x128x32, 8 warps (4m x 2n), rows padded to 80B. 2-stage, 2 CTAs/SM.
#define GB_BUF    40960
#define GB_AHI    0
#define GB_ALO    10240
#define GB_BHI    20480
#define GB_BLO    30720
#define GB_SMEM   (2 * GB_BUF)   // 81920

template<int ACT, int OSPLIT>
__global__ void __launch_bounds__(256, 2)
mmagemm_kernel(const __nv_bfloat16* __restrict__ Ahi,
               const __nv_bfloat16* __restrict__ Alo,
               const __nv_bfloat16* __restrict__ Whi,
               const __nv_bfloat16* __restrict__ Wlo,
               const float* __restrict__ bias,
               float* __restrict__ C,
               __nv_bfloat16* __restrict__ Chi,
               __nv_bfloat16* __restrict__ Clo)
{
    extern __shared__ char dsm[];
    const uint32_t sb32 = smem_u32(dsm);

    const int tid  = threadIdx.x;
    const int wid  = tid >> 5, lane = tid & 31;
    const int bx   = blockIdx.x;   // N tile (0..5)
    const int by   = blockIdx.y;   // M tile (0..255)
    const int wm   = wid >> 1;     // 0..3
    const int wn   = wid & 1;      // 0..1

    // staging: row r (0..127), half hf (16 bf16 = 32 B each)
    const int r  = tid >> 1;
    const int hf = tid & 1;
    const uint32_t stOff = (uint32_t)r * 80u + (uint32_t)hf * 32u;
    const char* aH = (const char*)(Ahi + ((size_t)(by * 128) + r) * 768 + hf * 16);
    const char* aL = (const char*)(Alo + ((size_t)(by * 128) + r) * 768 + hf * 16);
    const char* bH = (const char*)(Whi + ((size_t)(bx * 128) + r) * 768 + hf * 16);
    const char* bL = (const char*)(Wlo + ((size_t)(bx * 128) + r) * 768 + hf * 16);

    // ldmatrix per-lane offsets
    const uint32_t offA = (uint32_t)(wm * 32 + (lane & 15)) * 80u + ((lane >> 4) & 1) * 16u;
    const uint32_t offB = (uint32_t)(wn * 64 + (lane & 7) + ((lane >> 4) & 1) * 8) * 80u
                        + ((lane >> 3) & 1) * 16u;

    float acc[2][8][4];
    #pragma unroll
    for (int mt = 0; mt < 2; mt++)
        #pragma unroll
        for (int nt = 0; nt < 8; nt++)
            #pragma unroll
            for (int j = 0; j < 4; j++) acc[mt][nt][j] = 0.f;

    auto stage = [&](int kt, int buf) {
        uint32_t d = sb32 + (uint32_t)buf * GB_BUF + stOff;
        long o = (long)kt * 64;
        CP_ASYNC16(d + GB_AHI,      aH + o);
        CP_ASYNC16(d + GB_AHI + 16, aH + o + 16);
        CP_ASYNC16(d + GB_ALO,      aL + o);
        CP_ASYNC16(d + GB_ALO + 16, aL + o + 16);
        CP_ASYNC16(d + GB_BHI,      bH + o);
        CP_ASYNC16(d + GB_BHI + 16, bH + o + 16);
        CP_ASYNC16(d + GB_BLO,      bL + o);
        CP_ASYNC16(d + GB_BLO + 16, bL + o + 16);
        CP_COMMIT();
    };

    stage(0, 0);

    #pragma unroll 1
    for (int t = 0; t < 24; ++t) {
        const int cur = t & 1;
        const bool more = (t + 1 < 24);
        if (more) stage(t + 1, cur ^ 1);
        if (more) { CP_WAIT1(); } else { CP_WAIT0(); }
        __syncthreads();

        const uint32_t bufb = sb32 + (uint32_t)cur * GB_BUF;
        #pragma unroll
        for (int ks = 0; ks < 2; ks++) {
            uint32_t ah[2][4], al[2][4];
            #pragma unroll
            for (int mt = 0; mt < 2; mt++) {
                uint32_t ad = bufb + offA + (uint32_t)mt * (16u * 80u) + (uint32_t)ks * 32u;
                LDSMX4(ah[mt], ad + GB_AHI);
                LDSMX4(al[mt], ad + GB_ALO);
            }
            #pragma unroll
            for (int half = 0; half < 2; half++) {
                uint32_t bh[4][2], bl[4][2];
                #pragma unroll
                for (int np = 0; np < 2; np++) {
                    uint32_t bd = bufb + offB + (uint32_t)(half * 2 + np) * (16u * 80u)
                                + (uint32_t)ks * 32u;
                    uint32_t th[4], tl[4];
                    LDSMX4(th, bd + GB_BHI);
                    LDSMX4(tl, bd + GB_BLO);
                    bh[2*np][0] = th[0]; bh[2*np][1] = th[1];
                    bh[2*np+1][0] = th[2]; bh[2*np+1][1] = th[3];
                    bl[2*np][0] = tl[0]; bl[2*np][1] = tl[1];
                    bl[2*np+1][0] = tl[2]; bl[2*np+1][1] = tl[3];
                }
                #pragma unroll
                for (int mt = 0; mt < 2; mt++)
                    #pragma unroll
                    for (int j = 0; j < 4; j++) {
                        int nt = half * 4 + j;
                        MMA16816(acc[mt][nt], ah[mt], bh[j]);
                        MMA16816(acc[mt][nt], ah[mt], bl[j]);
                        MMA16816(acc[mt][nt], al[mt], bh[j]);
                    }
            }
        }
        __syncthreads();   // all ldsm of cur done before its buffer is re-staged
    }

    // ---- epilogue ----
    const int erow = lane >> 2;
    const int ecol = (lane & 3) * 2;
    #pragma unroll
    for (int mt = 0; mt < 2; mt++) {
        #pragma unroll
        for (int nt = 0; nt < 8; nt++) {
            int grow = by * 128 + wm * 32 + mt * 16 + erow;
            int gcol = bx * 128 + wn * 64 + nt * 8 + ecol;
            float b0 = __ldg(bias + gcol), b1 = __ldg(bias + gcol + 1);
            float v0 = acc[mt][nt][0] + b0;
            float v1 = acc[mt][nt][1] + b1;
            float v2 = acc[mt][nt][2] + b0;
            float v3 = acc[mt][nt][3] + b1;
            if (ACT == 1) {
                v0 = 0.5f * v0 * (1.0f + erff(v0 * 0.70710678118654752f));
                v1 = 0.5f * v1 * (1.0f + erff(v1 * 0.70710678118654752f));
                v2 = 0.5f * v2 * (1.0f + erff(v2 * 0.70710678118654752f));
                v3 = 0.5f * v3 * (1.0f + erff(v3 * 0.70710678118654752f));
            }
            if (OSPLIT == 0) {
                *(float2*)(C + (size_t)grow * 768 + gcol)       = make_float2(v0, v1);
                *(float2*)(C + (size_t)(grow + 8) * 768 + gcol) = make_float2(v2, v3);
            } else {
                __nv_bfloat16 h0, l0, h1, l1;
                split_bf16(v0, h0, l0); split_bf16(v1, h1, l1);
                __nv_bfloat162 hp = __halves2bfloat162(h0, h1);
                __nv_bfloat162 lp = __halves2bfloat162(l0, l1);
                *(uint32_t*)(Chi + (size_t)grow * 768 + gcol) = *(uint32_t*)&hp;
                *(uint32_t*)(Clo + (size_t)grow * 768 + gcol) = *(uint32_t*)&lp;
                split_bf16(v2, h0, l0); split_bf16(v3, h1, l1);
                hp = __halves2bfloat162(h0, h1);
                lp = __halves2bfloat162(l0, l1);
                *(uint32_t*)(Chi + (size_t)(grow + 8) * 768 + gcol) = *(uint32_t*)&hp;
                *(uint32_t*)(Clo + (size_t)(grow + 8) * 768 + gcol) = *(uint32_t*)&lp;
            }
        }
    }
}

// ---------------- rotary (in smem) + feature maps ----------------
__global__ void feat_kernel(const float* __restrict__ q, const float* __restrict__ k,
                            const float* __restrict__ om, const float* __restrict__ mask,
                            float* __restrict__ pq, float* __restrict__ pk)
{
    const int bs  = blockIdx.x;
    const int t   = bs % S_;
    const int tid = threadIdx.x;       // 384 threads

    __shared__ float sq[D_];
    __shared__ float sk[D_];
    __shared__ float som[DH_ * NF_];

    for (int i = tid; i < D_; i += 384) {
        sq[i] = q[(size_t)bs * D_ + i];
        sk[i] = k[(size_t)bs * D_ + i];
    }
    for (int i = tid; i < DH_ * NF_; i += 384) som[i] = om[i];
    __syncthreads();

    {
        const int hh = tid >> 5, j = tid & 31;
        const int base = hh * DH_ + j;
        float invf = expf(-(float)j * 0.28782313662425572f);
        float ang = (float)t * invf;
        float c = cosf(ang), s = sinf(ang);
        float qa = sq[base], qb = sq[base + 32];
        float ka = sk[base], kb = sk[base + 32];
        sq[base]      = qa * c - qb * s;
        sq[base + 32] = qb * c + qa * s;
        sk[base]      = ka * c - kb * s;
        sk[base + 32] = kb * c + ka * s;
    }
    __syncthreads();

    const int hh = tid >> 5, f = tid & 31;
    float aq = 0.f, ak = 0.f;
    #pragma unroll 16
    for (int d = 0; d < DH_; ++d) {
        float w = som[d * NF_ + f];
        aq = fmaf(sq[hh * DH_ + d], w, aq);
        ak = fmaf(sk[hh * DH_ + d], w, ak);
    }
    float m = mask[bs];
    pq[((size_t)bs * H_ + hh) * NF_ + f] = fmaxf(aq, 0.f);
    pk[((size_t)bs * H_ + hh) * NF_ + f] = fmaxf(ak, 0.f) * m;
}

// ---------------- kv + pk row-sum ----------------
__global__ void kv_kernel(const float* __restrict__ pk, const float* __restrict__ v,
                          float* __restrict__ kv, float* __restrict__ ps)
{
    const int b = blockIdx.x / H_;
    const int h = blockIdx.x % H_;
    const int tid = threadIdx.x;      // 256

    __shared__ float spk[32][NF_];
    __shared__ float sv [32][DH_];

    const int f  = tid >> 3;
    const int d0 = (tid & 7) * 8;

    float acc[8];
    #pragma unroll
    for (int i = 0; i < 8; i++) acc[i] = 0.f;
    float psum = 0.f;

    for (int s0 = 0; s0 < S_; s0 += 32) {
        for (int i = tid; i < 32 * NF_; i += 256) {
            int sl = i >> 5, ff = i & 31;
            spk[sl][ff] = pk[(((size_t)(b * S_ + s0 + sl)) * H_ + h) * NF_ + ff];
        }
        for (int i = tid; i < 32 * DH_; i += 256) {
            int sl = i >> 6, dd = i & 63;
            sv[sl][dd] = v[((size_t)(b * S_ + s0 + sl)) * D_ + h * DH_ + dd];
        }
        __syncthreads();
        #pragma unroll 8
        for (int sl = 0; sl < 32; ++sl) {
            float pv = spk[sl][f];
            psum += pv;
            #pragma unroll
            for (int i = 0; i < 8; i++)
                acc[i] = fmaf(pv, sv[sl][d0 + i], acc[i]);
        }
        __syncthreads();
    }
    #pragma unroll
    for (int i = 0; i < 8; i++)
        kv[(((size_t)(b * H_ + h)) * NF_ + f) * DH_ + d0 + i] = acc[i];
    if ((tid & 7) == 0) ps[((size_t)(b * H_ + h)) * NF_ + f] = psum;
}

// ---------------- att: z normalize + pq@kv -> bf16 hi/lo directly ----------------
__global__ void att_kernel(const float* __restrict__ pq, const float* __restrict__ kv,
                           const float* __restrict__ ps,
                           __nv_bfloat16* __restrict__ ahi, __nv_bfloat16* __restrict__ alo)
{
    const int b = blockIdx.x / H_;
    const int h = blockIdx.x % H_;
    const int tid = threadIdx.x;   // 512

    __shared__ float skv[NF_ * DH_];
    __shared__ float sps[NF_];
    __shared__ float spq[8][NF_];

    for (int i = tid; i < NF_ * DH_; i += 512)
        skv[i] = kv[((size_t)(b * H_ + h)) * NF_ * DH_ + i];
    if (tid < NF_) sps[tid] = ps[((size_t)(b * H_ + h)) * NF_ + tid];
    __syncthreads();

    const int sl = tid >> 6;   // 0..7
    const int d  = tid & 63;

    for (int s0 = 0; s0 < S_; s0 += 8) {
        if (tid < 256) {
            int l = tid >> 5, ff = tid & 31;
            spq[l][ff] = pq[(((size_t)(b * S_ + s0 + l)) * H_ + h) * NF_ + ff];
        }
        __syncthreads();
        float za = 0.f, aa = 0.f;
        #pragma unroll 8
        for (int ff = 0; ff < NF_; ++ff) {
            float pv = spq[sl][ff];
            za = fmaf(pv, sps[ff], za);
            aa = fmaf(pv, skv[ff * DH_ + d], aa);
        }
        float o = aa / (za + 1e-6f);
        __nv_bfloat16 hi, lo;
        split_bf16(o, hi, lo);
        size_t idx = ((size_t)(b * S_ + s0 + sl)) * D_ + h * DH_ + d;
        ahi[idx] = hi;
        alo[idx] = lo;
        __syncthreads();
    }
}

// ---------------- residual + LayerNorm (fp32 + hi/lo split out) ----------------
__global__ void addln_kernel(float* __restrict__ h, const float* __restrict__ r,
                             const float* __restrict__ gam, const float* __restrict__ bet,
                             __nv_bfloat16* __restrict__ hhi, __nv_bfloat16* __restrict__ hlo)
{
    const int row = blockIdx.x;
    const int tid = threadIdx.x;   // 256
    const size_t base = (size_t)row * D_;

    float x0 = h[base + tid]       + r[base + tid];
    float x1 = h[base + tid + 256] + r[base + tid + 256];
    float x2 = h[base + tid + 512] + r[base + tid + 512];

    __shared__ float red[8];
    float s = x0 + x1 + x2;
    #pragma unroll
    for (int o = 16; o; o >>= 1) s += __shfl_xor_sync(0xffffffffu, s, o);
    if ((tid & 31) == 0) red[tid >> 5] = s;
    __syncthreads();
    float tot = red[0] + red[1] + red[2] + red[3] + red[4] + red[5] + red[6] + red[7];
    float mean = tot * (1.0f / 768.0f);

    float d0 = x0 - mean, d1 = x1 - mean, d2 = x2 - mean;
    float s2 = d0 * d0 + d1 * d1 + d2 * d2;
    #pragma unroll
    for (int o = 16; o; o >>= 1) s2 += __shfl_xor_sync(0xffffffffu, s2, o);
    __syncthreads();
    if ((tid & 31) == 0) red[tid >> 5] = s2;
    __syncthreads();
    float var = (red[0] + red[1] + red[2] + red[3] + red[4] + red[5] + red[6] + red[7]) * (1.0f / 768.0f);
    float inv = rsqrtf(var + 1e-5f);

    float y0 = d0 * inv * gam[tid]       + bet[tid];
    float y1 = d1 * inv * gam[tid + 256] + bet[tid + 256];
    float y2 = d2 * inv * gam[tid + 512] + bet[tid + 512];
    h[base + tid]       = y0;
    h[base + tid + 256] = y1;
    h[base + tid + 512] = y2;
    __nv_bfloat16 hi, lo;
    split_bf16(y0, hi, lo); hhi[base + tid]       = hi; hlo[base + tid]       = lo;
    split_bf16(y1, hi, lo); hhi[base + tid + 256] = hi; hlo[base + tid + 256] = lo;
    split_bf16(y2, hi, lo); hhi[base + tid + 512] = hi; hlo[base + tid + 512] = lo;
}

// ---------------- masked mean pool ----------------
__global__ void pool_kernel(const float* __restrict__ h, const float* __restrict__ mask,
                            float* __restrict__ pool)
{
    const int b = blockIdx.x;
    const int c = blockIdx.y * 128 + threadIdx.x;   // grid.y = 6
    float acc = 0.f, dn = 0.f;
    for (int s = 0; s < S_; ++s) {
        float m = mask[b * S_ + s];
        dn += m;
        acc += h[((size_t)(b * S_ + s)) * D_ + c] * m;
    }
    dn = fmaxf(dn, 1e-9f);
    pool[(size_t)b * D_ + c] = acc / dn;
}

// ---------------- final: out = relu(pool @ Wl + bl) ----------------
__global__ void final_kernel(const float* __restrict__ pool, const float* __restrict__ Wl,
                             const float* __restrict__ bl, float* __restrict__ out)
{
    const int b = blockIdx.x;
    const int o = threadIdx.x;   // 512
    __shared__ float sp[D_];
    for (int i = o; i < D_; i += 512) sp[i] = pool[(size_t)b * D_ + i];
    __syncthreads();
    float acc = bl[o];
    #pragma unroll 8
    for (int k = 0; k < D_; ++k)
        acc = fmaf(sp[k], Wl[(size_t)k * OUT_ + o], acc);
    out[(size_t)b * OUT_ + o] = fmaxf(acc, 0.f);
}

// ---------------- host ----------------
extern "C" void kernel_launch(void* const* d_in, const int* in_sizes, int n_in,
                              void* d_out, int out_size)
{
    const int*   x     = (const int*)  d_in[0];
    const float* mask  = (const float*)d_in[1];
    const float* tok   = (const float*)d_in[2];
    const float* Wq    = (const float*)d_in[3];
    const float* bq    = (const float*)d_in[4];
    const float* Wk    = (const float*)d_in[5];
    const float* bk    = (const float*)d_in[6];
    const float* Wv    = (const float*)d_in[7];
    const float* bv    = (const float*)d_in[8];
    const float* Wo    = (const float*)d_in[9];
    const float* bo    = (const float*)d_in[10];
    const float* omega = (const float*)d_in[11];
    const float* ln1s  = (const float*)d_in[12];
    const float* ln1b  = (const float*)d_in[13];
    const float* W1    = (const float*)d_in[14];
    const float* b1    = (const float*)d_in[15];
    const float* W2    = (const float*)d_in[16];
    const float* b2    = (const float*)d_in[17];
    const float* ln2s  = (const float*)d_in[18];
    const float* ln2b  = (const float*)d_in[19];
    const float* Wl    = (const float*)d_in[20];
    const float* bl    = (const float*)d_in[21];

    float *h, *q, *k, *v, *t1, *pq, *pk, *kv, *ps, *pool;
    __nv_bfloat16 *whi, *wlo, *hhi, *hlo, *t1hi, *t1lo, *ffhi, *fflo;
    cudaGetSymbolAddress((void**)&h,  g_h);
    cudaGetSymbolAddress((void**)&q,  g_q);
    cudaGetSymbolAddress((void**)&k,  g_k);
    cudaGetSymbolAddress((void**)&v,  g_v);
    cudaGetSymbolAddress((void**)&t1, g_t1);
    cudaGetSymbolAddress((void**)&pq, g_pq);
    cudaGetSymbolAddress((void**)&pk, g_pk);
    cudaGetSymbolAddress((void**)&kv, g_kv);
    cudaGetSymbolAddress((void**)&ps, g_ps);
    cudaGetSymbolAddress((void**)&pool, g_pool);
    cudaGetSymbolAddress((void**)&whi, g_whi);
    cudaGetSymbolAddress((void**)&wlo, g_wlo);
    cudaGetSymbolAddress((void**)&hhi, g_hhi);
    cudaGetSymbolAddress((void**)&hlo, g_hlo);
    cudaGetSymbolAddress((void**)&t1hi, g_t1hi);
    cudaGetSymbolAddress((void**)&t1lo, g_t1lo);
    cudaGetSymbolAddress((void**)&ffhi, g_ffhi);
    cudaGetSymbolAddress((void**)&fflo, g_fflo);

    cudaFuncSetAttribute(mmagemm_kernel<0,0>, cudaFuncAttributeMaxDynamicSharedMemorySize, GB_SMEM);
    cudaFuncSetAttribute(mmagemm_kernel<1,1>, cudaFuncAttributeMaxDynamicSharedMemorySize, GB_SMEM);

    const size_t MATSZ = (size_t)NL_ * D_ * D_;

    // pre-split all weights: 0=Wq 1=Wk 2=Wv 3=Wo 4=W1 5=W2
    {
        dim3 gT(D_ / 32, D_ / 32, NL_);
        dim3 bT(32, 8);
        wsplit_kernel<<<gT, bT>>>(Wq, whi + 0 * MATSZ, wlo + 0 * MATSZ);
        wsplit_kernel<<<gT, bT>>>(Wk, whi + 1 * MATSZ, wlo + 1 * MATSZ);
        wsplit_kernel<<<gT, bT>>>(Wv, whi + 2 * MATSZ, wlo + 2 * MATSZ);
        wsplit_kernel<<<gT, bT>>>(Wo, whi + 3 * MATSZ, wlo + 3 * MATSZ);
        wsplit_kernel<<<gT, bT>>>(W1, whi + 4 * MATSZ, wlo + 4 * MATSZ);
        wsplit_kernel<<<gT, bT>>>(W2, whi + 5 * MATSZ, wlo + 5 * MATSZ);
    }

    embed_kernel<<<(BSD_ + 255) / 256, 256>>>(x, tok, h, hhi, hlo);

    dim3 gGemm(D_ / 128, BS_ / 128);   // (6, 256)
    const size_t LSZ = (size_t)D_ * D_;

    for (int l = 0; l < NL_; ++l) {
        const __nv_bfloat16* qh  = whi + 0 * MATSZ + l * LSZ;
        const __nv_bfloat16* ql  = wlo + 0 * MATSZ + l * LSZ;
        const __nv_bfloat16* kh  = whi + 1 * MATSZ + l * LSZ;
        const __nv_bfloat16* kl  = wlo + 1 * MATSZ + l * LSZ;
        const __nv_bfloat16* vh  = whi + 2 * MATSZ + l * LSZ;
        const __nv_bfloat16* vl  = wlo + 2 * MATSZ + l * LSZ;
        const __nv_bfloat16* oh  = whi + 3 * MATSZ + l * LSZ;
        const __nv_bfloat16* ol  = wlo + 3 * MATSZ + l * LSZ;
        const __nv_bfloat16* f1h = whi + 4 * MATSZ + l * LSZ;
        const __nv_bfloat16* f1l = wlo + 4 * MATSZ + l * LSZ;
        const __nv_bfloat16* f2h = whi + 5 * MATSZ + l * LSZ;
        const __nv_bfloat16* f2l = wlo + 5 * MATSZ + l * LSZ;
        const float* lbq = bq + (size_t)l * D_;
        const float* lbk = bk + (size_t)l * D_;
        const float* lbv = bv + (size_t)l * D_;
        const float* lbo = bo + (size_t)l * D_;
        const float* lb1 = b1 + (size_t)l * D_;
        const float* lb2 = b2 + (size_t)l * D_;
        const float* lom = omega + (size_t)l * DH_ * NF_;
        const float* l1s = ln1s + (size_t)l * D_;
        const float* l1b = ln1b + (size_t)l * D_;
        const float* l2s = ln2s + (size_t)l * D_;
        const float* l2b = ln2b + (size_t)l * D_;

        mmagemm_kernel<0,0><<<gGemm, 256, GB_SMEM>>>(hhi, hlo, qh, ql, lbq, q, nullptr, nullptr);
        mmagemm_kernel<0,0><<<gGemm, 256, GB_SMEM>>>(hhi, hlo, kh, kl, lbk, k, nullptr, nullptr);
        mmagemm_kernel<0,0><<<gGemm, 256, GB_SMEM>>>(hhi, hlo, vh, vl, lbv, v, nullptr, nullptr);

        feat_kernel<<<BS_, 384>>>(q, k, lom, mask, pq, pk);
        kv_kernel<<<B_ * H_, 256>>>(pk, v, kv, ps);
        att_kernel<<<B_ * H_, 512>>>(pq, kv, ps, t1hi, t1lo);

        mmagemm_kernel<0,0><<<gGemm, 256, GB_SMEM>>>(t1hi, t1lo, oh, ol, lbo, q, nullptr, nullptr);
        addln_kernel<<<BS_, 256>>>(h, q, l1s, l1b, hhi, hlo);

        mmagemm_kernel<1,1><<<gGemm, 256, GB_SMEM>>>(hhi, hlo, f1h, f1l, lb1, nullptr, ffhi, fflo);
        mmagemm_kernel<0,0><<<gGemm, 256, GB_SMEM>>>(ffhi, fflo, f2h, f2l, lb2, t1, nullptr, nullptr);
        addln_kernel<<<BS_, 256>>>(h, t1, l2s, l2b, hhi, hlo);
    }

    dim3 gPool(B_, D_ / 128);
    pool_kernel<<<gPool, 128>>>(h, mask, pool);
    final_kernel<<<B_, 512>>>(pool, Wl, bl, (float*)d_out);
}

// round 13
// speedup vs baseline: 2.5403x; 1.3348x over previous
#include <cuda_runtime.h>
#include <cuda_fp16.h>
#include <math.h>
#include <stdint.h>

#define B_  64
#define S_  512
#define D_  768
#define H_  12
#define DH_ 64
#define NF_ 32
#define NL_ 12
#define OUT_ 512

static const int BS_  = B_ * S_;        // 32768
static const int BSD_ = B_ * S_ * D_;   // 25165824

// ---------------- scratch (allowed: __device__ globals) ----------------
__device__ float g_h  [B_*S_*D_];
__device__ float g_qkv[3 * B_*S_*D_];   // fused Q,K,V outputs (contiguous)
__device__ float g_t1 [B_*S_*D_];
__device__ float g_pq[B_*S_*H_*NF_];
__device__ float g_pk[B_*S_*H_*NF_];
__device__ float g_kv[B_*H_*NF_*DH_];
__device__ float g_ps[B_*H_*NF_];
__device__ float g_pool[B_*D_];
// fp16 exact-pair activations (GEMM A operands)
__device__ __half g_hhi [B_*S_*D_];
__device__ __half g_hlo [B_*S_*D_];
__device__ __half g_t1hi[B_*S_*D_];
__device__ __half g_t1lo[B_*S_*D_];
__device__ __half g_ffhi[B_*S_*D_];
__device__ __half g_fflo[B_*S_*D_];
// fp16 transposed weights: [mat 0..5][layer][n][k]
__device__ __half g_wh[6 * NL_ * D_ * D_];

// ==================== PTX helpers ====================
__device__ __forceinline__ uint32_t smem_u32(const void* p){
    uint32_t a;
    asm("{ .reg .u64 t; cvta.to.shared.u64 t, %1; cvt.u32.u64 %0, t; }" : "=r"(a) : "l"(p));
    return a;
}

#define LDSMX4(r, addr) \
    asm volatile("ldmatrix.sync.aligned.m8n8.x4.shared.b16 {%0,%1,%2,%3}, [%4];" \
        : "=r"((r)[0]), "=r"((r)[1]), "=r"((r)[2]), "=r"((r)[3]) : "r"(addr))

#define MMA16816F16(d, a, b) \
    asm volatile("mma.sync.aligned.m16n8k16.row.col.f32.f16.f16.f32 " \
        "{%0,%1,%2,%3}, {%4,%5,%6,%7}, {%8,%9}, {%0,%1,%2,%3};" \
        : "+f"((d)[0]), "+f"((d)[1]), "+f"((d)[2]), "+f"((d)[3]) \
        : "r"((a)[0]), "r"((a)[1]), "r"((a)[2]), "r"((a)[3]), \
          "r"((b)[0]), "r"((b)[1]))

#define CP_ASYNC16(dst, src) \
    asm volatile("cp.async.cg.shared.global [%0], [%1], 16;" :: "r"(dst), "l"(src))
#define CP_COMMIT() asm volatile("cp.async.commit_group;" ::: "memory")
#define CP_WAIT0()  asm volatile("cp.async.wait_group 0;" ::: "memory")
#define CP_WAIT1()  asm volatile("cp.async.wait_group 1;" ::: "memory")

__device__ __forceinline__ void split_f16(float v, __half& hi, __half& lo){
    hi = __float2half_rn(v);
    lo = __float2half_rn(v - __half2float(hi));
}

// ---------------- embedding: h fp32 + exact fp16 pair ----------------
__global__ void embed_kernel(const int* __restrict__ x, const float* __restrict__ emb,
                             float* __restrict__ h,
                             __half* __restrict__ hhi, __half* __restrict__ hlo)
{
    long i = (long)blockIdx.x * blockDim.x + threadIdx.x;
    if (i < (long)BSD_) {
        int bs = (int)(i / D_);
        int d  = (int)(i % D_);
        float v = emb[(long)x[bs] * D_ + d];
        h[i] = v;
        __half hi, lo;
        split_f16(v, hi, lo);
        hhi[i] = hi; hlo[i] = lo;
    }
}

// ---------------- weight transpose + fp16 convert ----------------
// in: W[l][k][n] fp32; out: wh[(l*768+n)*768+k] fp16 ([N,K] K-major)
__global__ void wsplit_kernel(const float* __restrict__ W, __half* __restrict__ wh)
{
    __shared__ float s[32][33];
    const int l  = blockIdx.z;
    const int k0 = blockIdx.x * 32;
    const int n0 = blockIdx.y * 32;
    const int tx = threadIdx.x;       // 0..31
    const int ty = threadIdx.y;       // 0..7
    const float* Wl = W + (size_t)l * D_ * D_;
    #pragma unroll
    for (int i = 0; i < 4; i++)
        s[ty + 8 * i][tx] = Wl[(size_t)(k0 + ty + 8 * i) * D_ + n0 + tx];
    __syncthreads();
    #pragma unroll
    for (int i = 0; i < 4; i++) {
        int n = n0 + ty + 8 * i;
        int k = k0 + tx;
        wh[((size_t)l * D_ + n) * D_ + k] = __float2half_rn(s[tx][ty + 8 * i]);
    }
}

// ==================== mma.sync fp16 2-term GEMM ====================
// C = (Ahi + Alo) @ Wh^T + bias  (A exact fp16 pair, W single fp16, fp32 accum)
// Tile 128x128x32, 8 warps (4m x 2n), 80B-padded rows, 2-stage cp.async, 2 CTA/SM.
// grid.x = 6*nmats: mat = bx/6 selects weight block (stride wstride), bias, out block.
#define GB_BUF    30720
#define GB_AHI    0
#define GB_ALO    10240
#define GB_BH     20480
#define GB_SMEM   (2 * GB_BUF)   // 61440

template<int ACT, int OSPLIT>
__global__ void __launch_bounds__(256, 2)
mmagemm_kernel(const __half* __restrict__ Ahi,
               const __half* __restrict__ Alo,
               const __half* __restrict__ Wh, size_t wstride,
               const float* __restrict__ bias0, const float* __restrict__ bias1,
               const float* __restrict__ bias2,
               float* __restrict__ C,
               __half* __restrict__ Chi, __half* __restrict__ Clo,
               size_t ostride)
{
    extern __shared__ char dsm[];
    const uint32_t sb32 = smem_u32(dsm);

    const int tid  = threadIdx.x;
    const int wid  = tid >> 5, lane = tid & 31;
    const int mat  = blockIdx.x / 6;
    const int bx   = blockIdx.x % 6;   // N tile
    const int by   = blockIdx.y;       // M tile
    const int wm   = wid >> 1;         // 0..3
    const int wn   = wid & 1;          // 0..1

    const __half* Wm = Wh + (size_t)mat * wstride;
    const float* bias = (mat == 0) ? bias0 : ((mat == 1) ? bias1 : bias2);

    // staging: row r (0..127), half hf (16 halves = 32 B)
    const int r  = tid >> 1;
    const int hf = tid & 1;
    const uint32_t stOff = (uint32_t)r * 80u + (uint32_t)hf * 32u;
    const char* aH = (const char*)(Ahi + ((size_t)(by * 128) + r) * 768 + hf * 16);
    const char* aL = (const char*)(Alo + ((size_t)(by * 128) + r) * 768 + hf * 16);
    const char* bH = (const char*)(Wm  + ((size_t)(bx * 128) + r) * 768 + hf * 16);

    // ldmatrix per-lane offsets
    const uint32_t offA = (uint32_t)(wm * 32 + (lane & 15)) * 80u + ((lane >> 4) & 1) * 16u;
    const uint32_t offB = (uint32_t)(wn * 64 + (lane & 7) + ((lane >> 4) & 1) * 8) * 80u
                        + ((lane >> 3) & 1) * 16u;

    float acc[2][8][4];
    #pragma unroll
    for (int mt = 0; mt < 2; mt++)
        #pragma unroll
        for (int nt = 0; nt < 8; nt++)
            #pragma unroll
            for (int j = 0; j < 4; j++) acc[mt][nt][j] = 0.f;

    auto stage = [&](int kt, int buf) {
        uint32_t d = sb32 + (uint32_t)buf * GB_BUF + stOff;
        long o = (long)kt * 64;
        CP_ASYNC16(d + GB_AHI,      aH + o);
        CP_ASYNC16(d + GB_AHI + 16, aH + o + 16);
        CP_ASYNC16(d + GB_ALO,      aL + o);
        CP_ASYNC16(d + GB_ALO + 16, aL + o + 16);
        CP_ASYNC16(d + GB_BH,       bH + o);
        CP_ASYNC16(d + GB_BH + 16,  bH + o + 16);
        CP_COMMIT();
    };

    stage(0, 0);

    #pragma unroll 1
    for (int t = 0; t < 24; ++t) {
        const int cur = t & 1;
        const bool more = (t + 1 < 24);
        if (more) stage(t + 1, cur ^ 1);
        if (more) { CP_WAIT1(); } else { CP_WAIT0(); }
        __syncthreads();

        const uint32_t bufb = sb32 + (uint32_t)cur * GB_BUF;
        #pragma unroll
        for (int ks = 0; ks < 2; ks++) {
            uint32_t ah[2][4], al[2][4];
            #pragma unroll
            for (int mt = 0; mt < 2; mt++) {
                uint32_t ad = bufb + offA + (uint32_t)mt * (16u * 80u) + (uint32_t)ks * 32u;
                LDSMX4(ah[mt], ad + GB_AHI);
                LDSMX4(al[mt], ad + GB_ALO);
            }
            #pragma unroll
            for (int half = 0; half < 2; half++) {
                uint32_t bh[4][2];
                #pragma unroll
                for (int np = 0; np < 2; np++) {
                    uint32_t bd = bufb + offB + (uint32_t)(half * 2 + np) * (16u * 80u)
                                + (uint32_t)ks * 32u;
                    uint32_t th[4];
                    LDSMX4(th, bd + GB_BH);
                    bh[2*np][0]   = th[0]; bh[2*np][1]   = th[1];
                    bh[2*np+1][0] = th[2]; bh[2*np+1][1] = th[3];
                }
                #pragma unroll
                for (int mt = 0; mt < 2; mt++)
                    #pragma unroll
                    for (int j = 0; j < 4; j++) {
                        int nt = half * 4 + j;
                        MMA16816F16(acc[mt][nt], ah[mt], bh[j]);
                        MMA16816F16(acc[mt][nt], al[mt], bh[j]);
                    }
            }
        }
        __syncthreads();   // ldsm of cur done before its buffer is re-staged
    }

    // ---- epilogue ----
    const int erow = lane >> 2;
    const int ecol = (lane & 3) * 2;
    #pragma unroll
    for (int mt = 0; mt < 2; mt++) {
        #pragma unroll
        for (int nt = 0; nt < 8; nt++) {
            int grow = by * 128 + wm * 32 + mt * 16 + erow;
            int gcol = bx * 128 + wn * 64 + nt * 8 + ecol;
            float b0 = __ldg(bias + gcol), b1 = __ldg(bias + gcol + 1);
            float v0 = acc[mt][nt][0] + b0;
            float v1 = acc[mt][nt][1] + b1;
            float v2 = acc[mt][nt][2] + b0;
            float v3 = acc[mt][nt][3] + b1;
            if (ACT == 1) {
                v0 = 0.5f * v0 * (1.0f + erff(v0 * 0.70710678118654752f));
                v1 = 0.5f * v1 * (1.0f + erff(v1 * 0.70710678118654752f));
                v2 = 0.5f * v2 * (1.0f + erff(v2 * 0.70710678118654752f));
                v3 = 0.5f * v3 * (1.0f + erff(v3 * 0.70710678118654752f));
            }
            if (OSPLIT == 0) {
                float* Cb = C + (size_t)mat * ostride;
                *(float2*)(Cb + (size_t)grow * 768 + gcol)       = make_float2(v0, v1);
                *(float2*)(Cb + (size_t)(grow + 8) * 768 + gcol) = make_float2(v2, v3);
            } else {
                __half h0, l0, h1, l1;
                split_f16(v0, h0, l0); split_f16(v1, h1, l1);
                __half2 hp = __halves2half2(h0, h1);
                __half2 lp = __halves2half2(l0, l1);
                *(uint32_t*)(Chi + (size_t)grow * 768 + gcol) = *(uint32_t*)&hp;
                *(uint32_t*)(Clo + (size_t)grow * 768 + gcol) = *(uint32_t*)&lp;
                split_f16(v2, h0, l0); split_f16(v3, h1, l1);
                hp = __halves2half2(h0, h1);
                lp = __halves2half2(l0, l1);
                *(uint32_t*)(Chi + (size_t)(grow + 8) * 768 + gcol) = *(uint32_t*)&hp;
                *(uint32_t*)(Clo + (size_t)(grow + 8) * 768 + gcol) = *(uint32_t*)&lp;
            }
        }
    }
}

// ---------------- rotary (in smem) + feature maps ----------------
__global__ void feat_kernel(const float* __restrict__ q, const float* __restrict__ k,
                            const float* __restrict__ om, const float* __restrict__ mask,
                            float* __restrict__ pq, float* __restrict__ pk)
{
    const int bs  = blockIdx.x;
    const int t   = bs % S_;
    const int tid = threadIdx.x;       // 384 threads

    __shared__ float sq[D_];
    __shared__ float sk[D_];
    __shared__ float som[DH_ * NF_];

    for (int i = tid; i < D_; i += 384) {
        sq[i] = q[(size_t)bs * D_ + i];
        sk[i] = k[(size_t)bs * D_ + i];
    }
    for (int i = tid; i < DH_ * NF_; i += 384) som[i] = om[i];
    __syncthreads();

    {
        const int hh = tid >> 5, j = tid & 31;
        const int base = hh * DH_ + j;
        float invf = expf(-(float)j * 0.28782313662425572f);
        float ang = (float)t * invf;
        float c = cosf(ang), s = sinf(ang);
        float qa = sq[base], qb = sq[base + 32];
        float ka = sk[base], kb = sk[base + 32];
        sq[base]      = qa * c - qb * s;
        sq[base + 32] = qb * c + qa * s;
        sk[base]      = ka * c - kb * s;
        sk[base + 32] = kb * c + ka * s;
    }
    __syncthreads();

    const int hh = tid >> 5, f = tid & 31;
    float aq = 0.f, ak = 0.f;
    #pragma unroll 16
    for (int d = 0; d < DH_; ++d) {
        float w = som[d * NF_ + f];
        aq = fmaf(sq[hh * DH_ + d], w, aq);
        ak = fmaf(sk[hh * DH_ + d], w, ak);
    }
    float m = mask[bs];
    pq[((size_t)bs * H_ + hh) * NF_ + f] = fmaxf(aq, 0.f);
    pk[((size_t)bs * H_ + hh) * NF_ + f] = fmaxf(ak, 0.f) * m;
}

// ---------------- kv + pk row-sum ----------------
__global__ void kv_kernel(const float* __restrict__ pk, const float* __restrict__ v,
                          float* __restrict__ kv, float* __restrict__ ps)
{
    const int b = blockIdx.x / H_;
    const int h = blockIdx.x % H_;
    const int tid = threadIdx.x;      // 256

    __shared__ float spk[32][NF_];
    __shared__ float sv [32][DH_];

    const int f  = tid >> 3;
    const int d0 = (tid & 7) * 8;

    float acc[8];
    #pragma unroll
    for (int i = 0; i < 8; i++) acc[i] = 0.f;
    float psum = 0.f;

    for (int s0 = 0; s0 < S_; s0 += 32) {
        for (int i = tid; i < 32 * NF_; i += 256) {
            int sl = i >> 5, ff = i & 31;
            spk[sl][ff] = pk[(((size_t)(b * S_ + s0 + sl)) * H_ + h) * NF_ + ff];
        }
        for (int i = tid; i < 32 * DH_; i += 256) {
            int sl = i >> 6, dd = i & 63;
            sv[sl][dd] = v[((size_t)(b * S_ + s0 + sl)) * D_ + h * DH_ + dd];
        }
        __syncthreads();
        #pragma unroll 8
        for (int sl = 0; sl < 32; ++sl) {
            float pv = spk[sl][f];
            psum += pv;
            #pragma unroll
            for (int i = 0; i < 8; i++)
                acc[i] = fmaf(pv, sv[sl][d0 + i], acc[i]);
        }
        __syncthreads();
    }
    #pragma unroll
    for (int i = 0; i < 8; i++)
        kv[(((size_t)(b * H_ + h)) * NF_ + f) * DH_ + d0 + i] = acc[i];
    if ((tid & 7) == 0) ps[((size_t)(b * H_ + h)) * NF_ + f] = psum;
}

// ---------------- att: z normalize + pq@kv -> exact fp16 pair ----------------
__global__ void att_kernel(const float* __restrict__ pq, const float* __restrict__ kv,
                           const float* __restrict__ ps,
                           __half* __restrict__ ahi, __half* __restrict__ alo)
{
    const int b = blockIdx.x / H_;
    const int h = blockIdx.x % H_;
    const int tid = threadIdx.x;   // 512

    __shared__ float skv[NF_ * DH_];
    __shared__ float sps[NF_];
    __shared__ float spq[8][NF_];

    for (int i = tid; i < NF_ * DH_; i += 512)
        skv[i] = kv[((size_t)(b * H_ + h)) * NF_ * DH_ + i];
    if (tid < NF_) sps[tid] = ps[((size_t)(b * H_ + h)) * NF_ + tid];
    __syncthreads();

    const int sl = tid >> 6;   // 0..7
    const int d  = tid & 63;

    for (int s0 = 0; s0 < S_; s0 += 8) {
        if (tid < 256) {
            int l = tid >> 5, ff = tid & 31;
            spq[l][ff] = pq[(((size_t)(b * S_ + s0 + l)) * H_ + h) * NF_ + ff];
        }
        __syncthreads();
        float za = 0.f, aa = 0.f;
        #pragma unroll 8
        for (int ff = 0; ff < NF_; ++ff) {
            float pv = spq[sl][ff];
            za = fmaf(pv, sps[ff], za);
            aa = fmaf(pv, skv[ff * DH_ + d], aa);
        }
        float o = aa / (za + 1e-6f);
        __half hi, lo;
        split_f16(o, hi, lo);
        size_t idx = ((size_t)(b * S_ + s0 + sl)) * D_ + h * DH_ + d;
        ahi[idx] = hi;
        alo[idx] = lo;
        __syncthreads();
    }
}

// ---------------- residual + LayerNorm (fp32 h + exact fp16 pair out) ----------------
__global__ void addln_kernel(float* __restrict__ h, const float* __restrict__ r,
                             const float* __restrict__ gam, const float* __restrict__ bet,
                             __half* __restrict__ hhi, __half* __restrict__ hlo)
{
    const int row = blockIdx.x;
    const int tid = threadIdx.x;   // 256
    const size_t base = (size_t)row * D_;

    float x0 = h[base + tid]       + r[base + tid];
    float x1 = h[base + tid + 256] + r[base + tid + 256];
    float x2 = h[base + tid + 512] + r[base + tid + 512];

    __shared__ float red[8];
    float s = x0 + x1 + x2;
    #pragma unroll
    for (int o = 16; o; o >>= 1) s += __shfl_xor_sync(0xffffffffu, s, o);
    if ((tid & 31) == 0) red[tid >> 5] = s;
    __syncthreads();
    float tot = red[0] + red[1] + red[2] + red[3] + red[4] + red[5] + red[6] + red[7];
    float mean = tot * (1.0f / 768.0f);

    float d0 = x0 - mean, d1 = x1 - mean, d2 = x2 - mean;
    float s2 = d0 * d0 + d1 * d1 + d2 * d2;
    #pragma unroll
    for (int o = 16; o; o >>= 1) s2 += __shfl_xor_sync(0xffffffffu, s2, o);
    __syncthreads();
    if ((tid & 31) == 0) red[tid >> 5] = s2;
    __syncthreads();
    float var = (red[0] + red[1] + red[2] + red[3] + red[4] + red[5] + red[6] + red[7]) * (1.0f / 768.0f);
    float inv = rsqrtf(var + 1e-5f);

    float y0 = d0 * inv * gam[tid]       + bet[tid];
    float y1 = d1 * inv * gam[tid + 256] + bet[tid + 256];
    float y2 = d2 * inv * gam[tid + 512] + bet[tid + 512];
    h[base + tid]       = y0;
    h[base + tid + 256] = y1;
    h[base + tid + 512] = y2;
    __half hi, lo;
    split_f16(y0, hi, lo); hhi[base + tid]       = hi; hlo[base + tid]       = lo;
    split_f16(y1, hi, lo); hhi[base + tid + 256] = hi; hlo[base + tid + 256] = lo;
    split_f16(y2, hi, lo); hhi[base + tid + 512] = hi; hlo[base + tid + 512] = lo;
}

// ---------------- masked mean pool ----------------
__global__ void pool_kernel(const float* __restrict__ h, const float* __restrict__ mask,
                            float* __restrict__ pool)
{
    const int b = blockIdx.x;
    const int c = blockIdx.y * 128 + threadIdx.x;   // grid.y = 6
    float acc = 0.f, dn = 0.f;
    for (int s = 0; s < S_; ++s) {
        float m = mask[b * S_ + s];
        dn += m;
        acc += h[((size_t)(b * S_ + s)) * D_ + c] * m;
    }
    dn = fmaxf(dn, 1e-9f);
    pool[(size_t)b * D_ + c] = acc / dn;
}

// ---------------- final: out = relu(pool @ Wl + bl) ----------------
__global__ void final_kernel(const float* __restrict__ pool, const float* __restrict__ Wl,
                             const float* __restrict__ bl, float* __restrict__ out)
{
    const int b = blockIdx.x;
    const int o = threadIdx.x;   // 512
    __shared__ float sp[D_];
    for (int i = o; i < D_; i += 512) sp[i] = pool[(size_t)b * D_ + i];
    __syncthreads();
    float acc = bl[o];
    #pragma unroll 8
    for (int k = 0; k < D_; ++k)
        acc = fmaf(sp[k], Wl[(size_t)k * OUT_ + o], acc);
    out[(size_t)b * OUT_ + o] = fmaxf(acc, 0.f);
}

// ---------------- host ----------------
extern "C" void kernel_launch(void* const* d_in, const int* in_sizes, int n_in,
                              void* d_out, int out_size)
{
    const int*   x     = (const int*)  d_in[0];
    const float* mask  = (const float*)d_in[1];
    const float* tok   = (const float*)d_in[2];
    const float* Wq    = (const float*)d_in[3];
    const float* bq    = (const float*)d_in[4];
    const float* Wk    = (const float*)d_in[5];
    const float* bk    = (const float*)d_in[6];
    const float* Wv    = (const float*)d_in[7];
    const float* bv    = (const float*)d_in[8];
    const float* Wo    = (const float*)d_in[9];
    const float* bo    = (const float*)d_in[10];
    const float* omega = (const float*)d_in[11];
    const float* ln1s  = (const float*)d_in[12];
    const float* ln1b  = (const float*)d_in[13];
    const float* W1    = (const float*)d_in[14];
    const float* b1    = (const float*)d_in[15];
    const float* W2    = (const float*)d_in[16];
    const float* b2    = (const float*)d_in[17];
    const float* ln2s  = (const float*)d_in[18];
    const float* ln2b  = (const float*)d_in[19];
    const float* Wl    = (const float*)d_in[20];
    const float* bl    = (const float*)d_in[21];

    float *h, *qkv, *t1, *pq, *pk, *kv, *ps, *pool;
    __half *wh, *hhi, *hlo, *t1hi, *t1lo, *ffhi, *fflo;
    cudaGetSymbolAddress((void**)&h,   g_h);
    cudaGetSymbolAddress((void**)&qkv, g_qkv);
    cudaGetSymbolAddress((void**)&t1,  g_t1);
    cudaGetSymbolAddress((void**)&pq,  g_pq);
    cudaGetSymbolAddress((void**)&pk,  g_pk);
    cudaGetSymbolAddress((void**)&kv,  g_kv);
    cudaGetSymbolAddress((void**)&ps,  g_ps);
    cudaGetSymbolAddress((void**)&pool, g_pool);
    cudaGetSymbolAddress((void**)&wh,   g_wh);
    cudaGetSymbolAddress((void**)&hhi,  g_hhi);
    cudaGetSymbolAddress((void**)&hlo,  g_hlo);
    cudaGetSymbolAddress((void**)&t1hi, g_t1hi);
    cudaGetSymbolAddress((void**)&t1lo, g_t1lo);
    cudaGetSymbolAddress((void**)&ffhi, g_ffhi);
    cudaGetSymbolAddress((void**)&fflo, g_fflo);

    cudaFuncSetAttribute(mmagemm_kernel<0,0>, cudaFuncAttributeMaxDynamicSharedMemorySize, GB_SMEM);
    cudaFuncSetAttribute(mmagemm_kernel<1,1>, cudaFuncAttributeMaxDynamicSharedMemorySize, GB_SMEM);

    const size_t MATSZ = (size_t)NL_ * D_ * D_;
    const size_t LSZ   = (size_t)D_ * D_;

    dim3 gT(D_ / 32, D_ / 32, NL_);
    dim3 bT(32, 8);
    dim3 gQKV(18, BS_ / 128);   // fused Q,K,V
    dim3 gGemm(6, BS_ / 128);

    // launch order chosen so launch index 5 (ncu -s 5 -c 1) is the QKV GEMM
    embed_kernel<<<(BSD_ + 255) / 256, 256>>>(x, tok, h, hhi, hlo);      // 0
    wsplit_kernel<<<gT, bT>>>(Wq, wh + 0 * MATSZ);                        // 1
    wsplit_kernel<<<gT, bT>>>(Wk, wh + 1 * MATSZ);                        // 2
    wsplit_kernel<<<gT, bT>>>(Wv, wh + 2 * MATSZ);                        // 3
    wsplit_kernel<<<gT, bT>>>(Wo, wh + 3 * MATSZ);                        // 4
    // layer 0 QKV = launch 5 (profiled)
    mmagemm_kernel<0,0><<<gQKV, 256, GB_SMEM>>>(hhi, hlo, wh + 0 * MATSZ + 0 * LSZ, MATSZ,
                                                bq, bk, bv, qkv, nullptr, nullptr, (size_t)BSD_);
    wsplit_kernel<<<gT, bT>>>(W1, wh + 4 * MATSZ);                        // 6
    wsplit_kernel<<<gT, bT>>>(W2, wh + 5 * MATSZ);                        // 7

    for (int l = 0; l < NL_; ++l) {
        const float* lbq = bq + (size_t)l * D_;
        const float* lbk = bk + (size_t)l * D_;
        const float* lbv = bv + (size_t)l * D_;
        const float* lbo = bo + (size_t)l * D_;
        const float* lb1 = b1 + (size_t)l * D_;
        const float* lb2 = b2 + (size_t)l * D_;
        const float* lom = omega + (size_t)l * DH_ * NF_;
        const float* l1s = ln1s + (size_t)l * D_;
        const float* l1b = ln1b + (size_t)l * D_;
        const float* l2s = ln2s + (size_t)l * D_;
        const float* l2b = ln2b + (size_t)l * D_;

        if (l > 0) {
            mmagemm_kernel<0,0><<<gQKV, 256, GB_SMEM>>>(hhi, hlo, wh + 0 * MATSZ + l * LSZ, MATSZ,
                                                        lbq, lbk, lbv, qkv, nullptr, nullptr, (size_t)BSD_);
        }

        feat_kernel<<<BS_, 384>>>(qkv, qkv + BSD_, lom, mask, pq, pk);
        kv_kernel<<<B_ * H_, 256>>>(pk, qkv + 2 * (size_t)BSD_, kv, ps);
        att_kernel<<<B_ * H_, 512>>>(pq, kv, ps, t1hi, t1lo);

        // O projection -> qkv (free after att)
        mmagemm_kernel<0,0><<<gGemm, 256, GB_SMEM>>>(t1hi, t1lo, wh + 3 * MATSZ + l * LSZ, 0,
                                                     lbo, lbo, lbo, qkv, nullptr, nullptr, 0);
        addln_kernel<<<BS_, 256>>>(h, qkv, l1s, l1b, hhi, hlo);

        mmagemm_kernel<1,1><<<gGemm, 256, GB_SMEM>>>(hhi, hlo, wh + 4 * MATSZ + l * LSZ, 0,
                                                     lb1, lb1, lb1, nullptr, ffhi, fflo, 0);
        mmagemm_kernel<0,0><<<gGemm, 256, GB_SMEM>>>(ffhi, fflo, wh + 5 * MATSZ + l * LSZ, 0,
                                                     lb2, lb2, lb2, t1, nullptr, nullptr, 0);
        addln_kernel<<<BS_, 256>>>(h, t1, l2s, l2b, hhi, hlo);
    }

    dim3 gPool(B_, D_ / 128);
    pool_kernel<<<gPool, 128>>>(h, mask, pool);
    final_kernel<<<B_, 512>>>(pool, Wl, bl, (float*)d_out);
}

// round 14
// speedup vs baseline: 2.5544x; 1.0056x over previous
#include <cuda_runtime.h>
#include <cuda_fp16.h>
#include <math.h>
#include <stdint.h>

#define B_  64
#define S_  512
#define D_  768
#define H_  12
#define DH_ 64
#define NF_ 32
#define NL_ 12
#define OUT_ 512

static const int BS_  = B_ * S_;        // 32768
static const int BSD_ = B_ * S_ * D_;   // 25165824

// ---------------- scratch (allowed: __device__ globals) ----------------
__device__ float g_qkv[3 * B_*S_*D_];   // fused Q,K,V outputs (fp32)
__device__ float g_t1 [B_*S_*D_];       // FF2 out (residual)
__device__ float g_kv[B_*H_*NF_*DH_];
__device__ float g_ps[B_*H_*NF_];
__device__ float g_pool[B_*D_];
// fp16 exact-pair activations (GEMM A operands); h lives ONLY as this pair
__device__ __half g_hhi [B_*S_*D_];
__device__ __half g_hlo [B_*S_*D_];
__device__ __half g_t1hi[B_*S_*D_];
__device__ __half g_t1lo[B_*S_*D_];
__device__ __half g_ffhi[B_*S_*D_];
__device__ __half g_fflo[B_*S_*D_];
// fp16 transposed weights: [mat 0..5][layer][n][k]
__device__ __half g_wh[6 * NL_ * D_ * D_];

// ==================== PTX helpers ====================
__device__ __forceinline__ uint32_t smem_u32(const void* p){
    uint32_t a;
    asm("{ .reg .u64 t; cvta.to.shared.u64 t, %1; cvt.u32.u64 %0, t; }" : "=r"(a) : "l"(p));
    return a;
}

#define LDSMX4(r, addr) \
    asm volatile("ldmatrix.sync.aligned.m8n8.x4.shared.b16 {%0,%1,%2,%3}, [%4];" \
        : "=r"((r)[0]), "=r"((r)[1]), "=r"((r)[2]), "=r"((r)[3]) : "r"(addr))

#define MMA16816F16(d, a, b) \
    asm volatile("mma.sync.aligned.m16n8k16.row.col.f32.f16.f16.f32 " \
        "{%0,%1,%2,%3}, {%4,%5,%6,%7}, {%8,%9}, {%0,%1,%2,%3};" \
        : "+f"((d)[0]), "+f"((d)[1]), "+f"((d)[2]), "+f"((d)[3]) \
        : "r"((a)[0]), "r"((a)[1]), "r"((a)[2]), "r"((a)[3]), \
          "r"((b)[0]), "r"((b)[1]))

#define CP_ASYNC16(dst, src) \
    asm volatile("cp.async.cg.shared.global [%0], [%1], 16;" :: "r"(dst), "l"(src))
#define CP_COMMIT() asm volatile("cp.async.commit_group;" ::: "memory")
#define CP_WAIT0()  asm volatile("cp.async.wait_group 0;" ::: "memory")
#define CP_WAIT1()  asm volatile("cp.async.wait_group 1;" ::: "memory")

__device__ __forceinline__ void split_f16(float v, __half& hi, __half& lo){
    hi = __float2half_rn(v);
    lo = __float2half_rn(v - __half2float(hi));
}

// ---------------- embedding: exact fp16 pair only ----------------
__global__ void embed_kernel(const int* __restrict__ x, const float* __restrict__ emb,
                             __half* __restrict__ hhi, __half* __restrict__ hlo)
{
    long i = (long)blockIdx.x * blockDim.x + threadIdx.x;
    if (i < (long)BSD_) {
        int bs = (int)(i / D_);
        int d  = (int)(i % D_);
        float v = emb[(long)x[bs] * D_ + d];
        __half hi, lo;
        split_f16(v, hi, lo);
        hhi[i] = hi; hlo[i] = lo;
    }
}

// ---------------- weight transpose + fp16 convert ----------------
__global__ void wsplit_kernel(const float* __restrict__ W, __half* __restrict__ wh)
{
    __shared__ float s[32][33];
    const int l  = blockIdx.z;
    const int k0 = blockIdx.x * 32;
    const int n0 = blockIdx.y * 32;
    const int tx = threadIdx.x;       // 0..31
    const int ty = threadIdx.y;       // 0..7
    const float* Wl = W + (size_t)l * D_ * D_;
    #pragma unroll
    for (int i = 0; i < 4; i++)
        s[ty + 8 * i][tx] = Wl[(size_t)(k0 + ty + 8 * i) * D_ + n0 + tx];
    __syncthreads();
    #pragma unroll
    for (int i = 0; i < 4; i++) {
        int n = n0 + ty + 8 * i;
        int k = k0 + tx;
        wh[((size_t)l * D_ + n) * D_ + k] = __float2half_rn(s[tx][ty + 8 * i]);
    }
}

// ==================== mma.sync fp16 2-term GEMM ====================
#define GB_BUF    30720
#define GB_AHI    0
#define GB_ALO    10240
#define GB_BH     20480
#define GB_SMEM   (2 * GB_BUF)   // 61440

template<int ACT, int OSPLIT>
__global__ void __launch_bounds__(256, 2)
mmagemm_kernel(const __half* __restrict__ Ahi,
               const __half* __restrict__ Alo,
               const __half* __restrict__ Wh, size_t wstride,
               const float* __restrict__ bias0, const float* __restrict__ bias1,
               const float* __restrict__ bias2,
               float* __restrict__ C,
               __half* __restrict__ Chi, __half* __restrict__ Clo,
               size_t ostride)
{
    extern __shared__ char dsm[];
    const uint32_t sb32 = smem_u32(dsm);

    const int tid  = threadIdx.x;
    const int wid  = tid >> 5, lane = tid & 31;
    const int mat  = blockIdx.x / 6;
    const int bx   = blockIdx.x % 6;   // N tile
    const int by   = blockIdx.y;       // M tile
    const int wm   = wid >> 1;         // 0..3
    const int wn   = wid & 1;          // 0..1

    const __half* Wm = Wh + (size_t)mat * wstride;
    const float* bias = (mat == 0) ? bias0 : ((mat == 1) ? bias1 : bias2);

    const int r  = tid >> 1;
    const int hf = tid & 1;
    const uint32_t stOff = (uint32_t)r * 80u + (uint32_t)hf * 32u;
    const char* aH = (const char*)(Ahi + ((size_t)(by * 128) + r) * 768 + hf * 16);
    const char* aL = (const char*)(Alo + ((size_t)(by * 128) + r) * 768 + hf * 16);
    const char* bH = (const char*)(Wm  + ((size_t)(bx * 128) + r) * 768 + hf * 16);

    const uint32_t offA = (uint32_t)(wm * 32 + (lane & 15)) * 80u + ((lane >> 4) & 1) * 16u;
    const uint32_t offB = (uint32_t)(wn * 64 + (lane & 7) + ((lane >> 4) & 1) * 8) * 80u
                        + ((lane >> 3) & 1) * 16u;

    float acc[2][8][4];
    #pragma unroll
    for (int mt = 0; mt < 2; mt++)
        #pragma unroll
        for (int nt = 0; nt < 8; nt++)
            #pragma unroll
            for (int j = 0; j < 4; j++) acc[mt][nt][j] = 0.f;

    auto stage = [&](int kt, int buf) {
        uint32_t d = sb32 + (uint32_t)buf * GB_BUF + stOff;
        long o = (long)kt * 64;
        CP_ASYNC16(d + GB_AHI,      aH + o);
        CP_ASYNC16(d + GB_AHI + 16, aH + o + 16);
        CP_ASYNC16(d + GB_ALO,      aL + o);
        CP_ASYNC16(d + GB_ALO + 16, aL + o + 16);
        CP_ASYNC16(d + GB_BH,       bH + o);
        CP_ASYNC16(d + GB_BH + 16,  bH + o + 16);
        CP_COMMIT();
    };

    stage(0, 0);

    #pragma unroll 1
    for (int t = 0; t < 24; ++t) {
        const int cur = t & 1;
        const bool more = (t + 1 < 24);
        if (more) stage(t + 1, cur ^ 1);
        if (more) { CP_WAIT1(); } else { CP_WAIT0(); }
        __syncthreads();

        const uint32_t bufb = sb32 + (uint32_t)cur * GB_BUF;
        #pragma unroll
        for (int ks = 0; ks < 2; ks++) {
            uint32_t ah[2][4], al[2][4];
            #pragma unroll
            for (int mt = 0; mt < 2; mt++) {
                uint32_t ad = bufb + offA + (uint32_t)mt * (16u * 80u) + (uint32_t)ks * 32u;
                LDSMX4(ah[mt], ad + GB_AHI);
                LDSMX4(al[mt], ad + GB_ALO);
            }
            #pragma unroll
            for (int half = 0; half < 2; half++) {
                uint32_t bh[4][2];
                #pragma unroll
                for (int np = 0; np < 2; np++) {
                    uint32_t bd = bufb + offB + (uint32_t)(half * 2 + np) * (16u * 80u)
                                + (uint32_t)ks * 32u;
                    uint32_t th[4];
                    LDSMX4(th, bd + GB_BH);
                    bh[2*np][0]   = th[0]; bh[2*np][1]   = th[1];
                    bh[2*np+1][0] = th[2]; bh[2*np+1][1] = th[3];
                }
                #pragma unroll
                for (int mt = 0; mt < 2; mt++)
                    #pragma unroll
                    for (int j = 0; j < 4; j++) {
                        int nt = half * 4 + j;
                        MMA16816F16(acc[mt][nt], ah[mt], bh[j]);
                        MMA16816F16(acc[mt][nt], al[mt], bh[j]);
                    }
            }
        }
        __syncthreads();
    }

    // ---- epilogue ----
    const int erow = lane >> 2;
    const int ecol = (lane & 3) * 2;
    #pragma unroll
    for (int mt = 0; mt < 2; mt++) {
        #pragma unroll
        for (int nt = 0; nt < 8; nt++) {
            int grow = by * 128 + wm * 32 + mt * 16 + erow;
            int gcol = bx * 128 + wn * 64 + nt * 8 + ecol;
            float b0 = __ldg(bias + gcol), b1 = __ldg(bias + gcol + 1);
            float v0 = acc[mt][nt][0] + b0;
            float v1 = acc[mt][nt][1] + b1;
            float v2 = acc[mt][nt][2] + b0;
            float v3 = acc[mt][nt][3] + b1;
            if (ACT == 1) {
                v0 = 0.5f * v0 * (1.0f + erff(v0 * 0.70710678118654752f));
                v1 = 0.5f * v1 * (1.0f + erff(v1 * 0.70710678118654752f));
                v2 = 0.5f * v2 * (1.0f + erff(v2 * 0.70710678118654752f));
                v3 = 0.5f * v3 * (1.0f + erff(v3 * 0.70710678118654752f));
            }
            if (OSPLIT == 0) {
                float* Cb = C + (size_t)mat * ostride;
                *(float2*)(Cb + (size_t)grow * 768 + gcol)       = make_float2(v0, v1);
                *(float2*)(Cb + (size_t)(grow + 8) * 768 + gcol) = make_float2(v2, v3);
            } else {
                __half h0, l0, h1, l1;
                split_f16(v0, h0, l0); split_f16(v1, h1, l1);
                __half2 hp = __halves2half2(h0, h1);
                __half2 lp = __halves2half2(l0, l1);
                *(uint32_t*)(Chi + (size_t)grow * 768 + gcol) = *(uint32_t*)&hp;
                *(uint32_t*)(Clo + (size_t)grow * 768 + gcol) = *(uint32_t*)&lp;
                split_f16(v2, h0, l0); split_f16(v3, h1, l1);
                hp = __halves2half2(h0, h1);
                lp = __halves2half2(l0, l1);
                *(uint32_t*)(Chi + (size_t)(grow + 8) * 768 + gcol) = *(uint32_t*)&hp;
                *(uint32_t*)(Clo + (size_t)(grow + 8) * 768 + gcol) = *(uint32_t*)&lp;
            }
        }
    }
}

// ================= FK: rotary-k + feature map + kv/ps (per (b,h)) =================
__global__ void __launch_bounds__(256)
fk_kernel(const float* __restrict__ k, const float* __restrict__ v,
          const float* __restrict__ om, const float* __restrict__ mask,
          float* __restrict__ kvout, float* __restrict__ psout)
{
    const int b = blockIdx.x / H_;
    const int h = blockIdx.x % H_;
    const int tid = threadIdx.x;      // 256

    __shared__ float som[DH_ * NF_];  // [d][f]
    __shared__ float sk [8][DH_];
    __shared__ float sv [8][DH_];
    __shared__ float spk[8][NF_];

    for (int i = tid; i < DH_ * NF_; i += 256) som[i] = om[i];

    const int iA = tid >> 5, fA = tid & 31;   // phase A: (row, feature/rot-pair)
    const int fB = tid >> 3, dB = (tid & 7) * 8;

    // rotation recurrence: ang = s*invf, s = iA + 8*step
    const float invf = expf(-(float)fA * 0.28782313662425572f); // ln(1e4)/32
    float c, sn, c8, s8;
    sincosf((float)iA * invf, &sn, &c);
    sincosf(8.0f * invf, &s8, &c8);

    float acc[8];
    #pragma unroll
    for (int i = 0; i < 8; i++) acc[i] = 0.f;
    float psum = 0.f;

    __syncthreads();

    #pragma unroll 1
    for (int s0 = 0; s0 < S_; s0 += 8) {
        const int s = s0 + iA;
        const size_t rowb = ((size_t)(b * S_ + s)) * D_ + h * DH_;
        float ka = k[rowb + fA], kb = k[rowb + fA + 32];
        sk[iA][fA]      = ka * c - kb * sn;
        sk[iA][fA + 32] = kb * c + ka * sn;
        ((float2*)sv[iA])[fA] = ((const float2*)(v + rowb))[fA];
        __syncthreads();

        float a = 0.f;
        #pragma unroll
        for (int d = 0; d < DH_; ++d) a = fmaf(sk[iA][d], som[d * NF_ + fA], a);
        spk[iA][fA] = fmaxf(a, 0.f) * mask[b * S_ + s];
        __syncthreads();

        #pragma unroll
        for (int i = 0; i < 8; i++) {
            float p = spk[i][fB];
            psum += p;
            #pragma unroll
            for (int j = 0; j < 8; j++)
                acc[j] = fmaf(p, sv[i][dB + j], acc[j]);
        }
        // advance rotation by 8 steps
        float cn = c * c8 - sn * s8;
        sn = sn * c8 + c * s8;
        c = cn;
        __syncthreads();
    }

    #pragma unroll
    for (int j = 0; j < 8; j++)
        kvout[(((size_t)(b * H_ + h)) * NF_ + fB) * DH_ + dB + j] = acc[j];
    if ((tid & 7) == 0) psout[((size_t)(b * H_ + h)) * NF_ + fB] = psum;
}

// ============ FA: rotary-q + feature map + z + pq@kv -> fp16 pair ============
__global__ void __launch_bounds__(256)
fa_kernel(const float* __restrict__ q, const float* __restrict__ kvin,
          const float* __restrict__ psin, const float* __restrict__ om,
          __half* __restrict__ ahi, __half* __restrict__ alo)
{
    const int b = blockIdx.x / H_;
    const int h = blockIdx.x % H_;
    const int tid = threadIdx.x;      // 256

    __shared__ float som[DH_ * NF_];  // [d][f]
    __shared__ float skv[NF_][DH_];
    __shared__ float sps[NF_];
    __shared__ float sq [8][DH_];
    __shared__ float spq[8][NF_];
    __shared__ float sz [8];

    for (int i = tid; i < DH_ * NF_; i += 256) som[i] = om[i];
    for (int i = tid; i < NF_ * DH_; i += 256)
        ((float*)skv)[i] = kvin[((size_t)(b * H_ + h)) * NF_ * DH_ + i];
    if (tid < NF_) sps[tid] = psin[((size_t)(b * H_ + h)) * NF_ + tid];

    const int iA = tid >> 5, fA = tid & 31;

    const float invf = expf(-(float)fA * 0.28782313662425572f);
    float c, sn, c8, s8;
    sincosf((float)iA * invf, &sn, &c);
    sincosf(8.0f * invf, &s8, &c8);

    __syncthreads();

    #pragma unroll 1
    for (int s0 = 0; s0 < S_; s0 += 8) {
        const int s = s0 + iA;
        const size_t rowb = ((size_t)(b * S_ + s)) * D_ + h * DH_;
        float qa = q[rowb + fA], qb = q[rowb + fA + 32];
        sq[iA][fA]      = qa * c - qb * sn;
        sq[iA][fA + 32] = qb * c + qa * sn;
        __syncthreads();

        float a = 0.f;
        #pragma unroll
        for (int d = 0; d < DH_; ++d) a = fmaf(sq[iA][d], som[d * NF_ + fA], a);
        float pq = fmaxf(a, 0.f);
        spq[iA][fA] = pq;
        float zp = pq * sps[fA];
        #pragma unroll
        for (int o = 16; o; o >>= 1) zp += __shfl_xor_sync(0xffffffffu, zp, o);
        if (fA == 0) sz[iA] = zp;
        __syncthreads();

        // outputs: thread (iA, d=fA) and (iA, d=fA+32)
        float o1 = 0.f, o2 = 0.f;
        #pragma unroll
        for (int f = 0; f < NF_; ++f) {
            float p = spq[iA][f];
            o1 = fmaf(p, skv[f][fA],      o1);
            o2 = fmaf(p, skv[f][fA + 32], o2);
        }
        float zi = 1.0f / (sz[iA] + 1e-6f);
        o1 *= zi; o2 *= zi;
        __half hi, lo;
        split_f16(o1, hi, lo);
        ahi[rowb + fA]      = hi; alo[rowb + fA]      = lo;
        split_f16(o2, hi, lo);
        ahi[rowb + fA + 32] = hi; alo[rowb + fA + 32] = lo;

        float cn = c * c8 - sn * s8;
        sn = sn * c8 + c * s8;
        c = cn;
        __syncthreads();
    }
}

// ------- residual + LayerNorm: h kept ONLY as exact fp16 pair -------
__global__ void addln_kernel(__half* __restrict__ hhi, __half* __restrict__ hlo,
                             const float* __restrict__ r,
                             const float* __restrict__ gam, const float* __restrict__ bet)
{
    const int row = blockIdx.x;
    const int tid = threadIdx.x;   // 256
    const size_t base = (size_t)row * D_;

    float x0 = __half2float(hhi[base + tid])       + __half2float(hlo[base + tid])       + r[base + tid];
    float x1 = __half2float(hhi[base + tid + 256]) + __half2float(hlo[base + tid + 256]) + r[base + tid + 256];
    float x2 = __half2float(hhi[base + tid + 512]) + __half2float(hlo[base + tid + 512]) + r[base + tid + 512];

    __shared__ float red[8];
    float s = x0 + x1 + x2;
    #pragma unroll
    for (int o = 16; o; o >>= 1) s += __shfl_xor_sync(0xffffffffu, s, o);
    if ((tid & 31) == 0) red[tid >> 5] = s;
    __syncthreads();
    float tot = red[0] + red[1] + red[2] + red[3] + red[4] + red[5] + red[6] + red[7];
    float mean = tot * (1.0f / 768.0f);

    float d0 = x0 - mean, d1 = x1 - mean, d2 = x2 - mean;
    float s2 = d0 * d0 + d1 * d1 + d2 * d2;
    #pragma unroll
    for (int o = 16; o; o >>= 1) s2 += __shfl_xor_sync(0xffffffffu, s2, o);
    __syncthreads();
    if ((tid & 31) == 0) red[tid >> 5] = s2;
    __syncthreads();
    float var = (red[0] + red[1] + red[2] + red[3] + red[4] + red[5] + red[6] + red[7]) * (1.0f / 768.0f);
    float inv = rsqrtf(var + 1e-5f);

    float y0 = d0 * inv * gam[tid]       + bet[tid];
    float y1 = d1 * inv * gam[tid + 256] + bet[tid + 256];
    float y2 = d2 * inv * gam[tid + 512] + bet[tid + 512];
    __half hi, lo;
    split_f16(y0, hi, lo); hhi[base + tid]       = hi; hlo[base + tid]       = lo;
    split_f16(y1, hi, lo); hhi[base + tid + 256] = hi; hlo[base + tid + 256] = lo;
    split_f16(y2, hi, lo); hhi[base + tid + 512] = hi; hlo[base + tid + 512] = lo;
}

// ---------------- masked mean pool (reads fp16 pair) ----------------
__global__ void pool_kernel(const __half* __restrict__ hhi, const __half* __restrict__ hlo,
                            const float* __restrict__ mask, float* __restrict__ pool)
{
    const int b = blockIdx.x;
    const int c = blockIdx.y * 128 + threadIdx.x;   // grid.y = 6
    float acc = 0.f, dn = 0.f;
    for (int s = 0; s < S_; ++s) {
        float m = mask[b * S_ + s];
        dn += m;
        size_t i = ((size_t)(b * S_ + s)) * D_ + c;
        acc += (__half2float(hhi[i]) + __half2float(hlo[i])) * m;
    }
    dn = fmaxf(dn, 1e-9f);
    pool[(size_t)b * D_ + c] = acc / dn;
}

// ---------------- final: out = relu(pool @ Wl + bl) ----------------
__global__ void final_kernel(const float* __restrict__ pool, const float* __restrict__ Wl,
                             const float* __restrict__ bl, float* __restrict__ out)
{
    const int b = blockIdx.x;
    const int o = threadIdx.x;   // 512
    __shared__ float sp[D_];
    for (int i = o; i < D_; i += 512) sp[i] = pool[(size_t)b * D_ + i];
    __syncthreads();
    float acc = bl[o];
    #pragma unroll 8
    for (int k = 0; k < D_; ++k)
        acc = fmaf(sp[k], Wl[(size_t)k * OUT_ + o], acc);
    out[(size_t)b * OUT_ + o] = fmaxf(acc, 0.f);
}

// ---------------- host ----------------
extern "C" void kernel_launch(void* const* d_in, const int* in_sizes, int n_in,
                              void* d_out, int out_size)
{
    const int*   x     = (const int*)  d_in[0];
    const float* mask  = (const float*)d_in[1];
    const float* tok   = (const float*)d_in[2];
    const float* Wq    = (const float*)d_in[3];
    const float* bq    = (const float*)d_in[4];
    const float* Wk    = (const float*)d_in[5];
    const float* bk    = (const float*)d_in[6];
    const float* Wv    = (const float*)d_in[7];
    const float* bv    = (const float*)d_in[8];
    const float* Wo    = (const float*)d_in[9];
    const float* bo    = (const float*)d_in[10];
    const float* omega = (const float*)d_in[11];
    const float* ln1s  = (const float*)d_in[12];
    const float* ln1b  = (const float*)d_in[13];
    const float* W1    = (const float*)d_in[14];
    const float* b1    = (const float*)d_in[15];
    const float* W2    = (const float*)d_in[16];
    const float* b2    = (const float*)d_in[17];
    const float* ln2s  = (const float*)d_in[18];
    const float* ln2b  = (const float*)d_in[19];
    const float* Wl    = (const float*)d_in[20];
    const float* bl    = (const float*)d_in[21];

    float *qkv, *t1, *kv, *ps, *pool;
    __half *wh, *hhi, *hlo, *t1hi, *t1lo, *ffhi, *fflo;
    cudaGetSymbolAddress((void**)&qkv, g_qkv);
    cudaGetSymbolAddress((void**)&t1,  g_t1);
    cudaGetSymbolAddress((void**)&kv,  g_kv);
    cudaGetSymbolAddress((void**)&ps,  g_ps);
    cudaGetSymbolAddress((void**)&pool, g_pool);
    cudaGetSymbolAddress((void**)&wh,   g_wh);
    cudaGetSymbolAddress((void**)&hhi,  g_hhi);
    cudaGetSymbolAddress((void**)&hlo,  g_hlo);
    cudaGetSymbolAddress((void**)&t1hi, g_t1hi);
    cudaGetSymbolAddress((void**)&t1lo, g_t1lo);
    cudaGetSymbolAddress((void**)&ffhi, g_ffhi);
    cudaGetSymbolAddress((void**)&fflo, g_fflo);

    cudaFuncSetAttribute(mmagemm_kernel<0,0>, cudaFuncAttributeMaxDynamicSharedMemorySize, GB_SMEM);
    cudaFuncSetAttribute(mmagemm_kernel<1,1>, cudaFuncAttributeMaxDynamicSharedMemorySize, GB_SMEM);

    const size_t MATSZ = (size_t)NL_ * D_ * D_;
    const size_t LSZ   = (size_t)D_ * D_;

    dim3 gT(D_ / 32, D_ / 32, NL_);
    dim3 bT(32, 8);
    dim3 gQKV(18, BS_ / 128);
    dim3 gGemm(6, BS_ / 128);

    embed_kernel<<<(BSD_ + 255) / 256, 256>>>(x, tok, hhi, hlo);
    wsplit_kernel<<<gT, bT>>>(Wq, wh + 0 * MATSZ);
    wsplit_kernel<<<gT, bT>>>(Wk, wh + 1 * MATSZ);
    wsplit_kernel<<<gT, bT>>>(Wv, wh + 2 * MATSZ);
    wsplit_kernel<<<gT, bT>>>(Wo, wh + 3 * MATSZ);
    wsplit_kernel<<<gT, bT>>>(W1, wh + 4 * MATSZ);
    wsplit_kernel<<<gT, bT>>>(W2, wh + 5 * MATSZ);

    for (int l = 0; l < NL_; ++l) {
        const float* lbq = bq + (size_t)l * D_;
        const float* lbk = bk + (size_t)l * D_;
        const float* lbv = bv + (size_t)l * D_;
        const float* lbo = bo + (size_t)l * D_;
        const float* lb1 = b1 + (size_t)l * D_;
        const float* lb2 = b2 + (size_t)l * D_;
        const float* lom = omega + (size_t)l * DH_ * NF_;
        const float* l1s = ln1s + (size_t)l * D_;
        const float* l1b = ln1b + (size_t)l * D_;
        const float* l2s = ln2s + (size_t)l * D_;
        const float* l2b = ln2b + (size_t)l * D_;

        mmagemm_kernel<0,0><<<gQKV, 256, GB_SMEM>>>(hhi, hlo, wh + 0 * MATSZ + l * LSZ, MATSZ,
                                                    lbq, lbk, lbv, qkv, nullptr, nullptr, (size_t)BSD_);

        fk_kernel<<<B_ * H_, 256>>>(qkv + BSD_, qkv + 2 * (size_t)BSD_, lom, mask, kv, ps);
        fa_kernel<<<B_ * H_, 256>>>(qkv, kv, ps, lom, t1hi, t1lo);

        // O projection -> qkv buffer (free after fa)
        mmagemm_kernel<0,0><<<gGemm, 256, GB_SMEM>>>(t1hi, t1lo, wh + 3 * MATSZ + l * LSZ, 0,
                                                     lbo, lbo, lbo, qkv, nullptr, nullptr, 0);
        addln_kernel<<<BS_, 256>>>(hhi, hlo, qkv, l1s, l1b);

        mmagemm_kernel<1,1><<<gGemm, 256, GB_SMEM>>>(hhi, hlo, wh + 4 * MATSZ + l * LSZ, 0,
                                                     lb1, lb1, lb1, nullptr, ffhi, fflo, 0);
        mmagemm_kernel<0,0><<<gGemm, 256, GB_SMEM>>>(ffhi, fflo, wh + 5 * MATSZ + l * LSZ, 0,
                                                     lb2, lb2, lb2, t1, nullptr, nullptr, 0);
        addln_kernel<<<BS_, 256>>>(hhi, hlo, t1, l2s, l2b);
    }

    dim3 gPool(B_, D_ / 128);
    pool_kernel<<<gPool, 128>>>(hhi, hlo, mask, pool);
    final_kernel<<<B_, 512>>>(pool, Wl, bl, (float*)d_out);
}

// round 15
// speedup vs baseline: 2.5583x; 1.0015x over previous
#include <cuda_runtime.h>
#include <cuda_fp16.h>
#include <math.h>
#include <stdint.h>

#define B_  64
#define S_  512
#define D_  768
#define H_  12
#define DH_ 64
#define NF_ 32
#define NL_ 12
#define OUT_ 512

static const int BS_  = B_ * S_;        // 32768
static const int BSD_ = B_ * S_ * D_;   // 25165824

// ---------------- scratch (allowed: __device__ globals) ----------------
__device__ float g_qkv[3 * B_*S_*D_];   // fused Q,K,V outputs (fp32)
__device__ float g_t1 [B_*S_*D_];       // FF2 out (residual)
__device__ float g_kv[B_*H_*NF_*DH_];
__device__ float g_ps[B_*H_*NF_];
__device__ float g_pool[B_*D_];
// fp16 exact-pair activations (GEMM A operands); h lives ONLY as this pair
__device__ __half g_hhi [B_*S_*D_];
__device__ __half g_hlo [B_*S_*D_];
__device__ __half g_t1hi[B_*S_*D_];
__device__ __half g_t1lo[B_*S_*D_];
__device__ __half g_ffhi[B_*S_*D_];
__device__ __half g_fflo[B_*S_*D_];
// fp16 transposed weights: [mat 0..5][layer][n][k]
__device__ __half g_wh[6 * NL_ * D_ * D_];

// ==================== PTX helpers ====================
__device__ __forceinline__ uint32_t smem_u32(const void* p){
    uint32_t a;
    asm("{ .reg .u64 t; cvta.to.shared.u64 t, %1; cvt.u32.u64 %0, t; }" : "=r"(a) : "l"(p));
    return a;
}

#define LDSMX4(r, addr) \
    asm volatile("ldmatrix.sync.aligned.m8n8.x4.shared.b16 {%0,%1,%2,%3}, [%4];" \
        : "=r"((r)[0]), "=r"((r)[1]), "=r"((r)[2]), "=r"((r)[3]) : "r"(addr))

#define MMA16816F16(d, a, b) \
    asm volatile("mma.sync.aligned.m16n8k16.row.col.f32.f16.f16.f32 " \
        "{%0,%1,%2,%3}, {%4,%5,%6,%7}, {%8,%9}, {%0,%1,%2,%3};" \
        : "+f"((d)[0]), "+f"((d)[1]), "+f"((d)[2]), "+f"((d)[3]) \
        : "r"((a)[0]), "r"((a)[1]), "r"((a)[2]), "r"((a)[3]), \
          "r"((b)[0]), "r"((b)[1]))

#define CP_ASYNC16(dst, src) \
    asm volatile("cp.async.cg.shared.global [%0], [%1], 16;" :: "r"(dst), "l"(src))
#define CP_COMMIT() asm volatile("cp.async.commit_group;" ::: "memory")
#define CP_WAIT0()  asm volatile("cp.async.wait_group 0;" ::: "memory")
#define CP_WAIT1()  asm volatile("cp.async.wait_group 1;" ::: "memory")

__device__ __forceinline__ void split_f16(float v, __half& hi, __half& lo){
    hi = __float2half_rn(v);
    lo = __float2half_rn(v - __half2float(hi));
}

// ---------------- embedding: exact fp16 pair only ----------------
__global__ void embed_kernel(const int* __restrict__ x, const float* __restrict__ emb,
                             __half* __restrict__ hhi, __half* __restrict__ hlo)
{
    long i = (long)blockIdx.x * blockDim.x + threadIdx.x;
    if (i < (long)BSD_) {
        int bs = (int)(i / D_);
        int d  = (int)(i % D_);
        float v = emb[(long)x[bs] * D_ + d];
        __half hi, lo;
        split_f16(v, hi, lo);
        hhi[i] = hi; hlo[i] = lo;
    }
}

// ---------------- weight transpose + fp16 convert ----------------
__global__ void wsplit_kernel(const float* __restrict__ W, __half* __restrict__ wh)
{
    __shared__ float s[32][33];
    const int l  = blockIdx.z;
    const int k0 = blockIdx.x * 32;
    const int n0 = blockIdx.y * 32;
    const int tx = threadIdx.x;       // 0..31
    const int ty = threadIdx.y;       // 0..7
    const float* Wl = W + (size_t)l * D_ * D_;
    #pragma unroll
    for (int i = 0; i < 4; i++)
        s[ty + 8 * i][tx] = Wl[(size_t)(k0 + ty + 8 * i) * D_ + n0 + tx];
    __syncthreads();
    #pragma unroll
    for (int i = 0; i < 4; i++) {
        int n = n0 + ty + 8 * i;
        int k = k0 + tx;
        wh[((size_t)l * D_ + n) * D_ + k] = __float2half_rn(s[tx][ty + 8 * i]);
    }
}

// ==================== mma.sync fp16 2-term GEMM ====================
#define GB_BUF    30720
#define GB_AHI    0
#define GB_ALO    10240
#define GB_BH     20480
#define GB_SMEM   (2 * GB_BUF)   // 61440

template<int ACT, int OSPLIT>
__global__ void __launch_bounds__(256, 2)
mmagemm_kernel(const __half* __restrict__ Ahi,
               const __half* __restrict__ Alo,
               const __half* __restrict__ Wh, size_t wstride,
               const float* __restrict__ bias0, const float* __restrict__ bias1,
               const float* __restrict__ bias2,
               float* __restrict__ C,
               __half* __restrict__ Chi, __half* __restrict__ Clo,
               size_t ostride)
{
    extern __shared__ char dsm[];
    const uint32_t sb32 = smem_u32(dsm);

    const int tid  = threadIdx.x;
    const int wid  = tid >> 5, lane = tid & 31;
    const int mat  = blockIdx.x / 6;
    const int bx   = blockIdx.x % 6;   // N tile
    const int by   = blockIdx.y;       // M tile
    const int wm   = wid >> 1;         // 0..3
    const int wn   = wid & 1;          // 0..1

    const __half* Wm = Wh + (size_t)mat * wstride;
    const float* bias = (mat == 0) ? bias0 : ((mat == 1) ? bias1 : bias2);

    const int r  = tid >> 1;
    const int hf = tid & 1;
    const uint32_t stOff = (uint32_t)r * 80u + (uint32_t)hf * 32u;
    const char* aH = (const char*)(Ahi + ((size_t)(by * 128) + r) * 768 + hf * 16);
    const char* aL = (const char*)(Alo + ((size_t)(by * 128) + r) * 768 + hf * 16);
    const char* bH = (const char*)(Wm  + ((size_t)(bx * 128) + r) * 768 + hf * 16);

    const uint32_t offA = (uint32_t)(wm * 32 + (lane & 15)) * 80u + ((lane >> 4) & 1) * 16u;
    const uint32_t offB = (uint32_t)(wn * 64 + (lane & 7) + ((lane >> 4) & 1) * 8) * 80u
                        + ((lane >> 3) & 1) * 16u;

    float acc[2][8][4];
    #pragma unroll
    for (int mt = 0; mt < 2; mt++)
        #pragma unroll
        for (int nt = 0; nt < 8; nt++)
            #pragma unroll
            for (int j = 0; j < 4; j++) acc[mt][nt][j] = 0.f;

    auto stage = [&](int kt, int buf) {
        uint32_t d = sb32 + (uint32_t)buf * GB_BUF + stOff;
        long o = (long)kt * 64;
        CP_ASYNC16(d + GB_AHI,      aH + o);
        CP_ASYNC16(d + GB_AHI + 16, aH + o + 16);
        CP_ASYNC16(d + GB_ALO,      aL + o);
        CP_ASYNC16(d + GB_ALO + 16, aL + o + 16);
        CP_ASYNC16(d + GB_BH,       bH + o);
        CP_ASYNC16(d + GB_BH + 16,  bH + o + 16);
        CP_COMMIT();
    };

    stage(0, 0);

    #pragma unroll 1
    for (int t = 0; t < 24; ++t) {
        const int cur = t & 1;
        const bool more = (t + 1 < 24);
        if (more) stage(t + 1, cur ^ 1);
        if (more) { CP_WAIT1(); } else { CP_WAIT0(); }
        __syncthreads();

        const uint32_t bufb = sb32 + (uint32_t)cur * GB_BUF;
        #pragma unroll
        for (int ks = 0; ks < 2; ks++) {
            uint32_t ah[2][4], al[2][4];
            #pragma unroll
            for (int mt = 0; mt < 2; mt++) {
                uint32_t ad = bufb + offA + (uint32_t)mt * (16u * 80u) + (uint32_t)ks * 32u;
                LDSMX4(ah[mt], ad + GB_AHI);
                LDSMX4(al[mt], ad + GB_ALO);
            }
            #pragma unroll
            for (int half = 0; half < 2; half++) {
                uint32_t bh[4][2];
                #pragma unroll
                for (int np = 0; np < 2; np++) {
                    uint32_t bd = bufb + offB + (uint32_t)(half * 2 + np) * (16u * 80u)
                                + (uint32_t)ks * 32u;
                    uint32_t th[4];
                    LDSMX4(th, bd + GB_BH);
                    bh[2*np][0]   = th[0]; bh[2*np][1]   = th[1];
                    bh[2*np+1][0] = th[2]; bh[2*np+1][1] = th[3];
                }
                #pragma unroll
                for (int mt = 0; mt < 2; mt++)
                    #pragma unroll
                    for (int j = 0; j < 4; j++) {
                        int nt = half * 4 + j;
                        MMA16816F16(acc[mt][nt], ah[mt], bh[j]);
                        MMA16816F16(acc[mt][nt], al[mt], bh[j]);
                    }
            }
        }
        __syncthreads();
    }

    // ---- epilogue ----
    const int erow = lane >> 2;
    const int ecol = (lane & 3) * 2;
    #pragma unroll
    for (int mt = 0; mt < 2; mt++) {
        #pragma unroll
        for (int nt = 0; nt < 8; nt++) {
            int grow = by * 128 + wm * 32 + mt * 16 + erow;
            int gcol = bx * 128 + wn * 64 + nt * 8 + ecol;
            float b0 = __ldg(bias + gcol), b1 = __ldg(bias + gcol + 1);
            float v0 = acc[mt][nt][0] + b0;
            float v1 = acc[mt][nt][1] + b1;
            float v2 = acc[mt][nt][2] + b0;
            float v3 = acc[mt][nt][3] + b1;
            if (ACT == 1) {
                v0 = 0.5f * v0 * (1.0f + erff(v0 * 0.70710678118654752f));
                v1 = 0.5f * v1 * (1.0f + erff(v1 * 0.70710678118654752f));
                v2 = 0.5f * v2 * (1.0f + erff(v2 * 0.70710678118654752f));
                v3 = 0.5f * v3 * (1.0f + erff(v3 * 0.70710678118654752f));
            }
            if (OSPLIT == 0) {
                float* Cb = C + (size_t)mat * ostride;
                *(float2*)(Cb + (size_t)grow * 768 + gcol)       = make_float2(v0, v1);
                *(float2*)(Cb + (size_t)(grow + 8) * 768 + gcol) = make_float2(v2, v3);
            } else {
                __half h0, l0, h1, l1;
                split_f16(v0, h0, l0); split_f16(v1, h1, l1);
                __half2 hp = __halves2half2(h0, h1);
                __half2 lp = __halves2half2(l0, l1);
                *(uint32_t*)(Chi + (size_t)grow * 768 + gcol) = *(uint32_t*)&hp;
                *(uint32_t*)(Clo + (size_t)grow * 768 + gcol) = *(uint32_t*)&lp;
                split_f16(v2, h0, l0); split_f16(v3, h1, l1);
                hp = __halves2half2(h0, h1);
                lp = __halves2half2(l0, l1);
                *(uint32_t*)(Chi + (size_t)(grow + 8) * 768 + gcol) = *(uint32_t*)&hp;
                *(uint32_t*)(Clo + (size_t)(grow + 8) * 768 + gcol) = *(uint32_t*)&lp;
            }
        }
    }
}

// ================= FK: rotary-k + feature map + kv/ps (per (b,h)) =================
__global__ void __launch_bounds__(256)
fk_kernel(const float* __restrict__ k, const float* __restrict__ v,
          const float* __restrict__ om, const float* __restrict__ mask,
          float* __restrict__ kvout, float* __restrict__ psout)
{
    const int b = blockIdx.x / H_;
    const int h = blockIdx.x % H_;
    const int tid = threadIdx.x;      // 256

    __shared__ float som[DH_ * NF_];  // [d][f]
    __shared__ float sk [8][DH_];
    __shared__ float sv [8][DH_];
    __shared__ float spk[8][NF_];

    for (int i = tid; i < DH_ * NF_; i += 256) som[i] = om[i];

    const int iA = tid >> 5, fA = tid & 31;   // phase A: (row, feature/rot-pair)
    const int fB = tid >> 3, dB = (tid & 7) * 8;

    // rotation recurrence: ang = s*invf, s = iA + 8*step
    const float invf = expf(-(float)fA * 0.28782313662425572f); // ln(1e4)/32
    float c, sn, c8, s8;
    sincosf((float)iA * invf, &sn, &c);
    sincosf(8.0f * invf, &s8, &c8);

    float acc[8];
    #pragma unroll
    for (int i = 0; i < 8; i++) acc[i] = 0.f;
    float psum = 0.f;

    __syncthreads();

    #pragma unroll 1
    for (int s0 = 0; s0 < S_; s0 += 8) {
        const int s = s0 + iA;
        const size_t rowb = ((size_t)(b * S_ + s)) * D_ + h * DH_;
        float ka = k[rowb + fA], kb = k[rowb + fA + 32];
        sk[iA][fA]      = ka * c - kb * sn;
        sk[iA][fA + 32] = kb * c + ka * sn;
        ((float2*)sv[iA])[fA] = ((const float2*)(v + rowb))[fA];
        __syncthreads();

        float a = 0.f;
        #pragma unroll
        for (int d = 0; d < DH_; ++d) a = fmaf(sk[iA][d], som[d * NF_ + fA], a);
        spk[iA][fA] = fmaxf(a, 0.f) * mask[b * S_ + s];
        __syncthreads();

        #pragma unroll
        for (int i = 0; i < 8; i++) {
            float p = spk[i][fB];
            psum += p;
            #pragma unroll
            for (int j = 0; j < 8; j++)
                acc[j] = fmaf(p, sv[i][dB + j], acc[j]);
        }
        // advance rotation by 8 steps
        float cn = c * c8 - sn * s8;
        sn = sn * c8 + c * s8;
        c = cn;
        __syncthreads();
    }

    #pragma unroll
    for (int j = 0; j < 8; j++)
        kvout[(((size_t)(b * H_ + h)) * NF_ + fB) * DH_ + dB + j] = acc[j];
    if ((tid & 7) == 0) psout[((size_t)(b * H_ + h)) * NF_ + fB] = psum;
}

// ============ FA: rotary-q + feature map + z + pq@kv -> fp16 pair ============
__global__ void __launch_bounds__(256)
fa_kernel(const float* __restrict__ q, const float* __restrict__ kvin,
          const float* __restrict__ psin, const float* __restrict__ om,
          __half* __restrict__ ahi, __half* __restrict__ alo)
{
    const int b = blockIdx.x / H_;
    const int h = blockIdx.x % H_;
    const int tid = threadIdx.x;      // 256

    __shared__ float som[DH_ * NF_];  // [d][f]
    __shared__ float skv[NF_][DH_];
    __shared__ float sps[NF_];
    __shared__ float sq [8][DH_];
    __shared__ float spq[8][NF_];
    __shared__ float sz [8];

    for (int i = tid; i < DH_ * NF_; i += 256) som[i] = om[i];
    for (int i = tid; i < NF_ * DH_; i += 256)
        ((float*)skv)[i] = kvin[((size_t)(b * H_ + h)) * NF_ * DH_ + i];
    if (tid < NF_) sps[tid] = psin[((size_t)(b * H_ + h)) * NF_ + tid];

    const int iA = tid >> 5, fA = tid & 31;

    const float invf = expf(-(float)fA * 0.28782313662425572f);
    float c, sn, c8, s8;
    sincosf((float)iA * invf, &sn, &c);
    sincosf(8.0f * invf, &s8, &c8);

    __syncthreads();

    #pragma unroll 1
    for (int s0 = 0; s0 < S_; s0 += 8) {
        const int s = s0 + iA;
        const size_t rowb = ((size_t)(b * S_ + s)) * D_ + h * DH_;
        float qa = q[rowb + fA], qb = q[rowb + fA + 32];
        sq[iA][fA]      = qa * c - qb * sn;
        sq[iA][fA + 32] = qb * c + qa * sn;
        __syncthreads();

        float a = 0.f;
        #pragma unroll
        for (int d = 0; d < DH_; ++d) a = fmaf(sq[iA][d], som[d * NF_ + fA], a);
        float pq = fmaxf(a, 0.f);
        spq[iA][fA] = pq;
        float zp = pq * sps[fA];
        #pragma unroll
        for (int o = 16; o; o >>= 1) zp += __shfl_xor_sync(0xffffffffu, zp, o);
        if (fA == 0) sz[iA] = zp;
        __syncthreads();

        // outputs: thread (iA, d=fA) and (iA, d=fA+32)
        float o1 = 0.f, o2 = 0.f;
        #pragma unroll
        for (int f = 0; f < NF_; ++f) {
            float p = spq[iA][f];
            o1 = fmaf(p, skv[f][fA],      o1);
            o2 = fmaf(p, skv[f][fA + 32], o2);
        }
        float zi = 1.0f / (sz[iA] + 1e-6f);
        o1 *= zi; o2 *= zi;
        __half hi, lo;
        split_f16(o1, hi, lo);
        ahi[rowb + fA]      = hi; alo[rowb + fA]      = lo;
        split_f16(o2, hi, lo);
        ahi[rowb + fA + 32] = hi; alo[rowb + fA + 32] = lo;

        float cn = c * c8 - sn * s8;
        sn = sn * c8 + c * s8;
        c = cn;
        __syncthreads();
    }
}

// ------- residual + LayerNorm: h kept ONLY as exact fp16 pair -------
__global__ void addln_kernel(__half* __restrict__ hhi, __half* __restrict__ hlo,
                             const float* __restrict__ r,
                             const float* __restrict__ gam, const float* __restrict__ bet)
{
    const int row = blockIdx.x;
    const int tid = threadIdx.x;   // 256
    const size_t base = (size_t)row * D_;

    float x0 = __half2float(hhi[base + tid])       + __half2float(hlo[base + tid])       + r[base + tid];
    float x1 = __half2float(hhi[base + tid + 256]) + __half2float(hlo[base + tid + 256]) + r[base + tid + 256];
    float x2 = __half2float(hhi[base + tid + 512]) + __half2float(hlo[base + tid + 512]) + r[base + tid + 512];

    __shared__ float red[8];
    float s = x0 + x1 + x2;
    #pragma unroll
    for (int o = 16; o; o >>= 1) s += __shfl_xor_sync(0xffffffffu, s, o);
    if ((tid & 31) == 0) red[tid >> 5] = s;
    __syncthreads();
    float tot = red[0] + red[1] + red[2] + red[3] + red[4] + red[5] + red[6] + red[7];
    float mean = tot * (1.0f / 768.0f);

    float d0 = x0 - mean, d1 = x1 - mean, d2 = x2 - mean;
    float s2 = d0 * d0 + d1 * d1 + d2 * d2;
    #pragma unroll
    for (int o = 16; o; o >>= 1) s2 += __shfl_xor_sync(0xffffffffu, s2, o);
    __syncthreads();
    if ((tid & 31) == 0) red[tid >> 5] = s2;
    __syncthreads();
    float var = (red[0] + red[1] + red[2] + red[3] + red[4] + red[5] + red[6] + red[7]) * (1.0f / 768.0f);
    float inv = rsqrtf(var + 1e-5f);

    float y0 = d0 * inv * gam[tid]       + bet[tid];
    float y1 = d1 * inv * gam[tid + 256] + bet[tid + 256];
    float y2 = d2 * inv * gam[tid + 512] + bet[tid + 512];
    __half hi, lo;
    split_f16(y0, hi, lo); hhi[base + tid]       = hi; hlo[base + tid]       = lo;
    split_f16(y1, hi, lo); hhi[base + tid + 256] = hi; hlo[base + tid + 256] = lo;
    split_f16(y2, hi, lo); hhi[base + tid + 512] = hi; hlo[base + tid + 512] = lo;
}

// ---------------- masked mean pool (reads fp16 pair) ----------------
__global__ void pool_kernel(const __half* __restrict__ hhi, const __half* __restrict__ hlo,
                            const float* __restrict__ mask, float* __restrict__ pool)
{
    const int b = blockIdx.x;
    const int c = blockIdx.y * 128 + threadIdx.x;   // grid.y = 6
    float acc = 0.f, dn = 0.f;
    for (int s = 0; s < S_; ++s) {
        float m = mask[b * S_ + s];
        dn += m;
        size_t i = ((size_t)(b * S_ + s)) * D_ + c;
        acc += (__half2float(hhi[i]) + __half2float(hlo[i])) * m;
    }
    dn = fmaxf(dn, 1e-9f);
    pool[(size_t)b * D_ + c] = acc / dn;
}

// ---------------- final: out = relu(pool @ Wl + bl) ----------------
__global__ void final_kernel(const float* __restrict__ pool, const float* __restrict__ Wl,
                             const float* __restrict__ bl, float* __restrict__ out)
{
    const int b = blockIdx.x;
    const int o = threadIdx.x;   // 512
    __shared__ float sp[D_];
    for (int i = o; i < D_; i += 512) sp[i] = pool[(size_t)b * D_ + i];
    __syncthreads();
    float acc = bl[o];
    #pragma unroll 8
    for (int k = 0; k < D_; ++k)
        acc = fmaf(sp[k], Wl[(size_t)k * OUT_ + o], acc);
    out[(size_t)b * OUT_ + o] = fmaxf(acc, 0.f);
}

// ---------------- host ----------------
extern "C" void kernel_launch(void* const* d_in, const int* in_sizes, int n_in,
                              void* d_out, int out_size)
{
    const int*   x     = (const int*)  d_in[0];
    const float* mask  = (const float*)d_in[1];
    const float* tok   = (const float*)d_in[2];
    const float* Wq    = (const float*)d_in[3];
    const float* bq    = (const float*)d_in[4];
    const float* Wk    = (const float*)d_in[5];
    const float* bk    = (const float*)d_in[6];
    const float* Wv    = (const float*)d_in[7];
    const float* bv    = (const float*)d_in[8];
    const float* Wo    = (const float*)d_in[9];
    const float* bo    = (const float*)d_in[10];
    const float* omega = (const float*)d_in[11];
    const float* ln1s  = (const float*)d_in[12];
    const float* ln1b  = (const float*)d_in[13];
    const float* W1    = (const float*)d_in[14];
    const float* b1    = (const float*)d_in[15];
    const float* W2    = (const float*)d_in[16];
    const float* b2    = (const float*)d_in[17];
    const float* ln2s  = (const float*)d_in[18];
    const float* ln2b  = (const float*)d_in[19];
    const float* Wl    = (const float*)d_in[20];
    const float* bl    = (const float*)d_in[21];

    float *qkv, *t1, *kv, *ps, *pool;
    __half *wh, *hhi, *hlo, *t1hi, *t1lo, *ffhi, *fflo;
    cudaGetSymbolAddress((void**)&qkv, g_qkv);
    cudaGetSymbolAddress((void**)&t1,  g_t1);
    cudaGetSymbolAddress((void**)&kv,  g_kv);
    cudaGetSymbolAddress((void**)&ps,  g_ps);
    cudaGetSymbolAddress((void**)&pool, g_pool);
    cudaGetSymbolAddress((void**)&wh,   g_wh);
    cudaGetSymbolAddress((void**)&hhi,  g_hhi);
    cudaGetSymbolAddress((void**)&hlo,  g_hlo);
    cudaGetSymbolAddress((void**)&t1hi, g_t1hi);
    cudaGetSymbolAddress((void**)&t1lo, g_t1lo);
    cudaGetSymbolAddress((void**)&ffhi, g_ffhi);
    cudaGetSymbolAddress((void**)&fflo, g_fflo);

    cudaFuncSetAttribute(mmagemm_kernel<0,0>, cudaFuncAttributeMaxDynamicSharedMemorySize, GB_SMEM);
    cudaFuncSetAttribute(mmagemm_kernel<1,1>, cudaFuncAttributeMaxDynamicSharedMemorySize, GB_SMEM);

    const size_t MATSZ = (size_t)NL_ * D_ * D_;
    const size_t LSZ   = (size_t)D_ * D_;

    dim3 gT(D_ / 32, D_ / 32, NL_);
    dim3 bT(32, 8);
    dim3 gQKV(18, BS_ / 128);
    dim3 gGemm(6, BS_ / 128);

    embed_kernel<<<(BSD_ + 255) / 256, 256>>>(x, tok, hhi, hlo);
    wsplit_kernel<<<gT, bT>>>(Wq, wh + 0 * MATSZ);
    wsplit_kernel<<<gT, bT>>>(Wk, wh + 1 * MATSZ);
    wsplit_kernel<<<gT, bT>>>(Wv, wh + 2 * MATSZ);
    wsplit_kernel<<<gT, bT>>>(Wo, wh + 3 * MATSZ);
    wsplit_kernel<<<gT, bT>>>(W1, wh + 4 * MATSZ);
    wsplit_kernel<<<gT, bT>>>(W2, wh + 5 * MATSZ);

    for (int l = 0; l < NL_; ++l) {
        const float* lbq = bq + (size_t)l * D_;
        const float* lbk = bk + (size_t)l * D_;
        const float* lbv = bv + (size_t)l * D_;
        const float* lbo = bo + (size_t)l * D_;
        const float* lb1 = b1 + (size_t)l * D_;
        const float* lb2 = b2 + (size_t)l * D_;
        const float* lom = omega + (size_t)l * DH_ * NF_;
        const float* l1s = ln1s + (size_t)l * D_;
        const float* l1b = ln1b + (size_t)l * D_;
        const float* l2s = ln2s + (size_t)l * D_;
        const float* l2b = ln2b + (size_t)l * D_;

        mmagemm_kernel<0,0><<<gQKV, 256, GB_SMEM>>>(hhi, hlo, wh + 0 * MATSZ + l * LSZ, MATSZ,
                                                    lbq, lbk, lbv, qkv, nullptr, nullptr, (size_t)BSD_);

        fk_kernel<<<B_ * H_, 256>>>(qkv + BSD_, qkv + 2 * (size_t)BSD_, lom, mask, kv, ps);
        fa_kernel<<<B_ * H_, 256>>>(qkv, kv, ps, lom, t1hi, t1lo);

        // O projection -> qkv buffer (free after fa)
        mmagemm_kernel<0,0><<<gGemm, 256, GB_SMEM>>>(t1hi, t1lo, wh + 3 * MATSZ + l * LSZ, 0,
                                                     lbo, lbo, lbo, qkv, nullptr, nullptr, 0);
        addln_kernel<<<BS_, 256>>>(hhi, hlo, qkv, l1s, l1b);

        mmagemm_kernel<1,1><<<gGemm, 256, GB_SMEM>>>(hhi, hlo, wh + 4 * MATSZ + l * LSZ, 0,
                                                     lb1, lb1, lb1, nullptr, ffhi, fflo, 0);
        mmagemm_kernel<0,0><<<gGemm, 256, GB_SMEM>>>(ffhi, fflo, wh + 5 * MATSZ + l * LSZ, 0,
                                                     lb2, lb2, lb2, t1, nullptr, nullptr, 0);
        addln_kernel<<<BS_, 256>>>(hhi, hlo, t1, l2s, l2b);
    }

    dim3 gPool(B_, D_ / 128);
    pool_kernel<<<gPool, 128>>>(hhi, hlo, mask, pool);
    final_kernel<<<B_, 512>>>(pool, Wl, bl, (float*)d_out);
}

// round 16
// speedup vs baseline: 2.5644x; 1.0024x over previous
#include <cuda_runtime.h>
#include <cuda_fp16.h>
#include <math.h>
#include <stdint.h>

#define B_  64
#define S_  512
#define D_  768
#define H_  12
#define DH_ 64
#define NF_ 32
#define NL_ 12
#define OUT_ 512

static const int BS_  = B_ * S_;        // 32768
static const int BSD_ = B_ * S_ * D_;   // 25165824

// ---------------- scratch (allowed: __device__ globals) ----------------
__device__ float g_qkv[3 * B_*S_*D_];   // fused Q,K,V outputs (fp32)
__device__ float g_t1 [B_*S_*D_];       // FF2 out (residual)
__device__ float g_kv[B_*H_*NF_*DH_];
__device__ float g_ps[B_*H_*NF_];
__device__ float g_pool[B_*D_];
// fp16 exact-pair activations (GEMM A operands); h lives ONLY as this pair
__device__ __half g_hhi [B_*S_*D_];
__device__ __half g_hlo [B_*S_*D_];
__device__ __half g_t1hi[B_*S_*D_];
__device__ __half g_t1lo[B_*S_*D_];
__device__ __half g_ffhi[B_*S_*D_];
__device__ __half g_fflo[B_*S_*D_];
// fp16 transposed weights: [mat 0..5][layer][n][k]
__device__ __half g_wh[6 * NL_ * D_ * D_];

// ==================== PTX helpers ====================
__device__ __forceinline__ uint32_t smem_u32(const void* p){
    uint32_t a;
    asm("{ .reg .u64 t; cvta.to.shared.u64 t, %1; cvt.u32.u64 %0, t; }" : "=r"(a) : "l"(p));
    return a;
}

#define LDSMX4(r, addr) \
    asm volatile("ldmatrix.sync.aligned.m8n8.x4.shared.b16 {%0,%1,%2,%3}, [%4];" \
        : "=r"((r)[0]), "=r"((r)[1]), "=r"((r)[2]), "=r"((r)[3]) : "r"(addr))

#define MMA16816F16(d, a, b) \
    asm volatile("mma.sync.aligned.m16n8k16.row.col.f32.f16.f16.f32 " \
        "{%0,%1,%2,%3}, {%4,%5,%6,%7}, {%8,%9}, {%0,%1,%2,%3};" \
        : "+f"((d)[0]), "+f"((d)[1]), "+f"((d)[2]), "+f"((d)[3]) \
        : "r"((a)[0]), "r"((a)[1]), "r"((a)[2]), "r"((a)[3]), \
          "r"((b)[0]), "r"((b)[1]))

#define CP_ASYNC16(dst, src) \
    asm volatile("cp.async.cg.shared.global [%0], [%1], 16;" :: "r"(dst), "l"(src))
#define CP_COMMIT() asm volatile("cp.async.commit_group;" ::: "memory")
#define CP_WAIT0()  asm volatile("cp.async.wait_group 0;" ::: "memory")
#define CP_WAIT1()  asm volatile("cp.async.wait_group 1;" ::: "memory")

__device__ __forceinline__ void split_f16(float v, __half& hi, __half& lo){
    hi = __float2half_rn(v);
    lo = __float2half_rn(v - __half2float(hi));
}

// ---------------- embedding: exact fp16 pair only ----------------
__global__ void embed_kernel(const int* __restrict__ x, const float* __restrict__ emb,
                             __half* __restrict__ hhi, __half* __restrict__ hlo)
{
    long i = (long)blockIdx.x * blockDim.x + threadIdx.x;
    if (i < (long)BSD_) {
        int bs = (int)(i / D_);
        int d  = (int)(i % D_);
        float v = emb[(long)x[bs] * D_ + d];
        __half hi, lo;
        split_f16(v, hi, lo);
        hhi[i] = hi; hlo[i] = lo;
    }
}

// ---------------- weight transpose + fp16 convert ----------------
__global__ void wsplit_kernel(const float* __restrict__ W, __half* __restrict__ wh)
{
    __shared__ float s[32][33];
    const int l  = blockIdx.z;
    const int k0 = blockIdx.x * 32;
    const int n0 = blockIdx.y * 32;
    const int tx = threadIdx.x;       // 0..31
    const int ty = threadIdx.y;       // 0..7
    const float* Wl = W + (size_t)l * D_ * D_;
    #pragma unroll
    for (int i = 0; i < 4; i++)
        s[ty + 8 * i][tx] = Wl[(size_t)(k0 + ty + 8 * i) * D_ + n0 + tx];
    __syncthreads();
    #pragma unroll
    for (int i = 0; i < 4; i++) {
        int n = n0 + ty + 8 * i;
        int k = k0 + tx;
        wh[((size_t)l * D_ + n) * D_ + k] = __float2half_rn(s[tx][ty + 8 * i]);
    }
}

// ==================== mma.sync fp16 2-term GEMM (3-stage, 1 sync/chunk) ====================
#define GB_BUF    30720
#define GB_AHI    0
#define GB_ALO    10240
#define GB_BH     20480
#define GB_SMEM   (3 * GB_BUF)   // 92160

template<int ACT, int OSPLIT>
__global__ void __launch_bounds__(256, 2)
mmagemm_kernel(const __half* __restrict__ Ahi,
               const __half* __restrict__ Alo,
               const __half* __restrict__ Wh, size_t wstride,
               const float* __restrict__ bias0, const float* __restrict__ bias1,
               const float* __restrict__ bias2,
               float* __restrict__ C,
               __half* __restrict__ Chi, __half* __restrict__ Clo,
               size_t ostride)
{
    extern __shared__ char dsm[];
    const uint32_t sb32 = smem_u32(dsm);

    const int tid  = threadIdx.x;
    const int wid  = tid >> 5, lane = tid & 31;
    const int mat  = blockIdx.x / 6;
    const int bx   = blockIdx.x % 6;   // N tile
    const int by   = blockIdx.y;       // M tile
    const int wm   = wid >> 1;         // 0..3
    const int wn   = wid & 1;          // 0..1

    const __half* Wm = Wh + (size_t)mat * wstride;
    const float* bias = (mat == 0) ? bias0 : ((mat == 1) ? bias1 : bias2);

    const int r  = tid >> 1;
    const int hf = tid & 1;
    const uint32_t stOff = (uint32_t)r * 80u + (uint32_t)hf * 32u;
    const char* aH = (const char*)(Ahi + ((size_t)(by * 128) + r) * 768 + hf * 16);
    const char* aL = (const char*)(Alo + ((size_t)(by * 128) + r) * 768 + hf * 16);
    const char* bH = (const char*)(Wm  + ((size_t)(bx * 128) + r) * 768 + hf * 16);

    const uint32_t offA = (uint32_t)(wm * 32 + (lane & 15)) * 80u + ((lane >> 4) & 1) * 16u;
    const uint32_t offB = (uint32_t)(wn * 64 + (lane & 7) + ((lane >> 4) & 1) * 8) * 80u
                        + ((lane >> 3) & 1) * 16u;

    float acc[2][8][4];
    #pragma unroll
    for (int mt = 0; mt < 2; mt++)
        #pragma unroll
        for (int nt = 0; nt < 8; nt++)
            #pragma unroll
            for (int j = 0; j < 4; j++) acc[mt][nt][j] = 0.f;

    auto stage = [&](int kt, int buf) {
        uint32_t d = sb32 + (uint32_t)buf * GB_BUF + stOff;
        long o = (long)kt * 64;
        CP_ASYNC16(d + GB_AHI,      aH + o);
        CP_ASYNC16(d + GB_AHI + 16, aH + o + 16);
        CP_ASYNC16(d + GB_ALO,      aL + o);
        CP_ASYNC16(d + GB_ALO + 16, aL + o + 16);
        CP_ASYNC16(d + GB_BH,       bH + o);
        CP_ASYNC16(d + GB_BH + 16,  bH + o + 16);
        CP_COMMIT();
    };

    // 3-stage prologue
    stage(0, 0);
    stage(1, 1);

    int buf = 0;
    #pragma unroll 1
    for (int t = 0; t < 24; ++t) {
        if (t == 23) { CP_WAIT0(); } else { CP_WAIT1(); }   // chunk t landed
        __syncthreads();   // also: everyone done reading buffer being restaged below

        if (t + 2 < 24) {
            int nb = buf + 2; if (nb >= 3) nb -= 3;
            stage(t + 2, nb);
        }

        const uint32_t bufb = sb32 + (uint32_t)buf * GB_BUF;
        #pragma unroll
        for (int ks = 0; ks < 2; ks++) {
            uint32_t ah[2][4], al[2][4];
            #pragma unroll
            for (int mt = 0; mt < 2; mt++) {
                uint32_t ad = bufb + offA + (uint32_t)mt * (16u * 80u) + (uint32_t)ks * 32u;
                LDSMX4(ah[mt], ad + GB_AHI);
                LDSMX4(al[mt], ad + GB_ALO);
            }
            #pragma unroll
            for (int half = 0; half < 2; half++) {
                uint32_t bh[4][2];
                #pragma unroll
                for (int np = 0; np < 2; np++) {
                    uint32_t bd = bufb + offB + (uint32_t)(half * 2 + np) * (16u * 80u)
                                + (uint32_t)ks * 32u;
                    uint32_t th[4];
                    LDSMX4(th, bd + GB_BH);
                    bh[2*np][0]   = th[0]; bh[2*np][1]   = th[1];
                    bh[2*np+1][0] = th[2]; bh[2*np+1][1] = th[3];
                }
                #pragma unroll
                for (int mt = 0; mt < 2; mt++)
                    #pragma unroll
                    for (int j = 0; j < 4; j++) {
                        int nt = half * 4 + j;
                        MMA16816F16(acc[mt][nt], ah[mt], bh[j]);
                        MMA16816F16(acc[mt][nt], al[mt], bh[j]);
                    }
            }
        }
        if (++buf == 3) buf = 0;
    }

    // ---- epilogue ----
    const int erow = lane >> 2;
    const int ecol = (lane & 3) * 2;
    #pragma unroll
    for (int mt = 0; mt < 2; mt++) {
        #pragma unroll
        for (int nt = 0; nt < 8; nt++) {
            int grow = by * 128 + wm * 32 + mt * 16 + erow;
            int gcol = bx * 128 + wn * 64 + nt * 8 + ecol;
            float b0 = __ldg(bias + gcol), b1 = __ldg(bias + gcol + 1);
            float v0 = acc[mt][nt][0] + b0;
            float v1 = acc[mt][nt][1] + b1;
            float v2 = acc[mt][nt][2] + b0;
            float v3 = acc[mt][nt][3] + b1;
            if (ACT == 1) {
                v0 = 0.5f * v0 * (1.0f + erff(v0 * 0.70710678118654752f));
                v1 = 0.5f * v1 * (1.0f + erff(v1 * 0.70710678118654752f));
                v2 = 0.5f * v2 * (1.0f + erff(v2 * 0.70710678118654752f));
                v3 = 0.5f * v3 * (1.0f + erff(v3 * 0.70710678118654752f));
            }
            if (OSPLIT == 0) {
                float* Cb = C + (size_t)mat * ostride;
                *(float2*)(Cb + (size_t)grow * 768 + gcol)       = make_float2(v0, v1);
                *(float2*)(Cb + (size_t)(grow + 8) * 768 + gcol) = make_float2(v2, v3);
            } else {
                __half h0, l0, h1, l1;
                split_f16(v0, h0, l0); split_f16(v1, h1, l1);
                __half2 hp = __halves2half2(h0, h1);
                __half2 lp = __halves2half2(l0, l1);
                *(uint32_t*)(Chi + (size_t)grow * 768 + gcol) = *(uint32_t*)&hp;
                *(uint32_t*)(Clo + (size_t)grow * 768 + gcol) = *(uint32_t*)&lp;
                split_f16(v2, h0, l0); split_f16(v3, h1, l1);
                hp = __halves2half2(h0, h1);
                lp = __halves2half2(l0, l1);
                *(uint32_t*)(Chi + (size_t)(grow + 8) * 768 + gcol) = *(uint32_t*)&hp;
                *(uint32_t*)(Clo + (size_t)(grow + 8) * 768 + gcol) = *(uint32_t*)&lp;
            }
        }
    }
}

// ================= FK: rotary-k + feature map + kv/ps (per (b,h)) =================
__global__ void __launch_bounds__(256)
fk_kernel(const float* __restrict__ k, const float* __restrict__ v,
          const float* __restrict__ om, const float* __restrict__ mask,
          float* __restrict__ kvout, float* __restrict__ psout)
{
    const int b = blockIdx.x / H_;
    const int h = blockIdx.x % H_;
    const int tid = threadIdx.x;      // 256

    __shared__ float som[DH_ * NF_];  // [d][f]
    __shared__ float sk [8][DH_];
    __shared__ float sv [8][DH_];
    __shared__ float spk[8][NF_];

    for (int i = tid; i < DH_ * NF_; i += 256) som[i] = om[i];

    const int iA = tid >> 5, fA = tid & 31;
    const int fB = tid >> 3, dB = (tid & 7) * 8;

    const float invf = expf(-(float)fA * 0.28782313662425572f); // ln(1e4)/32
    float c, sn, c8, s8;
    sincosf((float)iA * invf, &sn, &c);
    sincosf(8.0f * invf, &s8, &c8);

    float acc[8];
    #pragma unroll
    for (int i = 0; i < 8; i++) acc[i] = 0.f;
    float psum = 0.f;

    __syncthreads();

    #pragma unroll 1
    for (int s0 = 0; s0 < S_; s0 += 8) {
        const int s = s0 + iA;
        const size_t rowb = ((size_t)(b * S_ + s)) * D_ + h * DH_;
        float ka = k[rowb + fA], kb = k[rowb + fA + 32];
        sk[iA][fA]      = ka * c - kb * sn;
        sk[iA][fA + 32] = kb * c + ka * sn;
        ((float2*)sv[iA])[fA] = ((const float2*)(v + rowb))[fA];
        __syncthreads();

        float a = 0.f;
        #pragma unroll
        for (int d = 0; d < DH_; ++d) a = fmaf(sk[iA][d], som[d * NF_ + fA], a);
        spk[iA][fA] = fmaxf(a, 0.f) * mask[b * S_ + s];
        __syncthreads();

        #pragma unroll
        for (int i = 0; i < 8; i++) {
            float p = spk[i][fB];
            psum += p;
            #pragma unroll
            for (int j = 0; j < 8; j++)
                acc[j] = fmaf(p, sv[i][dB + j], acc[j]);
        }
        float cn = c * c8 - sn * s8;
        sn = sn * c8 + c * s8;
        c = cn;
        __syncthreads();
    }

    #pragma unroll
    for (int j = 0; j < 8; j++)
        kvout[(((size_t)(b * H_ + h)) * NF_ + fB) * DH_ + dB + j] = acc[j];
    if ((tid & 7) == 0) psout[((size_t)(b * H_ + h)) * NF_ + fB] = psum;
}

// ============ FA: rotary-q + feature map + z + pq@kv -> fp16 pair ============
__global__ void __launch_bounds__(256)
fa_kernel(const float* __restrict__ q, const float* __restrict__ kvin,
          const float* __restrict__ psin, const float* __restrict__ om,
          __half* __restrict__ ahi, __half* __restrict__ alo)
{
    const int b = blockIdx.x / H_;
    const int h = blockIdx.x % H_;
    const int tid = threadIdx.x;      // 256

    __shared__ float som[DH_ * NF_];
    __shared__ float skv[NF_][DH_];
    __shared__ float sps[NF_];
    __shared__ float sq [8][DH_];
    __shared__ float spq[8][NF_];
    __shared__ float sz [8];

    for (int i = tid; i < DH_ * NF_; i += 256) som[i] = om[i];
    for (int i = tid; i < NF_ * DH_; i += 256)
        ((float*)skv)[i] = kvin[((size_t)(b * H_ + h)) * NF_ * DH_ + i];
    if (tid < NF_) sps[tid] = psin[((size_t)(b * H_ + h)) * NF_ + tid];

    const int iA = tid >> 5, fA = tid & 31;

    const float invf = expf(-(float)fA * 0.28782313662425572f);
    float c, sn, c8, s8;
    sincosf((float)iA * invf, &sn, &c);
    sincosf(8.0f * invf, &s8, &c8);

    __syncthreads();

    #pragma unroll 1
    for (int s0 = 0; s0 < S_; s0 += 8) {
        const int s = s0 + iA;
        const size_t rowb = ((size_t)(b * S_ + s)) * D_ + h * DH_;
        float qa = q[rowb + fA], qb = q[rowb + fA + 32];
        sq[iA][fA]      = qa * c - qb * sn;
        sq[iA][fA + 32] = qb * c + qa * sn;
        __syncthreads();

        float a = 0.f;
        #pragma unroll
        for (int d = 0; d < DH_; ++d) a = fmaf(sq[iA][d], som[d * NF_ + fA], a);
        float pq = fmaxf(a, 0.f);
        spq[iA][fA] = pq;
        float zp = pq * sps[fA];
        #pragma unroll
        for (int o = 16; o; o >>= 1) zp += __shfl_xor_sync(0xffffffffu, zp, o);
        if (fA == 0) sz[iA] = zp;
        __syncthreads();

        float o1 = 0.f, o2 = 0.f;
        #pragma unroll
        for (int f = 0; f < NF_; ++f) {
            float p = spq[iA][f];
            o1 = fmaf(p, skv[f][fA],      o1);
            o2 = fmaf(p, skv[f][fA + 32], o2);
        }
        float zi = 1.0f / (sz[iA] + 1e-6f);
        o1 *= zi; o2 *= zi;
        __half hi, lo;
        split_f16(o1, hi, lo);
        ahi[rowb + fA]      = hi; alo[rowb + fA]      = lo;
        split_f16(o2, hi, lo);
        ahi[rowb + fA + 32] = hi; alo[rowb + fA + 32] = lo;

        float cn = c * c8 - sn * s8;
        sn = sn * c8 + c * s8;
        c = cn;
        __syncthreads();
    }
}

// ------- residual + LayerNorm: h kept ONLY as exact fp16 pair -------
__global__ void addln_kernel(__half* __restrict__ hhi, __half* __restrict__ hlo,
                             const float* __restrict__ r,
                             const float* __restrict__ gam, const float* __restrict__ bet)
{
    const int row = blockIdx.x;
    const int tid = threadIdx.x;   // 256
    const size_t base = (size_t)row * D_;

    float x0 = __half2float(hhi[base + tid])       + __half2float(hlo[base + tid])       + r[base + tid];
    float x1 = __half2float(hhi[base + tid + 256]) + __half2float(hlo[base + tid + 256]) + r[base + tid + 256];
    float x2 = __half2float(hhi[base + tid + 512]) + __half2float(hlo[base + tid + 512]) + r[base + tid + 512];

    __shared__ float red[8];
    float s = x0 + x1 + x2;
    #pragma unroll
    for (int o = 16; o; o >>= 1) s += __shfl_xor_sync(0xffffffffu, s, o);
    if ((tid & 31) == 0) red[tid >> 5] = s;
    __syncthreads();
    float tot = red[0] + red[1] + red[2] + red[3] + red[4] + red[5] + red[6] + red[7];
    float mean = tot * (1.0f / 768.0f);

    float d0 = x0 - mean, d1 = x1 - mean, d2 = x2 - mean;
    float s2 = d0 * d0 + d1 * d1 + d2 * d2;
    #pragma unroll
    for (int o = 16; o; o >>= 1) s2 += __shfl_xor_sync(0xffffffffu, s2, o);
    __syncthreads();
    if ((tid & 31) == 0) red[tid >> 5] = s2;
    __syncthreads();
    float var = (red[0] + red[1] + red[2] + red[3] + red[4] + red[5] + red[6] + red[7]) * (1.0f / 768.0f);
    float inv = rsqrtf(var + 1e-5f);

    float y0 = d0 * inv * gam[tid]       + bet[tid];
    float y1 = d1 * inv * gam[tid + 256] + bet[tid + 256];
    float y2 = d2 * inv * gam[tid + 512] + bet[tid + 512];
    __half hi, lo;
    split_f16(y0, hi, lo); hhi[base + tid]       = hi; hlo[base + tid]       = lo;
    split_f16(y1, hi, lo); hhi[base + tid + 256] = hi; hlo[base + tid + 256] = lo;
    split_f16(y2, hi, lo); hhi[base + tid + 512] = hi; hlo[base + tid + 512] = lo;
}

// ---------------- masked mean pool (reads fp16 pair) ----------------
__global__ void pool_kernel(const __half* __restrict__ hhi, const __half* __restrict__ hlo,
                            const float* __restrict__ mask, float* __restrict__ pool)
{
    const int b = blockIdx.x;
    const int c = blockIdx.y * 128 + threadIdx.x;   // grid.y = 6
    float acc = 0.f, dn = 0.f;
    for (int s = 0; s < S_; ++s) {
        float m = mask[b * S_ + s];
        dn += m;
        size_t i = ((size_t)(b * S_ + s)) * D_ + c;
        acc += (__half2float(hhi[i]) + __half2float(hlo[i])) * m;
    }
    dn = fmaxf(dn, 1e-9f);
    pool[(size_t)b * D_ + c] = acc / dn;
}

// ---------------- final: out = relu(pool @ Wl + bl) ----------------
__global__ void final_kernel(const float* __restrict__ pool, const float* __restrict__ Wl,
                             const float* __restrict__ bl, float* __restrict__ out)
{
    const int b = blockIdx.x;
    const int o = threadIdx.x;   // 512
    __shared__ float sp[D_];
    for (int i = o; i < D_; i += 512) sp[i] = pool[(size_t)b * D_ + i];
    __syncthreads();
    float acc = bl[o];
    #pragma unroll 8
    for (int k = 0; k < D_; ++k)
        acc = fmaf(sp[k], Wl[(size_t)k * OUT_ + o], acc);
    out[(size_t)b * OUT_ + o] = fmaxf(acc, 0.f);
}

// ---------------- host ----------------
extern "C" void kernel_launch(void* const* d_in, const int* in_sizes, int n_in,
                              void* d_out, int out_size)
{
    const int*   x     = (const int*)  d_in[0];
    const float* mask  = (const float*)d_in[1];
    const float* tok   = (const float*)d_in[2];
    const float* Wq    = (const float*)d_in[3];
    const float* bq    = (const float*)d_in[4];
    const float* Wk    = (const float*)d_in[5];
    const float* bk    = (const float*)d_in[6];
    const float* Wv    = (const float*)d_in[7];
    const float* bv    = (const float*)d_in[8];
    const float* Wo    = (const float*)d_in[9];
    const float* bo    = (const float*)d_in[10];
    const float* omega = (const float*)d_in[11];
    const float* ln1s  = (const float*)d_in[12];
    const float* ln1b  = (const float*)d_in[13];
    const float* W1    = (const float*)d_in[14];
    const float* b1    = (const float*)d_in[15];
    const float* W2    = (const float*)d_in[16];
    const float* b2    = (const float*)d_in[17];
    const float* ln2s  = (const float*)d_in[18];
    const float* ln2b  = (const float*)d_in[19];
    const float* Wl    = (const float*)d_in[20];
    const float* bl    = (const float*)d_in[21];

    float *qkv, *t1, *kv, *ps, *pool;
    __half *wh, *hhi, *hlo, *t1hi, *t1lo, *ffhi, *fflo;
    cudaGetSymbolAddress((void**)&qkv, g_qkv);
    cudaGetSymbolAddress((void**)&t1,  g_t1);
    cudaGetSymbolAddress((void**)&kv,  g_kv);
    cudaGetSymbolAddress((void**)&ps,  g_ps);
    cudaGetSymbolAddress((void**)&pool, g_pool);
    cudaGetSymbolAddress((void**)&wh,   g_wh);
    cudaGetSymbolAddress((void**)&hhi,  g_hhi);
    cudaGetSymbolAddress((void**)&hlo,  g_hlo);
    cudaGetSymbolAddress((void**)&t1hi, g_t1hi);
    cudaGetSymbolAddress((void**)&t1lo, g_t1lo);
    cudaGetSymbolAddress((void**)&ffhi, g_ffhi);
    cudaGetSymbolAddress((void**)&fflo, g_fflo);

    cudaFuncSetAttribute(mmagemm_kernel<0,0>, cudaFuncAttributeMaxDynamicSharedMemorySize, GB_SMEM);
    cudaFuncSetAttribute(mmagemm_kernel<1,1>, cudaFuncAttributeMaxDynamicSharedMemorySize, GB_SMEM);

    const size_t MATSZ = (size_t)NL_ * D_ * D_;
    const size_t LSZ   = (size_t)D_ * D_;

    dim3 gT(D_ / 32, D_ / 32, NL_);
    dim3 bT(32, 8);
    dim3 gQKV(18, BS_ / 128);
    dim3 gGemm(6, BS_ / 128);

    // Order arranged so ncu capture slot 5 (1 harness launch + skip) = layer-0 QKV GEMM.
    embed_kernel<<<(BSD_ + 255) / 256, 256>>>(x, tok, hhi, hlo);          // our 0
    wsplit_kernel<<<gT, bT>>>(Wq, wh + 0 * MATSZ);                         // 1
    wsplit_kernel<<<gT, bT>>>(Wk, wh + 1 * MATSZ);                         // 2
    wsplit_kernel<<<gT, bT>>>(Wv, wh + 2 * MATSZ);                         // 3
    mmagemm_kernel<0,0><<<gQKV, 256, GB_SMEM>>>(hhi, hlo, wh + 0 * MATSZ + 0 * LSZ, MATSZ,
                                                bq, bk, bv, qkv, nullptr, nullptr, (size_t)BSD_); // 4
    wsplit_kernel<<<gT, bT>>>(Wo, wh + 3 * MATSZ);                         // 5
    wsplit_kernel<<<gT, bT>>>(W1, wh + 4 * MATSZ);                         // 6
    wsplit_kernel<<<gT, bT>>>(W2, wh + 5 * MATSZ);                         // 7

    for (int l = 0; l < NL_; ++l) {
        const float* lbq = bq + (size_t)l * D_;
        const float* lbk = bk + (size_t)l * D_;
        const float* lbv = bv + (size_t)l * D_;
        const float* lbo = bo + (size_t)l * D_;
        const float* lb1 = b1 + (size_t)l * D_;
        const float* lb2 = b2 + (size_t)l * D_;
        const float* lom = omega + (size_t)l * DH_ * NF_;
        const float* l1s = ln1s + (size_t)l * D_;
        const float* l1b = ln1b + (size_t)l * D_;
        const float* l2s = ln2s + (size_t)l * D_;
        const float* l2b = ln2b + (size_t)l * D_;

        if (l > 0) {
            mmagemm_kernel<0,0><<<gQKV, 256, GB_SMEM>>>(hhi, hlo, wh + 0 * MATSZ + l * LSZ, MATSZ,
                                                        lbq, lbk, lbv, qkv, nullptr, nullptr, (size_t)BSD_);
        }

        fk_kernel<<<B_ * H_, 256>>>(qkv + BSD_, qkv + 2 * (size_t)BSD_, lom, mask, kv, ps);
        fa_kernel<<<B_ * H_, 256>>>(qkv, kv, ps, lom, t1hi, t1lo);

        mmagemm_kernel<0,0><<<gGemm, 256, GB_SMEM>>>(t1hi, t1lo, wh + 3 * MATSZ + l * LSZ, 0,
                                                     lbo, lbo, lbo, qkv, nullptr, nullptr, 0);
        addln_kernel<<<BS_, 256>>>(hhi, hlo, qkv, l1s, l1b);

        mmagemm_kernel<1,1><<<gGemm, 256, GB_SMEM>>>(hhi, hlo, wh + 4 * MATSZ + l * LSZ, 0,
                                                     lb1, lb1, lb1, nullptr, ffhi, fflo, 0);
        mmagemm_kernel<0,0><<<gGemm, 256, GB_SMEM>>>(ffhi, fflo, wh + 5 * MATSZ + l * LSZ, 0,
                                                     lb2, lb2, lb2, t1, nullptr, nullptr, 0);
        addln_kernel<<<BS_, 256>>>(hhi, hlo, t1, l2s, l2b);
    }

    dim3 gPool(B_, D_ / 128);
    pool_kernel<<<gPool, 128>>>(hhi, hlo, mask, pool);
    final_kernel<<<B_, 512>>>(pool, Wl, bl, (float*)d_out);
}

// round 17
// speedup vs baseline: 3.0303x; 1.1817x over previous
#include <cuda_runtime.h>
#include <cuda_fp16.h>
#include <math.h>
#include <stdint.h>

#define B_  64
#define S_  512
#define D_  768
#define H_  12
#define DH_ 64
#define NF_ 32
#define NL_ 12
#define OUT_ 512

static const int BS_  = B_ * S_;        // 32768
static const int BSD_ = B_ * S_ * D_;   // 25165824

// ---------------- scratch (allowed: __device__ globals) ----------------
__device__ float g_qkv[3 * B_*S_*D_];   // fused Q,K,V outputs (fp32)
__device__ float g_t1 [B_*S_*D_];       // FF2 out (residual)
__device__ float g_kv[B_*H_*NF_*DH_];
__device__ float g_ps[B_*H_*NF_];
__device__ float g_pool[B_*D_];
// fp16 exact-pair activations (GEMM A operands); h lives ONLY as this pair
__device__ __half g_hhi [B_*S_*D_];
__device__ __half g_hlo [B_*S_*D_];
__device__ __half g_t1hi[B_*S_*D_];
__device__ __half g_t1lo[B_*S_*D_];
__device__ __half g_ffhi[B_*S_*D_];
__device__ __half g_fflo[B_*S_*D_];
// fp16 transposed weights: [mat 0..5][layer][n][k]
__device__ __half g_wh[6 * NL_ * D_ * D_];

// ==================== PTX helpers ====================
__device__ __forceinline__ uint32_t smem_u32(const void* p){
    uint32_t a;
    asm("{ .reg .u64 t; cvta.to.shared.u64 t, %1; cvt.u32.u64 %0, t; }" : "=r"(a) : "l"(p));
    return a;
}

#define LDSMX4(r, addr) \
    asm volatile("ldmatrix.sync.aligned.m8n8.x4.shared.b16 {%0,%1,%2,%3}, [%4];" \
        : "=r"((r)[0]), "=r"((r)[1]), "=r"((r)[2]), "=r"((r)[3]) : "r"(addr))

#define MMA16816F16(d, a, b) \
    asm volatile("mma.sync.aligned.m16n8k16.row.col.f32.f16.f16.f32 " \
        "{%0,%1,%2,%3}, {%4,%5,%6,%7}, {%8,%9}, {%0,%1,%2,%3};" \
        : "+f"((d)[0]), "+f"((d)[1]), "+f"((d)[2]), "+f"((d)[3]) \
        : "r"((a)[0]), "r"((a)[1]), "r"((a)[2]), "r"((a)[3]), \
          "r"((b)[0]), "r"((b)[1]))

#define CP_ASYNC16(dst, src) \
    asm volatile("cp.async.cg.shared.global [%0], [%1], 16;" :: "r"(dst), "l"(src))
#define CP_COMMIT() asm volatile("cp.async.commit_group;" ::: "memory")
#define CP_WAIT0()  asm volatile("cp.async.wait_group 0;" ::: "memory")
#define CP_WAIT1()  asm volatile("cp.async.wait_group 1;" ::: "memory")

__device__ __forceinline__ void split_f16(float v, __half& hi, __half& lo){
    hi = __float2half_rn(v);
    lo = __float2half_rn(v - __half2float(hi));
}

// ---------------- embedding: exact fp16 pair only ----------------
__global__ void embed_kernel(const int* __restrict__ x, const float* __restrict__ emb,
                             __half* __restrict__ hhi, __half* __restrict__ hlo)
{
    long i = (long)blockIdx.x * blockDim.x + threadIdx.x;
    if (i < (long)BSD_) {
        int bs = (int)(i / D_);
        int d  = (int)(i % D_);
        float v = emb[(long)x[bs] * D_ + d];
        __half hi, lo;
        split_f16(v, hi, lo);
        hhi[i] = hi; hlo[i] = lo;
    }
}

// ---------------- weight transpose + fp16 convert ----------------
__global__ void wsplit_kernel(const float* __restrict__ W, __half* __restrict__ wh)
{
    __shared__ float s[32][33];
    const int l  = blockIdx.z;
    const int k0 = blockIdx.x * 32;
    const int n0 = blockIdx.y * 32;
    const int tx = threadIdx.x;       // 0..31
    const int ty = threadIdx.y;       // 0..7
    const float* Wl = W + (size_t)l * D_ * D_;
    #pragma unroll
    for (int i = 0; i < 4; i++)
        s[ty + 8 * i][tx] = Wl[(size_t)(k0 + ty + 8 * i) * D_ + n0 + tx];
    __syncthreads();
    #pragma unroll
    for (int i = 0; i < 4; i++) {
        int n = n0 + ty + 8 * i;
        int k = k0 + tx;
        wh[((size_t)l * D_ + n) * D_ + k] = __float2half_rn(s[tx][ty + 8 * i]);
    }
}

// ==================== mma.sync fp16 2-term GEMM (3-stage, mask-skipped M-tiles) ====================
#define GB_BUF    30720
#define GB_AHI    0
#define GB_ALO    10240
#define GB_BH     20480
#define GB_SMEM   (3 * GB_BUF)   // 92160

template<int ACT, int OSPLIT>
__global__ void __launch_bounds__(256, 2)
mmagemm_kernel(const __half* __restrict__ Ahi,
               const __half* __restrict__ Alo,
               const __half* __restrict__ Wh, size_t wstride,
               const float* __restrict__ bias0, const float* __restrict__ bias1,
               const float* __restrict__ bias2,
               float* __restrict__ C,
               __half* __restrict__ Chi, __half* __restrict__ Clo,
               size_t ostride,
               const float* __restrict__ mask)
{
    const int by = blockIdx.y;         // M tile (0..255); each tile lies inside one batch elem
    // dead-tile skip: tile covers rows of batch b = by>>2, starting at s0 = (by&3)*128.
    // mask is a contiguous prefix per batch, so mask[b*512+s0]==0 => whole tile is padding.
    if (mask[((by >> 2) * S_) + ((by & 3) << 7)] == 0.f) return;

    extern __shared__ char dsm[];
    const uint32_t sb32 = smem_u32(dsm);

    const int tid  = threadIdx.x;
    const int wid  = tid >> 5, lane = tid & 31;
    const int mat  = blockIdx.x / 6;
    const int bx   = blockIdx.x % 6;   // N tile
    const int wm   = wid >> 1;         // 0..3
    const int wn   = wid & 1;          // 0..1

    const __half* Wm = Wh + (size_t)mat * wstride;
    const float* bias = (mat == 0) ? bias0 : ((mat == 1) ? bias1 : bias2);

    const int r  = tid >> 1;
    const int hf = tid & 1;
    const uint32_t stOff = (uint32_t)r * 80u + (uint32_t)hf * 32u;
    const char* aH = (const char*)(Ahi + ((size_t)(by * 128) + r) * 768 + hf * 16);
    const char* aL = (const char*)(Alo + ((size_t)(by * 128) + r) * 768 + hf * 16);
    const char* bH = (const char*)(Wm  + ((size_t)(bx * 128) + r) * 768 + hf * 16);

    const uint32_t offA = (uint32_t)(wm * 32 + (lane & 15)) * 80u + ((lane >> 4) & 1) * 16u;
    const uint32_t offB = (uint32_t)(wn * 64 + (lane & 7) + ((lane >> 4) & 1) * 8) * 80u
                        + ((lane >> 3) & 1) * 16u;

    float acc[2][8][4];
    #pragma unroll
    for (int mt = 0; mt < 2; mt++)
        #pragma unroll
        for (int nt = 0; nt < 8; nt++)
            #pragma unroll
            for (int j = 0; j < 4; j++) acc[mt][nt][j] = 0.f;

    auto stage = [&](int kt, int buf) {
        uint32_t d = sb32 + (uint32_t)buf * GB_BUF + stOff;
        long o = (long)kt * 64;
        CP_ASYNC16(d + GB_AHI,      aH + o);
        CP_ASYNC16(d + GB_AHI + 16, aH + o + 16);
        CP_ASYNC16(d + GB_ALO,      aL + o);
        CP_ASYNC16(d + GB_ALO + 16, aL + o + 16);
        CP_ASYNC16(d + GB_BH,       bH + o);
        CP_ASYNC16(d + GB_BH + 16,  bH + o + 16);
        CP_COMMIT();
    };

    // 3-stage prologue
    stage(0, 0);
    stage(1, 1);

    int buf = 0;
    #pragma unroll 1
    for (int t = 0; t < 24; ++t) {
        if (t == 23) { CP_WAIT0(); } else { CP_WAIT1(); }   // chunk t landed
        __syncthreads();   // also: everyone done reading buffer being restaged below

        if (t + 2 < 24) {
            int nb = buf + 2; if (nb >= 3) nb -= 3;
            stage(t + 2, nb);
        }

        const uint32_t bufb = sb32 + (uint32_t)buf * GB_BUF;
        #pragma unroll
        for (int ks = 0; ks < 2; ks++) {
            uint32_t ah[2][4], al[2][4];
            #pragma unroll
            for (int mt = 0; mt < 2; mt++) {
                uint32_t ad = bufb + offA + (uint32_t)mt * (16u * 80u) + (uint32_t)ks * 32u;
                LDSMX4(ah[mt], ad + GB_AHI);
                LDSMX4(al[mt], ad + GB_ALO);
            }
            #pragma unroll
            for (int half = 0; half < 2; half++) {
                uint32_t bh[4][2];
                #pragma unroll
                for (int np = 0; np < 2; np++) {
                    uint32_t bd = bufb + offB + (uint32_t)(half * 2 + np) * (16u * 80u)
                                + (uint32_t)ks * 32u;
                    uint32_t th[4];
                    LDSMX4(th, bd + GB_BH);
                    bh[2*np][0]   = th[0]; bh[2*np][1]   = th[1];
                    bh[2*np+1][0] = th[2]; bh[2*np+1][1] = th[3];
                }
                #pragma unroll
                for (int mt = 0; mt < 2; mt++)
                    #pragma unroll
                    for (int j = 0; j < 4; j++) {
                        int nt = half * 4 + j;
                        MMA16816F16(acc[mt][nt], ah[mt], bh[j]);
                        MMA16816F16(acc[mt][nt], al[mt], bh[j]);
                    }
            }
        }
        if (++buf == 3) buf = 0;
    }

    // ---- epilogue ----
    const int erow = lane >> 2;
    const int ecol = (lane & 3) * 2;
    #pragma unroll
    for (int mt = 0; mt < 2; mt++) {
        #pragma unroll
        for (int nt = 0; nt < 8; nt++) {
            int grow = by * 128 + wm * 32 + mt * 16 + erow;
            int gcol = bx * 128 + wn * 64 + nt * 8 + ecol;
            float b0 = __ldg(bias + gcol), b1 = __ldg(bias + gcol + 1);
            float v0 = acc[mt][nt][0] + b0;
            float v1 = acc[mt][nt][1] + b1;
            float v2 = acc[mt][nt][2] + b0;
            float v3 = acc[mt][nt][3] + b1;
            if (ACT == 1) {
                v0 = 0.5f * v0 * (1.0f + erff(v0 * 0.70710678118654752f));
                v1 = 0.5f * v1 * (1.0f + erff(v1 * 0.70710678118654752f));
                v2 = 0.5f * v2 * (1.0f + erff(v2 * 0.70710678118654752f));
                v3 = 0.5f * v3 * (1.0f + erff(v3 * 0.70710678118654752f));
            }
            if (OSPLIT == 0) {
                float* Cb = C + (size_t)mat * ostride;
                *(float2*)(Cb + (size_t)grow * 768 + gcol)       = make_float2(v0, v1);
                *(float2*)(Cb + (size_t)(grow + 8) * 768 + gcol) = make_float2(v2, v3);
            } else {
                __half h0, l0, h1, l1;
                split_f16(v0, h0, l0); split_f16(v1, h1, l1);
                __half2 hp = __halves2half2(h0, h1);
                __half2 lp = __halves2half2(l0, l1);
                *(uint32_t*)(Chi + (size_t)grow * 768 + gcol) = *(uint32_t*)&hp;
                *(uint32_t*)(Clo + (size_t)grow * 768 + gcol) = *(uint32_t*)&lp;
                split_f16(v2, h0, l0); split_f16(v3, h1, l1);
                hp = __halves2half2(h0, h1);
                lp = __halves2half2(l0, l1);
                *(uint32_t*)(Chi + (size_t)(grow + 8) * 768 + gcol) = *(uint32_t*)&hp;
                *(uint32_t*)(Clo + (size_t)(grow + 8) * 768 + gcol) = *(uint32_t*)&lp;
            }
        }
    }
}

// ================= FK: rotary-k + feature map + kv/ps (per (b,h), mask-bounded) =================
__global__ void __launch_bounds__(256)
fk_kernel(const float* __restrict__ k, const float* __restrict__ v,
          const float* __restrict__ om, const float* __restrict__ mask,
          float* __restrict__ kvout, float* __restrict__ psout)
{
    const int b = blockIdx.x / H_;
    const int h = blockIdx.x % H_;
    const int tid = threadIdx.x;      // 256

    __shared__ float som[DH_ * NF_];  // [d][f]
    __shared__ float sk [8][DH_];
    __shared__ float sv [8][DH_];
    __shared__ float spk[8][NF_];

    for (int i = tid; i < DH_ * NF_; i += 256) som[i] = om[i];

    const int iA = tid >> 5, fA = tid & 31;
    const int fB = tid >> 3, dB = (tid & 7) * 8;

    const float invf = expf(-(float)fA * 0.28782313662425572f); // ln(1e4)/32
    float c, sn, c8, s8;
    sincosf((float)iA * invf, &sn, &c);
    sincosf(8.0f * invf, &s8, &c8);

    float acc[8];
    #pragma unroll
    for (int i = 0; i < 8; i++) acc[i] = 0.f;
    float psum = 0.f;

    __syncthreads();

    #pragma unroll 1
    for (int s0 = 0; s0 < S_; s0 += 8) {
        if (mask[b * S_ + s0] == 0.f) break;   // contiguous prefix: rest is padding
        const int s = s0 + iA;
        const size_t rowb = ((size_t)(b * S_ + s)) * D_ + h * DH_;
        float ka = k[rowb + fA], kb = k[rowb + fA + 32];
        sk[iA][fA]      = ka * c - kb * sn;
        sk[iA][fA + 32] = kb * c + ka * sn;
        ((float2*)sv[iA])[fA] = ((const float2*)(v + rowb))[fA];
        __syncthreads();

        float a = 0.f;
        #pragma unroll
        for (int d = 0; d < DH_; ++d) a = fmaf(sk[iA][d], som[d * NF_ + fA], a);
        spk[iA][fA] = fmaxf(a, 0.f) * mask[b * S_ + s];
        __syncthreads();

        #pragma unroll
        for (int i = 0; i < 8; i++) {
            float p = spk[i][fB];
            psum += p;
            #pragma unroll
            for (int j = 0; j < 8; j++)
                acc[j] = fmaf(p, sv[i][dB + j], acc[j]);
        }
        float cn = c * c8 - sn * s8;
        sn = sn * c8 + c * s8;
        c = cn;
        __syncthreads();
    }

    #pragma unroll
    for (int j = 0; j < 8; j++)
        kvout[(((size_t)(b * H_ + h)) * NF_ + fB) * DH_ + dB + j] = acc[j];
    if ((tid & 7) == 0) psout[((size_t)(b * H_ + h)) * NF_ + fB] = psum;
}

// ============ FA: rotary-q + feature map + z + pq@kv -> fp16 pair (mask-bounded) ============
__global__ void __launch_bounds__(256)
fa_kernel(const float* __restrict__ q, const float* __restrict__ kvin,
          const float* __restrict__ psin, const float* __restrict__ om,
          const float* __restrict__ mask,
          __half* __restrict__ ahi, __half* __restrict__ alo)
{
    const int b = blockIdx.x / H_;
    const int h = blockIdx.x % H_;
    const int tid = threadIdx.x;      // 256

    __shared__ float som[DH_ * NF_];
    __shared__ float skv[NF_][DH_];
    __shared__ float sps[NF_];
    __shared__ float sq [8][DH_];
    __shared__ float spq[8][NF_];
    __shared__ float sz [8];

    for (int i = tid; i < DH_ * NF_; i += 256) som[i] = om[i];
    for (int i = tid; i < NF_ * DH_; i += 256)
        ((float*)skv)[i] = kvin[((size_t)(b * H_ + h)) * NF_ * DH_ + i];
    if (tid < NF_) sps[tid] = psin[((size_t)(b * H_ + h)) * NF_ + tid];

    const int iA = tid >> 5, fA = tid & 31;

    const float invf = expf(-(float)fA * 0.28782313662425572f);
    float c, sn, c8, s8;
    sincosf((float)iA * invf, &sn, &c);
    sincosf(8.0f * invf, &s8, &c8);

    __syncthreads();

    #pragma unroll 1
    for (int s0 = 0; s0 < S_; s0 += 8) {
        if (mask[b * S_ + s0] == 0.f) break;   // padding suffix: outputs never read
        const int s = s0 + iA;
        const size_t rowb = ((size_t)(b * S_ + s)) * D_ + h * DH_;
        float qa = q[rowb + fA], qb = q[rowb + fA + 32];
        sq[iA][fA]      = qa * c - qb * sn;
        sq[iA][fA + 32] = qb * c + qa * sn;
        __syncthreads();

        float a = 0.f;
        #pragma unroll
        for (int d = 0; d < DH_; ++d) a = fmaf(sq[iA][d], som[d * NF_ + fA], a);
        float pq = fmaxf(a, 0.f);
        spq[iA][fA] = pq;
        float zp = pq * sps[fA];
        #pragma unroll
        for (int o = 16; o; o >>= 1) zp += __shfl_xor_sync(0xffffffffu, zp, o);
        if (fA == 0) sz[iA] = zp;
        __syncthreads();

        float o1 = 0.f, o2 = 0.f;
        #pragma unroll
        for (int f = 0; f < NF_; ++f) {
            float p = spq[iA][f];
            o1 = fmaf(p, skv[f][fA],      o1);
            o2 = fmaf(p, skv[f][fA + 32], o2);
        }
        float zi = 1.0f / (sz[iA] + 1e-6f);
        o1 *= zi; o2 *= zi;
        __half hi, lo;
        split_f16(o1, hi, lo);
        ahi[rowb + fA]      = hi; alo[rowb + fA]      = lo;
        split_f16(o2, hi, lo);
        ahi[rowb + fA + 32] = hi; alo[rowb + fA + 32] = lo;

        float cn = c * c8 - sn * s8;
        sn = sn * c8 + c * s8;
        c = cn;
        __syncthreads();
    }
}

// ------- residual + LayerNorm: fp16 pair in/out, dead rows skipped -------
__global__ void addln_kernel(__half* __restrict__ hhi, __half* __restrict__ hlo,
                             const float* __restrict__ r,
                             const float* __restrict__ gam, const float* __restrict__ bet,
                             const float* __restrict__ mask)
{
    const int row = blockIdx.x;
    if (mask[row] == 0.f) return;      // padding row: value never read
    const int tid = threadIdx.x;   // 256
    const size_t base = (size_t)row * D_;

    float x0 = __half2float(hhi[base + tid])       + __half2float(hlo[base + tid])       + r[base + tid];
    float x1 = __half2float(hhi[base + tid + 256]) + __half2float(hlo[base + tid + 256]) + r[base + tid + 256];
    float x2 = __half2float(hhi[base + tid + 512]) + __half2float(hlo[base + tid + 512]) + r[base + tid + 512];

    __shared__ float red[8];
    float s = x0 + x1 + x2;
    #pragma unroll
    for (int o = 16; o; o >>= 1) s += __shfl_xor_sync(0xffffffffu, s, o);
    if ((tid & 31) == 0) red[tid >> 5] = s;
    __syncthreads();
    float tot = red[0] + red[1] + red[2] + red[3] + red[4] + red[5] + red[6] + red[7];
    float mean = tot * (1.0f / 768.0f);

    float d0 = x0 - mean, d1 = x1 - mean, d2 = x2 - mean;
    float s2 = d0 * d0 + d1 * d1 + d2 * d2;
    #pragma unroll
    for (int o = 16; o; o >>= 1) s2 += __shfl_xor_sync(0xffffffffu, s2, o);
    __syncthreads();
    if ((tid & 31) == 0) red[tid >> 5] = s2;
    __syncthreads();
    float var = (red[0] + red[1] + red[2] + red[3] + red[4] + red[5] + red[6] + red[7]) * (1.0f / 768.0f);
    float inv = rsqrtf(var + 1e-5f);

    float y0 = d0 * inv * gam[tid]       + bet[tid];
    float y1 = d1 * inv * gam[tid + 256] + bet[tid + 256];
    float y2 = d2 * inv * gam[tid + 512] + bet[tid + 512];
    __half hi, lo;
    split_f16(y0, hi, lo); hhi[base + tid]       = hi; hlo[base + tid]       = lo;
    split_f16(y1, hi, lo); hhi[base + tid + 256] = hi; hlo[base + tid + 256] = lo;
    split_f16(y2, hi, lo); hhi[base + tid + 512] = hi; hlo[base + tid + 512] = lo;
}

// ---------------- masked mean pool (reads fp16 pair, mask-bounded) ----------------
__global__ void pool_kernel(const __half* __restrict__ hhi, const __half* __restrict__ hlo,
                            const float* __restrict__ mask, float* __restrict__ pool)
{
    const int b = blockIdx.x;
    const int c = blockIdx.y * 128 + threadIdx.x;   // grid.y = 6
    float acc = 0.f, dn = 0.f;
    for (int s = 0; s < S_; ++s) {
        float m = mask[b * S_ + s];
        if (m == 0.f) break;           // contiguous prefix
        dn += m;
        size_t i = ((size_t)(b * S_ + s)) * D_ + c;
        acc += (__half2float(hhi[i]) + __half2float(hlo[i])) * m;
    }
    dn = fmaxf(dn, 1e-9f);
    pool[(size_t)b * D_ + c] = acc / dn;
}

// ---------------- final: out = relu(pool @ Wl + bl) ----------------
__global__ void final_kernel(const float* __restrict__ pool, const float* __restrict__ Wl,
                             const float* __restrict__ bl, float* __restrict__ out)
{
    const int b = blockIdx.x;
    const int o = threadIdx.x;   // 512
    __shared__ float sp[D_];
    for (int i = o; i < D_; i += 512) sp[i] = pool[(size_t)b * D_ + i];
    __syncthreads();
    float acc = bl[o];
    #pragma unroll 8
    for (int k = 0; k < D_; ++k)
        acc = fmaf(sp[k], Wl[(size_t)k * OUT_ + o], acc);
    out[(size_t)b * OUT_ + o] = fmaxf(acc, 0.f);
}

// ---------------- host ----------------
extern "C" void kernel_launch(void* const* d_in, const int* in_sizes, int n_in,
                              void* d_out, int out_size)
{
    const int*   x     = (const int*)  d_in[0];
    const float* mask  = (const float*)d_in[1];
    const float* tok   = (const float*)d_in[2];
    const float* Wq    = (const float*)d_in[3];
    const float* bq    = (const float*)d_in[4];
    const float* Wk    = (const float*)d_in[5];
    const float* bk    = (const float*)d_in[6];
    const float* Wv    = (const float*)d_in[7];
    const float* bv    = (const float*)d_in[8];
    const float* Wo    = (const float*)d_in[9];
    const float* bo    = (const float*)d_in[10];
    const float* omega = (const float*)d_in[11];
    const float* ln1s  = (const float*)d_in[12];
    const float* ln1b  = (const float*)d_in[13];
    const float* W1    = (const float*)d_in[14];
    const float* b1    = (const float*)d_in[15];
    const float* W2    = (const float*)d_in[16];
    const float* b2    = (const float*)d_in[17];
    const float* ln2s  = (const float*)d_in[18];
    const float* ln2b  = (const float*)d_in[19];
    const float* Wl    = (const float*)d_in[20];
    const float* bl    = (const float*)d_in[21];

    float *qkv, *t1, *kv, *ps, *pool;
    __half *wh, *hhi, *hlo, *t1hi, *t1lo, *ffhi, *fflo;
    cudaGetSymbolAddress((void**)&qkv, g_qkv);
    cudaGetSymbolAddress((void**)&t1,  g_t1);
    cudaGetSymbolAddress((void**)&kv,  g_kv);
    cudaGetSymbolAddress((void**)&ps,  g_ps);
    cudaGetSymbolAddress((void**)&pool, g_pool);
    cudaGetSymbolAddress((void**)&wh,   g_wh);
    cudaGetSymbolAddress((void**)&hhi,  g_hhi);
    cudaGetSymbolAddress((void**)&hlo,  g_hlo);
    cudaGetSymbolAddress((void**)&t1hi, g_t1hi);
    cudaGetSymbolAddress((void**)&t1lo, g_t1lo);
    cudaGetSymbolAddress((void**)&ffhi, g_ffhi);
    cudaGetSymbolAddress((void**)&fflo, g_fflo);

    cudaFuncSetAttribute(mmagemm_kernel<0,0>, cudaFuncAttributeMaxDynamicSharedMemorySize, GB_SMEM);
    cudaFuncSetAttribute(mmagemm_kernel<1,1>, cudaFuncAttributeMaxDynamicSharedMemorySize, GB_SMEM);

    const size_t MATSZ = (size_t)NL_ * D_ * D_;
    const size_t LSZ   = (size_t)D_ * D_;

    dim3 gT(D_ / 32, D_ / 32, NL_);
    dim3 bT(32, 8);
    dim3 gQKV(18, BS_ / 128);
    dim3 gGemm(6, BS_ / 128);

    embed_kernel<<<(BSD_ + 255) / 256, 256>>>(x, tok, hhi, hlo);
    wsplit_kernel<<<gT, bT>>>(Wq, wh + 0 * MATSZ);
    wsplit_kernel<<<gT, bT>>>(Wk, wh + 1 * MATSZ);
    wsplit_kernel<<<gT, bT>>>(Wv, wh + 2 * MATSZ);
    mmagemm_kernel<0,0><<<gQKV, 256, GB_SMEM>>>(hhi, hlo, wh + 0 * MATSZ + 0 * LSZ, MATSZ,
                                                bq, bk, bv, qkv, nullptr, nullptr, (size_t)BSD_, mask);
    wsplit_kernel<<<gT, bT>>>(Wo, wh + 3 * MATSZ);
    wsplit_kernel<<<gT, bT>>>(W1, wh + 4 * MATSZ);
    wsplit_kernel<<<gT, bT>>>(W2, wh + 5 * MATSZ);

    for (int l = 0; l < NL_; ++l) {
        const float* lbq = bq + (size_t)l * D_;
        const float* lbk = bk + (size_t)l * D_;
        const float* lbv = bv + (size_t)l * D_;
        const float* lbo = bo + (size_t)l * D_;
        const float* lb1 = b1 + (size_t)l * D_;
        const float* lb2 = b2 + (size_t)l * D_;
        const float* lom = omega + (size_t)l * DH_ * NF_;
        const float* l1s = ln1s + (size_t)l * D_;
        const float* l1b = ln1b + (size_t)l * D_;
        const float* l2s = ln2s + (size_t)l * D_;
        const float* l2b = ln2b + (size_t)l * D_;

        if (l > 0) {
            mmagemm_kernel<0,0><<<gQKV, 256, GB_SMEM>>>(hhi, hlo, wh + 0 * MATSZ + l * LSZ, MATSZ,
                                                        lbq, lbk, lbv, qkv, nullptr, nullptr, (size_t)BSD_, mask);
        }

        fk_kernel<<<B_ * H_, 256>>>(qkv + BSD_, qkv + 2 * (size_t)BSD_, lom, mask, kv, ps);
        fa_kernel<<<B_ * H_, 256>>>(qkv, kv, ps, lom, mask, t1hi, t1lo);

        mmagemm_kernel<0,0><<<gGemm, 256, GB_SMEM>>>(t1hi, t1lo, wh + 3 * MATSZ + l * LSZ, 0,
                                                     lbo, lbo, lbo, qkv, nullptr, nullptr, 0, mask);
        addln_kernel<<<BS_, 256>>>(hhi, hlo, qkv, l1s, l1b, mask);

        mmagemm_kernel<1,1><<<gGemm, 256, GB_SMEM>>>(hhi, hlo, wh + 4 * MATSZ + l * LSZ, 0,
                                                     lb1, lb1, lb1, nullptr, ffhi, fflo, 0, mask);
        mmagemm_kernel<0,0><<<gGemm, 256, GB_SMEM>>>(ffhi, fflo, wh + 5 * MATSZ + l * LSZ, 0,
                                                     lb2, lb2, lb2, t1, nullptr, nullptr, 0, mask);
        addln_kernel<<<BS_, 256>>>(hhi, hlo, t1, l2s, l2b, mask);
    }

    dim3 gPool(B_, D_ / 128);
    pool_kernel<<<gPool, 128>>>(hhi, hlo, mask, pool);
    final_kernel<<<B_, 512>>>(pool, Wl, bl, (float*)d_out);
}